// round 1
// baseline (speedup 1.0000x reference)
#include <cuda_runtime.h>
#include <math.h>

// Problem dims
static constexpr int Bb = 64;
static constexpr int Ss = 512;
static constexpr int Ee = 512;
static constexpr int Hh = 8;
static constexpr int Dd = 64;
static constexpr int Mm = Bb * Ss;        // 32768 rows
static constexpr int HD = Hh * Dd;        // 512

// Scratch (device globals: allocation-free rule)
__device__ float g_Q[Mm * HD];
__device__ float g_K[Mm * HD];
__device__ float g_V[Mm * HD];
__device__ float g_attn[Mm * HD];

// ---------------------------------------------------------------------------
// Kernel 1: fused (x + BE) then per-head projection GEMM.
//   A[m,k] = x[m,k] + BE[m % S, k]          (M=32768, K=512)
//   W is [H, E, D]; output column n = h*64+d -> W[(n>>6)*E*D + k*D + (n&63)]
//   Out[m, n] in [B,S,H*D] layout. blockIdx.z selects Q / K / V.
// ---------------------------------------------------------------------------
__global__ __launch_bounds__(256) void qkv_gemm_kernel(
    const float* __restrict__ x, const float* __restrict__ be,
    const float* __restrict__ WQ, const float* __restrict__ WK,
    const float* __restrict__ WV)
{
    constexpr int BM = 128, BN = 128, BK = 16;
    __shared__ float As[BK][BM + 4];
    __shared__ float Bs[BK][BN];

    const float* W  = (blockIdx.z == 0) ? WQ : ((blockIdx.z == 1) ? WK : WV);
    float* Out      = (blockIdx.z == 0) ? g_Q : ((blockIdx.z == 1) ? g_K : g_V);

    const int m0 = blockIdx.x * BM;
    const int n0 = blockIdx.y * BN;
    const int tid = threadIdx.x;
    const int trow = (tid >> 4) * 8;   // 0..120
    const int tcol = (tid & 15) * 8;   // 0..120

    float acc[8][8];
#pragma unroll
    for (int i = 0; i < 8; i++)
#pragma unroll
        for (int j = 0; j < 8; j++) acc[i][j] = 0.f;

    for (int k0 = 0; k0 < Ee; k0 += BK) {
        // A tile: 128 rows x 16 k = 512 float4 (4 float4 per row along k)
#pragma unroll
        for (int l = 0; l < 2; l++) {
            int f   = tid + l * 256;          // 0..511
            int row = f >> 2;                 // 0..127
            int kq  = (f & 3) * 4;            // 0,4,8,12
            int gm  = m0 + row;
            const float4 xv = *(const float4*)&x[gm * Ee + k0 + kq];
            const float4 bv = *(const float4*)&be[(gm & (Ss - 1)) * Ee + k0 + kq];
            As[kq + 0][row] = xv.x + bv.x;
            As[kq + 1][row] = xv.y + bv.y;
            As[kq + 2][row] = xv.z + bv.z;
            As[kq + 3][row] = xv.w + bv.w;
        }
        // B tile: 16 k x 128 n = 512 float4
#pragma unroll
        for (int l = 0; l < 2; l++) {
            int f  = tid + l * 256;           // 0..511
            int kk = f >> 5;                  // 0..15
            int nq = (f & 31) * 4;            // 0..124
            int n  = n0 + nq;
            const float4 wv = *(const float4*)&W[(n >> 6) * (Ee * Dd) + (k0 + kk) * Dd + (n & 63)];
            *(float4*)&Bs[kk][nq] = wv;
        }
        __syncthreads();

#pragma unroll
        for (int kk = 0; kk < BK; kk++) {
            float a[8], bb[8];
            *(float4*)&a[0]  = *(const float4*)&As[kk][trow];
            *(float4*)&a[4]  = *(const float4*)&As[kk][trow + 4];
            *(float4*)&bb[0] = *(const float4*)&Bs[kk][tcol];
            *(float4*)&bb[4] = *(const float4*)&Bs[kk][tcol + 4];
#pragma unroll
            for (int i = 0; i < 8; i++)
#pragma unroll
                for (int j = 0; j < 8; j++)
                    acc[i][j] = fmaf(a[i], bb[j], acc[i][j]);
        }
        __syncthreads();
    }

#pragma unroll
    for (int i = 0; i < 8; i++) {
        int gm = m0 + trow + i;
#pragma unroll
        for (int j = 0; j < 8; j += 4) {
            float4 v = make_float4(acc[i][j], acc[i][j + 1], acc[i][j + 2], acc[i][j + 3]);
            *(float4*)&Out[gm * HD + n0 + tcol + j] = v;
        }
    }
}

// ---------------------------------------------------------------------------
// Kernel 2: fused attention per (b,h).
//   One thread = one query row (q + out accumulator in registers, D=64).
//   K/V streamed in 64-key SMEM tiles. Unstable softmax (scores bounded by
//   data distribution; identical result to stable softmax).
// ---------------------------------------------------------------------------
__global__ __launch_bounds__(128) void attn_kernel(const float* __restrict__ mask)
{
    __shared__ float Ksm[64][64];
    __shared__ float Vsm[64][64];
    __shared__ float biassm[64];

    const int b = blockIdx.z;
    const int h = blockIdx.y;
    const int tid = threadIdx.x;
    const int s = blockIdx.x * 128 + tid;

    const float4* qp = (const float4*)&g_Q[(b * Ss + s) * HD + h * Dd];
    float4 qv[16];
#pragma unroll
    for (int i = 0; i < 16; i++) qv[i] = qp[i];

    float4 accv[16];
#pragma unroll
    for (int i = 0; i < 16; i++) accv[i] = make_float4(0.f, 0.f, 0.f, 0.f);
    float rowsum = 0.f;
    const float scale = 0.044194173824159216f;  // 1/sqrt(512)

    for (int t0 = 0; t0 < Ss; t0 += 64) {
        // load K/V tiles: 1024 float4 each; 8 per thread, coalesced
#pragma unroll
        for (int l = 0; l < 8; l++) {
            int f   = tid + l * 128;          // 0..1023
            int row = f >> 4;                 // 0..63
            int cq  = f & 15;                 // float4 column
            int t   = t0 + row;
            const float4* kp = (const float4*)&g_K[(b * Ss + t) * HD + h * Dd];
            ((float4*)Ksm[row])[cq] = kp[cq];
            const float4* vp = (const float4*)&g_V[(b * Ss + t) * HD + h * Dd];
            ((float4*)Vsm[row])[cq] = vp[cq];
        }
        if (tid < 64) biassm[tid] = -1e10f * mask[b * Ss + t0 + tid];
        __syncthreads();

        for (int j = 0; j < 64; j++) {
            const float4* kr = (const float4*)Ksm[j];
            float sc0 = 0.f, sc1 = 0.f, sc2 = 0.f, sc3 = 0.f;
#pragma unroll
            for (int i = 0; i < 16; i++) {
                float4 kv = kr[i];
                sc0 = fmaf(qv[i].x, kv.x, sc0);
                sc1 = fmaf(qv[i].y, kv.y, sc1);
                sc2 = fmaf(qv[i].z, kv.z, sc2);
                sc3 = fmaf(qv[i].w, kv.w, sc3);
            }
            float sc = (sc0 + sc1) + (sc2 + sc3);
            float p = __expf(fmaf(sc, scale, biassm[j]));
            rowsum += p;
            const float4* vr = (const float4*)Vsm[j];
#pragma unroll
            for (int i = 0; i < 16; i++) {
                float4 vv = vr[i];
                accv[i].x = fmaf(p, vv.x, accv[i].x);
                accv[i].y = fmaf(p, vv.y, accv[i].y);
                accv[i].z = fmaf(p, vv.z, accv[i].z);
                accv[i].w = fmaf(p, vv.w, accv[i].w);
            }
        }
        __syncthreads();
    }

    float inv = 1.0f / rowsum;
    float4* op = (float4*)&g_attn[(b * Ss + s) * HD + h * Dd];
#pragma unroll
    for (int i = 0; i < 16; i++) {
        float4 v = accv[i];
        op[i] = make_float4(v.x * inv, v.y * inv, v.z * inv, v.w * inv);
    }
}

// ---------------------------------------------------------------------------
// Kernel 3: output projection. out[m,n] = sum_k attn[m,k] * WO[k,n]
//   WO is [H*D=512, E=512] row-major.
// ---------------------------------------------------------------------------
__global__ __launch_bounds__(256) void out_gemm_kernel(
    const float* __restrict__ WO, float* __restrict__ out)
{
    constexpr int BM = 128, BN = 128, BK = 16;
    __shared__ float As[BK][BM + 4];
    __shared__ float Bs[BK][BN];

    const int m0 = blockIdx.x * BM;
    const int n0 = blockIdx.y * BN;
    const int tid = threadIdx.x;
    const int trow = (tid >> 4) * 8;
    const int tcol = (tid & 15) * 8;

    float acc[8][8];
#pragma unroll
    for (int i = 0; i < 8; i++)
#pragma unroll
        for (int j = 0; j < 8; j++) acc[i][j] = 0.f;

    for (int k0 = 0; k0 < HD; k0 += BK) {
#pragma unroll
        for (int l = 0; l < 2; l++) {
            int f   = tid + l * 256;
            int row = f >> 2;
            int kq  = (f & 3) * 4;
            int gm  = m0 + row;
            const float4 av = *(const float4*)&g_attn[gm * HD + k0 + kq];
            As[kq + 0][row] = av.x;
            As[kq + 1][row] = av.y;
            As[kq + 2][row] = av.z;
            As[kq + 3][row] = av.w;
        }
#pragma unroll
        for (int l = 0; l < 2; l++) {
            int f  = tid + l * 256;
            int kk = f >> 5;
            int nq = (f & 31) * 4;
            const float4 wv = *(const float4*)&WO[(k0 + kk) * Ee + n0 + nq];
            *(float4*)&Bs[kk][nq] = wv;
        }
        __syncthreads();

#pragma unroll
        for (int kk = 0; kk < BK; kk++) {
            float a[8], bb[8];
            *(float4*)&a[0]  = *(const float4*)&As[kk][trow];
            *(float4*)&a[4]  = *(const float4*)&As[kk][trow + 4];
            *(float4*)&bb[0] = *(const float4*)&Bs[kk][tcol];
            *(float4*)&bb[4] = *(const float4*)&Bs[kk][tcol + 4];
#pragma unroll
            for (int i = 0; i < 8; i++)
#pragma unroll
                for (int j = 0; j < 8; j++)
                    acc[i][j] = fmaf(a[i], bb[j], acc[i][j]);
        }
        __syncthreads();
    }

#pragma unroll
    for (int i = 0; i < 8; i++) {
        int gm = m0 + trow + i;
#pragma unroll
        for (int j = 0; j < 8; j += 4) {
            float4 v = make_float4(acc[i][j], acc[i][j + 1], acc[i][j + 2], acc[i][j + 3]);
            *(float4*)&out[gm * Ee + n0 + tcol + j] = v;
        }
    }
}

// ---------------------------------------------------------------------------
extern "C" void kernel_launch(void* const* d_in, const int* in_sizes, int n_in,
                              void* d_out, int out_size)
{
    const float* x    = (const float*)d_in[0];
    const float* mask = (const float*)d_in[1];
    const float* WQ   = (const float*)d_in[2];
    const float* WK   = (const float*)d_in[3];
    const float* WV   = (const float*)d_in[4];
    const float* BE   = (const float*)d_in[5];
    const float* WO   = (const float*)d_in[6];
    float* out        = (float*)d_out;

    dim3 g1(Mm / 128, HD / 128, 3);
    qkv_gemm_kernel<<<g1, 256>>>(x, BE, WQ, WK, WV);

    dim3 g2(Ss / 128, Hh, Bb);
    attn_kernel<<<g2, 128>>>(mask);

    dim3 g3(Mm / 128, Ee / 128);
    out_gemm_kernel<<<g3, 256>>>(WO, out);
}

// round 3
// speedup vs baseline: 1.5181x; 1.5181x over previous
#include <cuda_runtime.h>
#include <cuda_bf16.h>
#include <stdint.h>
#include <math.h>

// ---------------------------------------------------------------- dims
static constexpr int Bb = 64;
static constexpr int Ss = 512;
static constexpr int Ee = 512;
static constexpr int Hh = 8;
static constexpr int Dd = 64;
static constexpr int Mm = Bb * Ss;     // 32768
static constexpr int HD = Hh * Dd;     // 512

// ---------------------------------------------------------------- scratch
__device__ float g_Q[Mm * HD];
__device__ float g_K[Mm * HD];
__device__ float g_V[Mm * HD];
__device__ __nv_bfloat16 g_Ah[Mm * Ee];
__device__ __nv_bfloat16 g_Al[Mm * Ee];
__device__ __nv_bfloat16 g_ATh[Mm * HD];
__device__ __nv_bfloat16 g_ATl[Mm * HD];
// B matrices, layout B[n][k] (k contiguous):
// rows 0..1535 = WQ/WK/WV (n = h*64+d), rows 1536..2047 = WO^T
__device__ __nv_bfloat16 g_Bh[2048 * 512];
__device__ __nv_bfloat16 g_Bl[2048 * 512];

// ---------------------------------------------------------------- helpers
__device__ __forceinline__ void split_bf16(float v, __nv_bfloat16& h, __nv_bfloat16& l) {
    h = __float2bfloat16(v);
    l = __float2bfloat16(v - __bfloat162float(h));
}
__device__ __forceinline__ uint32_t smem_u32(const void* p) {
    uint32_t a;
    asm("{ .reg .u64 t; cvta.to.shared.u64 t, %1; cvt.u32.u64 %0, t; }" : "=r"(a) : "l"(p));
    return a;
}
__device__ __forceinline__ void ldsm4(uint32_t r[4], uint32_t addr) {
    asm volatile("ldmatrix.sync.aligned.m8n8.x4.shared.b16 {%0,%1,%2,%3}, [%4];"
                 : "=r"(r[0]), "=r"(r[1]), "=r"(r[2]), "=r"(r[3]) : "r"(addr));
}
__device__ __forceinline__ void mma16816(float d[4], const uint32_t a[4],
                                         uint32_t b0, uint32_t b1) {
    asm volatile("mma.sync.aligned.m16n8k16.row.col.f32.bf16.bf16.f32 "
                 "{%0,%1,%2,%3}, {%4,%5,%6,%7}, {%8,%9}, {%0,%1,%2,%3};"
                 : "+f"(d[0]), "+f"(d[1]), "+f"(d[2]), "+f"(d[3])
                 : "r"(a[0]), "r"(a[1]), "r"(a[2]), "r"(a[3]), "r"(b0), "r"(b1));
}

// ---------------------------------------------------------------- prep kernels
__global__ __launch_bounds__(256) void prep_a_kernel(const float* __restrict__ x,
                                                     const float* __restrict__ be) {
    uint32_t i4 = blockIdx.x * 256 + threadIdx.x;       // float4 index
    int m = i4 >> 7;
    int k = (i4 & 127) << 2;
    const float4 xv = *(const float4*)&x[(size_t)m * Ee + k];
    const float4 bv = *(const float4*)&be[(size_t)(m & (Ss - 1)) * Ee + k];
    float v[4] = {xv.x + bv.x, xv.y + bv.y, xv.z + bv.z, xv.w + bv.w};
    __nv_bfloat16 h[4], l[4];
#pragma unroll
    for (int i = 0; i < 4; i++) split_bf16(v[i], h[i], l[i]);
    __nv_bfloat162 h01, h23, l01, l23;
    h01.x = h[0]; h01.y = h[1]; h23.x = h[2]; h23.y = h[3];
    l01.x = l[0]; l01.y = l[1]; l23.x = l[2]; l23.y = l[3];
    size_t o = (size_t)m * Ee + k;
    *(__nv_bfloat162*)&g_Ah[o]     = h01;
    *(__nv_bfloat162*)&g_Ah[o + 2] = h23;
    *(__nv_bfloat162*)&g_Al[o]     = l01;
    *(__nv_bfloat162*)&g_Al[o + 2] = l23;
}

__global__ __launch_bounds__(256) void prep_w_kernel(const float* __restrict__ WQ,
                                                     const float* __restrict__ WK,
                                                     const float* __restrict__ WV,
                                                     const float* __restrict__ WO) {
    uint32_t idx = blockIdx.x * 256 + threadIdx.x;      // 2048*512 total
    int r = idx >> 9;
    int k = idx & 511;
    float v;
    if (r < 1536) {
        int z = r >> 9;
        int n = r & 511;
        const float* W = (z == 0) ? WQ : (z == 1) ? WK : WV;
        v = W[(size_t)(n >> 6) * (Ee * Dd) + (size_t)k * Dd + (n & 63)];
    } else {
        int n = r - 1536;
        v = WO[(size_t)k * Ee + n];
    }
    __nv_bfloat16 h, l;
    split_bf16(v, h, l);
    g_Bh[idx] = h;
    g_Bl[idx] = l;
}

// ---------------------------------------------------------------- HMMA GEMM
// C[m,n] = sum_k A[m,k]*B[n,k], bf16x3. CTA tile 128x128, K-chunk 32.
// SMEM layout per array: 128 rows x 32 bf16 (64B), XOR swizzle:
//   phys_chunk16 = c8 ^ ((row>>1)&3)  -> conflict-free ldmatrix & stores.
static constexpr int SA_H = 0;
static constexpr int SA_L = 8192;
static constexpr int SB_H = 16384;
static constexpr int SB_L = 24576;

// WHICH=0: QKV projection (z = blockIdx.z picks C among g_Q/g_K/g_V)
// WHICH=1: output projection (C = param)
template <int WHICH>
__global__ __launch_bounds__(256, 2) void gemm_bf16x3_kernel(float* __restrict__ Cout)
{
    __shared__ __align__(16) char sm[32768];
    const uint32_t sb = smem_u32(sm);
    const int tid  = threadIdx.x;
    const int wid  = tid >> 5;
    const int lane = tid & 31;

    const int m0 = blockIdx.x * 128;
    const int n0 = blockIdx.y * 128;
    const int z  = (WHICH == 0) ? blockIdx.z : 0;

    const __nv_bfloat16* Ah = (WHICH == 0) ? g_Ah : g_ATh;
    const __nv_bfloat16* Al = (WHICH == 0) ? g_Al : g_ATl;
    const size_t boff = (WHICH == 0) ? (size_t)z * 512 * 512 : (size_t)1536 * 512;
    const __nv_bfloat16* Bh = g_Bh + boff;
    const __nv_bfloat16* Bl = g_Bl + boff;
    float* C = (WHICH == 0) ? ((z == 0) ? g_Q : (z == 1) ? g_K : g_V) : Cout;

    // warp tiling: 4 m-warps x 2 n-warps; warp tile 32m x 64n
    const int m_warp = (wid & 3) * 32;
    const int n_warp = (wid >> 2) * 64;

    // ldmatrix lane geometry
    const int rA   = m_warp + (lane & 7) + ((lane >> 3) & 1) * 8;  // + tm*16
    const int kbA  = lane >> 4;                                     // k8 offset bit
    const int sxA  = (rA >> 1) & 3;
    const int rB   = n_warp + (lane & 7) + (lane >> 4) * 8;         // + tp*16
    const int kbB  = (lane >> 3) & 1;
    const int sxB  = (rB >> 1) & 3;

    float acc[2][8][4];
#pragma unroll
    for (int i = 0; i < 2; i++)
#pragma unroll
        for (int j = 0; j < 8; j++)
#pragma unroll
            for (int u = 0; u < 4; u++) acc[i][j][u] = 0.f;

    // global load geometry (per thread: 2 x 16B chunks per array per k-chunk)
    const int grow0 = (tid + 0)   >> 2, gc80 = (tid + 0)   & 3;
    const int grow1 = (tid + 256) >> 2, gc81 = (tid + 256) & 3;
    const uint32_t so0 = grow0 * 64 + ((gc80 ^ ((grow0 >> 1) & 3)) * 16);
    const uint32_t so1 = grow1 * 64 + ((gc81 ^ ((grow1 >> 1) & 3)) * 16);

    for (int c = 0; c < 16; ++c) {
        const int k0 = c * 32;
        {
            size_t gA0 = (size_t)(m0 + grow0) * 512 + k0 + gc80 * 8;
            size_t gA1 = (size_t)(m0 + grow1) * 512 + k0 + gc81 * 8;
            size_t gB0 = (size_t)(n0 + grow0) * 512 + k0 + gc80 * 8;
            size_t gB1 = (size_t)(n0 + grow1) * 512 + k0 + gc81 * 8;
            *(uint4*)(sm + SA_H + so0) = *(const uint4*)&Ah[gA0];
            *(uint4*)(sm + SA_H + so1) = *(const uint4*)&Ah[gA1];
            *(uint4*)(sm + SA_L + so0) = *(const uint4*)&Al[gA0];
            *(uint4*)(sm + SA_L + so1) = *(const uint4*)&Al[gA1];
            *(uint4*)(sm + SB_H + so0) = *(const uint4*)&Bh[gB0];
            *(uint4*)(sm + SB_H + so1) = *(const uint4*)&Bh[gB1];
            *(uint4*)(sm + SB_L + so0) = *(const uint4*)&Bl[gB0];
            *(uint4*)(sm + SB_L + so1) = *(const uint4*)&Bl[gB1];
        }
        __syncthreads();

#pragma unroll
        for (int kk = 0; kk < 2; ++kk) {
            uint32_t ah[2][4], al[2][4];
#pragma unroll
            for (int tm = 0; tm < 2; ++tm) {
                uint32_t ro = (uint32_t)(rA + tm * 16) * 64 +
                              (uint32_t)(((kk * 2 + kbA) ^ sxA) * 16);
                ldsm4(ah[tm], sb + SA_H + ro);
                ldsm4(al[tm], sb + SA_L + ro);
            }
#pragma unroll
            for (int tp = 0; tp < 4; ++tp) {
                uint32_t bh[4], bl[4];
                uint32_t ro = (uint32_t)(rB + tp * 16) * 64 +
                              (uint32_t)(((kk * 2 + kbB) ^ sxB) * 16);
                ldsm4(bh, sb + SB_H + ro);
                ldsm4(bl, sb + SB_L + ro);
#pragma unroll
                for (int tm = 0; tm < 2; ++tm) {
                    mma16816(acc[tm][2 * tp],     ah[tm], bh[0], bh[1]);
                    mma16816(acc[tm][2 * tp],     ah[tm], bl[0], bl[1]);
                    mma16816(acc[tm][2 * tp],     al[tm], bh[0], bh[1]);
                    mma16816(acc[tm][2 * tp + 1], ah[tm], bh[2], bh[3]);
                    mma16816(acc[tm][2 * tp + 1], ah[tm], bl[2], bl[3]);
                    mma16816(acc[tm][2 * tp + 1], al[tm], bh[2], bh[3]);
                }
            }
        }
        __syncthreads();
    }

    // epilogue
#pragma unroll
    for (int tm = 0; tm < 2; ++tm) {
        const int m = m0 + m_warp + tm * 16 + (lane >> 2);
#pragma unroll
        for (int tn = 0; tn < 8; ++tn) {
            const int n = n0 + n_warp + tn * 8 + (lane & 3) * 2;
            float2 v0 = make_float2(acc[tm][tn][0], acc[tm][tn][1]);
            float2 v1 = make_float2(acc[tm][tn][2], acc[tm][tn][3]);
            *(float2*)&C[(size_t)m * 512 + n]       = v0;
            *(float2*)&C[(size_t)(m + 8) * 512 + n] = v1;
        }
    }
}

// ---------------------------------------------------------------- attention (fp32 SIMT)
__global__ __launch_bounds__(128) void attn_kernel(const float* __restrict__ mask)
{
    __shared__ float Ksm[64][64];
    __shared__ float Vsm[64][64];
    __shared__ float biassm[64];

    const int b = blockIdx.z;
    const int h = blockIdx.y;
    const int tid = threadIdx.x;
    const int s = blockIdx.x * 128 + tid;

    const float4* qp = (const float4*)&g_Q[(size_t)(b * Ss + s) * HD + h * Dd];
    float4 qv[16];
#pragma unroll
    for (int i = 0; i < 16; i++) qv[i] = qp[i];

    float4 accv[16];
#pragma unroll
    for (int i = 0; i < 16; i++) accv[i] = make_float4(0.f, 0.f, 0.f, 0.f);
    float rowsum = 0.f;
    const float scale = 0.044194173824159216f;  // 1/sqrt(512)

    for (int t0 = 0; t0 < Ss; t0 += 64) {
#pragma unroll
        for (int l = 0; l < 8; l++) {
            int f = tid + l * 128;
            int row = f >> 4;
            int cq = f & 15;
            int t = t0 + row;
            const float4* kp = (const float4*)&g_K[(size_t)(b * Ss + t) * HD + h * Dd];
            ((float4*)Ksm[row])[cq] = kp[cq];
            const float4* vp = (const float4*)&g_V[(size_t)(b * Ss + t) * HD + h * Dd];
            ((float4*)Vsm[row])[cq] = vp[cq];
        }
        if (tid < 64) biassm[tid] = -1e10f * mask[b * Ss + t0 + tid];
        __syncthreads();

        for (int j = 0; j < 64; j++) {
            const float4* kr = (const float4*)Ksm[j];
            float s0 = 0.f, s1 = 0.f, s2 = 0.f, s3 = 0.f;
#pragma unroll
            for (int i = 0; i < 16; i++) {
                float4 kvv = kr[i];
                s0 = fmaf(qv[i].x, kvv.x, s0);
                s1 = fmaf(qv[i].y, kvv.y, s1);
                s2 = fmaf(qv[i].z, kvv.z, s2);
                s3 = fmaf(qv[i].w, kvv.w, s3);
            }
            float sc = (s0 + s1) + (s2 + s3);
            float p = __expf(fmaf(sc, scale, biassm[j]));
            rowsum += p;
            const float4* vr = (const float4*)Vsm[j];
#pragma unroll
            for (int i = 0; i < 16; i++) {
                float4 vv = vr[i];
                accv[i].x = fmaf(p, vv.x, accv[i].x);
                accv[i].y = fmaf(p, vv.y, accv[i].y);
                accv[i].z = fmaf(p, vv.z, accv[i].z);
                accv[i].w = fmaf(p, vv.w, accv[i].w);
            }
        }
        __syncthreads();
    }

    const float inv = 1.0f / rowsum;
    size_t base = (size_t)(b * Ss + s) * HD + h * Dd;
    uint32_t hibuf[32], lobuf[32];
#pragma unroll
    for (int i = 0; i < 16; i++) {
        float v[4] = {accv[i].x * inv, accv[i].y * inv, accv[i].z * inv, accv[i].w * inv};
        __nv_bfloat16 h4[4], l4[4];
#pragma unroll
        for (int u = 0; u < 4; u++) split_bf16(v[u], h4[u], l4[u]);
        __nv_bfloat162 hp0, hp1, lp0, lp1;
        hp0.x = h4[0]; hp0.y = h4[1]; hp1.x = h4[2]; hp1.y = h4[3];
        lp0.x = l4[0]; lp0.y = l4[1]; lp1.x = l4[2]; lp1.y = l4[3];
        hibuf[2 * i]     = *(uint32_t*)&hp0;
        hibuf[2 * i + 1] = *(uint32_t*)&hp1;
        lobuf[2 * i]     = *(uint32_t*)&lp0;
        lobuf[2 * i + 1] = *(uint32_t*)&lp1;
    }
#pragma unroll
    for (int i = 0; i < 8; i++) {
        *(uint4*)&g_ATh[base + i * 8] = *(uint4*)&hibuf[i * 4];
        *(uint4*)&g_ATl[base + i * 8] = *(uint4*)&lobuf[i * 4];
    }
}

// ---------------------------------------------------------------- launch
extern "C" void kernel_launch(void* const* d_in, const int* in_sizes, int n_in,
                              void* d_out, int out_size)
{
    const float* x    = (const float*)d_in[0];
    const float* mask = (const float*)d_in[1];
    const float* WQ   = (const float*)d_in[2];
    const float* WK   = (const float*)d_in[3];
    const float* WV   = (const float*)d_in[4];
    const float* BE   = (const float*)d_in[5];
    const float* WO   = (const float*)d_in[6];
    float* out        = (float*)d_out;

    prep_a_kernel<<<(Mm * Ee / 4) / 256, 256>>>(x, BE);
    prep_w_kernel<<<(2048 * 512) / 256, 256>>>(WQ, WK, WV, WO);

    dim3 gq(Mm / 128, 512 / 128, 3);
    gemm_bf16x3_kernel<0><<<gq, 256>>>(nullptr);

    dim3 ga(Ss / 128, Hh, Bb);
    attn_kernel<<<ga, 128>>>(mask);

    dim3 go(Mm / 128, 512 / 128, 1);
    gemm_bf16x3_kernel<1><<<go, 256>>>(out);
}

// round 4
// speedup vs baseline: 2.9390x; 1.9360x over previous
#include <cuda_runtime.h>
#include <cuda_bf16.h>
#include <stdint.h>
#include <math.h>

// ---------------------------------------------------------------- dims
static constexpr int Bb = 64;
static constexpr int Ss = 512;
static constexpr int Ee = 512;
static constexpr int Hh = 8;
static constexpr int Dd = 64;
static constexpr int Mm = Bb * Ss;     // 32768
static constexpr int HD = Hh * Dd;     // 512

// ---------------------------------------------------------------- scratch
__device__ __nv_bfloat16 g_Ah[Mm * Ee];
__device__ __nv_bfloat16 g_Al[Mm * Ee];
__device__ __nv_bfloat16 g_ATh[Mm * HD];
__device__ __nv_bfloat16 g_ATl[Mm * HD];
// B matrices, layout B[n][k] (k contiguous):
// rows 0..1535 = WQ/WK/WV (n = h*64+d), rows 1536..2047 = WO^T
__device__ __nv_bfloat16 g_Bh[2048 * 512];
__device__ __nv_bfloat16 g_Bl[2048 * 512];
// Q/K/V in bf16 hi/lo, layout [b*512+s][h*64+d]
__device__ __nv_bfloat16 g_Qh[Mm * HD];
__device__ __nv_bfloat16 g_Ql[Mm * HD];
__device__ __nv_bfloat16 g_Kh[Mm * HD];
__device__ __nv_bfloat16 g_Kl[Mm * HD];
__device__ __nv_bfloat16 g_Vh[Mm * HD];
__device__ __nv_bfloat16 g_Vl[Mm * HD];

// ---------------------------------------------------------------- helpers
__device__ __forceinline__ void split_bf16(float v, __nv_bfloat16& h, __nv_bfloat16& l) {
    h = __float2bfloat16(v);
    l = __float2bfloat16(v - __bfloat162float(h));
}
__device__ __forceinline__ uint32_t pack_pair_hi(float a, float b) {
    __nv_bfloat162 p;
    p.x = __float2bfloat16(a);
    p.y = __float2bfloat16(b);
    return *(uint32_t*)&p;
}
__device__ __forceinline__ uint32_t pack_pair_lo(float a, float b) {
    __nv_bfloat162 p;
    p.x = __float2bfloat16(a - __bfloat162float(__float2bfloat16(a)));
    p.y = __float2bfloat16(b - __bfloat162float(__float2bfloat16(b)));
    return *(uint32_t*)&p;
}
__device__ __forceinline__ uint32_t smem_u32(const void* p) {
    uint32_t a;
    asm("{ .reg .u64 t; cvta.to.shared.u64 t, %1; cvt.u32.u64 %0, t; }" : "=r"(a) : "l"(p));
    return a;
}
__device__ __forceinline__ void ldsm4(uint32_t r[4], uint32_t addr) {
    asm volatile("ldmatrix.sync.aligned.m8n8.x4.shared.b16 {%0,%1,%2,%3}, [%4];"
                 : "=r"(r[0]), "=r"(r[1]), "=r"(r[2]), "=r"(r[3]) : "r"(addr));
}
__device__ __forceinline__ void ldsm4t(uint32_t r[4], uint32_t addr) {
    asm volatile("ldmatrix.sync.aligned.m8n8.x4.trans.shared.b16 {%0,%1,%2,%3}, [%4];"
                 : "=r"(r[0]), "=r"(r[1]), "=r"(r[2]), "=r"(r[3]) : "r"(addr));
}
__device__ __forceinline__ void mma16816(float d[4], const uint32_t a[4],
                                         uint32_t b0, uint32_t b1) {
    asm volatile("mma.sync.aligned.m16n8k16.row.col.f32.bf16.bf16.f32 "
                 "{%0,%1,%2,%3}, {%4,%5,%6,%7}, {%8,%9}, {%0,%1,%2,%3};"
                 : "+f"(d[0]), "+f"(d[1]), "+f"(d[2]), "+f"(d[3])
                 : "r"(a[0]), "r"(a[1]), "r"(a[2]), "r"(a[3]), "r"(b0), "r"(b1));
}

// ---------------------------------------------------------------- prep kernels
__global__ __launch_bounds__(256) void prep_a_kernel(const float* __restrict__ x,
                                                     const float* __restrict__ be) {
    uint32_t i4 = blockIdx.x * 256 + threadIdx.x;
    int m = i4 >> 7;
    int k = (i4 & 127) << 2;
    const float4 xv = *(const float4*)&x[(size_t)m * Ee + k];
    const float4 bv = *(const float4*)&be[(size_t)(m & (Ss - 1)) * Ee + k];
    float v[4] = {xv.x + bv.x, xv.y + bv.y, xv.z + bv.z, xv.w + bv.w};
    size_t o = (size_t)m * Ee + k;
    *(uint32_t*)&g_Ah[o]     = pack_pair_hi(v[0], v[1]);
    *(uint32_t*)&g_Ah[o + 2] = pack_pair_hi(v[2], v[3]);
    *(uint32_t*)&g_Al[o]     = pack_pair_lo(v[0], v[1]);
    *(uint32_t*)&g_Al[o + 2] = pack_pair_lo(v[2], v[3]);
}

__global__ __launch_bounds__(256) void prep_w_kernel(const float* __restrict__ WQ,
                                                     const float* __restrict__ WK,
                                                     const float* __restrict__ WV,
                                                     const float* __restrict__ WO) {
    uint32_t idx = blockIdx.x * 256 + threadIdx.x;
    int r = idx >> 9;
    int k = idx & 511;
    float v;
    if (r < 1536) {
        int z = r >> 9;
        int n = r & 511;
        const float* W = (z == 0) ? WQ : (z == 1) ? WK : WV;
        v = W[(size_t)(n >> 6) * (Ee * Dd) + (size_t)k * Dd + (n & 63)];
    } else {
        int n = r - 1536;
        v = WO[(size_t)k * Ee + n];
    }
    __nv_bfloat16 h, l;
    split_bf16(v, h, l);
    g_Bh[idx] = h;
    g_Bl[idx] = l;
}

// ---------------------------------------------------------------- HMMA GEMM
// C[m,n] = sum_k A[m,k]*B[n,k], bf16x3. CTA tile 128x128, K-chunk 32.
static constexpr int SA_H = 0;
static constexpr int SA_L = 8192;
static constexpr int SB_H = 16384;
static constexpr int SB_L = 24576;

// WHICH=0: QKV projection -> writes bf16 hi/lo (g_Qh.. g_Vl), z picks Q/K/V
// WHICH=1: output projection -> fp32 C = param
template <int WHICH>
__global__ __launch_bounds__(256, 2) void gemm_bf16x3_kernel(float* __restrict__ Cout)
{
    __shared__ __align__(16) char sm[32768];
    const uint32_t sb = smem_u32(sm);
    const int tid  = threadIdx.x;
    const int wid  = tid >> 5;
    const int lane = tid & 31;

    const int m0 = blockIdx.x * 128;
    const int n0 = blockIdx.y * 128;
    const int z  = (WHICH == 0) ? blockIdx.z : 0;

    const __nv_bfloat16* Ah = (WHICH == 0) ? g_Ah : g_ATh;
    const __nv_bfloat16* Al = (WHICH == 0) ? g_Al : g_ATl;
    const size_t boff = (WHICH == 0) ? (size_t)z * 512 * 512 : (size_t)1536 * 512;
    const __nv_bfloat16* Bh = g_Bh + boff;
    const __nv_bfloat16* Bl = g_Bl + boff;

    const int m_warp = (wid & 3) * 32;
    const int n_warp = (wid >> 2) * 64;

    const int rA   = m_warp + (lane & 7) + ((lane >> 3) & 1) * 8;
    const int kbA  = lane >> 4;
    const int sxA  = (rA >> 1) & 3;
    const int rB   = n_warp + (lane & 7) + (lane >> 4) * 8;
    const int kbB  = (lane >> 3) & 1;
    const int sxB  = (rB >> 1) & 3;

    float acc[2][8][4];
#pragma unroll
    for (int i = 0; i < 2; i++)
#pragma unroll
        for (int j = 0; j < 8; j++)
#pragma unroll
            for (int u = 0; u < 4; u++) acc[i][j][u] = 0.f;

    const int grow0 = (tid + 0)   >> 2, gc80 = (tid + 0)   & 3;
    const int grow1 = (tid + 256) >> 2, gc81 = (tid + 256) & 3;
    const uint32_t so0 = grow0 * 64 + ((gc80 ^ ((grow0 >> 1) & 3)) * 16);
    const uint32_t so1 = grow1 * 64 + ((gc81 ^ ((grow1 >> 1) & 3)) * 16);

    for (int c = 0; c < 16; ++c) {
        const int k0 = c * 32;
        {
            size_t gA0 = (size_t)(m0 + grow0) * 512 + k0 + gc80 * 8;
            size_t gA1 = (size_t)(m0 + grow1) * 512 + k0 + gc81 * 8;
            size_t gB0 = (size_t)(n0 + grow0) * 512 + k0 + gc80 * 8;
            size_t gB1 = (size_t)(n0 + grow1) * 512 + k0 + gc81 * 8;
            *(uint4*)(sm + SA_H + so0) = *(const uint4*)&Ah[gA0];
            *(uint4*)(sm + SA_H + so1) = *(const uint4*)&Ah[gA1];
            *(uint4*)(sm + SA_L + so0) = *(const uint4*)&Al[gA0];
            *(uint4*)(sm + SA_L + so1) = *(const uint4*)&Al[gA1];
            *(uint4*)(sm + SB_H + so0) = *(const uint4*)&Bh[gB0];
            *(uint4*)(sm + SB_H + so1) = *(const uint4*)&Bh[gB1];
            *(uint4*)(sm + SB_L + so0) = *(const uint4*)&Bl[gB0];
            *(uint4*)(sm + SB_L + so1) = *(const uint4*)&Bl[gB1];
        }
        __syncthreads();

#pragma unroll
        for (int kk = 0; kk < 2; ++kk) {
            uint32_t ah[2][4], al[2][4];
#pragma unroll
            for (int tm = 0; tm < 2; ++tm) {
                uint32_t ro = (uint32_t)(rA + tm * 16) * 64 +
                              (uint32_t)(((kk * 2 + kbA) ^ sxA) * 16);
                ldsm4(ah[tm], sb + SA_H + ro);
                ldsm4(al[tm], sb + SA_L + ro);
            }
#pragma unroll
            for (int tp = 0; tp < 4; ++tp) {
                uint32_t bh[4], bl[4];
                uint32_t ro = (uint32_t)(rB + tp * 16) * 64 +
                              (uint32_t)(((kk * 2 + kbB) ^ sxB) * 16);
                ldsm4(bh, sb + SB_H + ro);
                ldsm4(bl, sb + SB_L + ro);
#pragma unroll
                for (int tm = 0; tm < 2; ++tm) {
                    mma16816(acc[tm][2 * tp],     ah[tm], bh[0], bh[1]);
                    mma16816(acc[tm][2 * tp],     ah[tm], bl[0], bl[1]);
                    mma16816(acc[tm][2 * tp],     al[tm], bh[0], bh[1]);
                    mma16816(acc[tm][2 * tp + 1], ah[tm], bh[2], bh[3]);
                    mma16816(acc[tm][2 * tp + 1], ah[tm], bl[2], bl[3]);
                    mma16816(acc[tm][2 * tp + 1], al[tm], bh[2], bh[3]);
                }
            }
        }
        __syncthreads();
    }

    // epilogue
    if (WHICH == 0) {
        __nv_bfloat16* Ch = (z == 0) ? g_Qh : (z == 1) ? g_Kh : g_Vh;
        __nv_bfloat16* Cl = (z == 0) ? g_Ql : (z == 1) ? g_Kl : g_Vl;
#pragma unroll
        for (int tm = 0; tm < 2; ++tm) {
            const int m = m0 + m_warp + tm * 16 + (lane >> 2);
#pragma unroll
            for (int tn = 0; tn < 8; ++tn) {
                const int n = n0 + n_warp + tn * 8 + (lane & 3) * 2;
                size_t o0 = (size_t)m * 512 + n;
                size_t o1 = (size_t)(m + 8) * 512 + n;
                *(uint32_t*)&Ch[o0] = pack_pair_hi(acc[tm][tn][0], acc[tm][tn][1]);
                *(uint32_t*)&Cl[o0] = pack_pair_lo(acc[tm][tn][0], acc[tm][tn][1]);
                *(uint32_t*)&Ch[o1] = pack_pair_hi(acc[tm][tn][2], acc[tm][tn][3]);
                *(uint32_t*)&Cl[o1] = pack_pair_lo(acc[tm][tn][2], acc[tm][tn][3]);
            }
        }
    } else {
#pragma unroll
        for (int tm = 0; tm < 2; ++tm) {
            const int m = m0 + m_warp + tm * 16 + (lane >> 2);
#pragma unroll
            for (int tn = 0; tn < 8; ++tn) {
                const int n = n0 + n_warp + tn * 8 + (lane & 3) * 2;
                *(float2*)&Cout[(size_t)m * 512 + n] =
                    make_float2(acc[tm][tn][0], acc[tm][tn][1]);
                *(float2*)&Cout[(size_t)(m + 8) * 512 + n] =
                    make_float2(acc[tm][tn][2], acc[tm][tn][3]);
            }
        }
    }
}

// ---------------------------------------------------------------- tensor-core attention
// CTA: 128 queries x one (b,h). Key tiles of 64. bf16x3 for QK^T and PV.
// SMEM: 128B rows, 8x16B chunks, swizzle chunk' = chunk ^ (row & 7).
static constexpr int A_QH = 0;
static constexpr int A_QL = 16384;
static constexpr int A_KH = 32768;
static constexpr int A_KL = 40960;
static constexpr int A_VH = 49152;
static constexpr int A_VL = 57344;
static constexpr int A_PH = 65536;
static constexpr int A_PL = 81920;
static constexpr int A_BI = 98304;   // 512 floats
static constexpr int A_RS = 100352;  // 2 x 128 floats
static constexpr int ATTN_SMEM = 101376;

__global__ __launch_bounds__(256, 2) void attn_mma_kernel(const float* __restrict__ mask)
{
    extern __shared__ char sm[];
    const uint32_t sb = smem_u32(sm);
    const int tid  = threadIdx.x;
    const int wid  = tid >> 5;
    const int lane = tid & 31;

    const int qt = blockIdx.x;
    const int h  = blockIdx.y;
    const int b  = blockIdx.z;
    const int mq = (wid & 3) * 32;    // warp q-offset
    const int kw = wid >> 2;          // S: k-warp | PV: d-warp
    const size_t qrow0 = (size_t)b * 512 + qt * 128;

    // load Q hi/lo into swizzled smem
#pragma unroll
    for (int i = 0; i < 4; i++) {
        int idx = tid + i * 256;          // 0..1023
        int row = idx >> 3, c = idx & 7;
        uint32_t so = row * 128 + ((c ^ (row & 7)) * 16);
        size_t g = (qrow0 + row) * 512 + h * 64 + c * 8;
        *(uint4*)(sm + A_QH + so) = *(const uint4*)&g_Qh[g];
        *(uint4*)(sm + A_QL + so) = *(const uint4*)&g_Ql[g];
    }
    // bias (already includes -1e10 factor)
#pragma unroll
    for (int i = 0; i < 2; i++) {
        int t = tid + i * 256;
        ((float*)(sm + A_BI))[t] = -1e10f * mask[b * 512 + t];
    }

    float accO[2][4][4];
#pragma unroll
    for (int i = 0; i < 2; i++)
#pragma unroll
        for (int j = 0; j < 4; j++)
#pragma unroll
            for (int u = 0; u < 4; u++) accO[i][j][u] = 0.f;
    float rsum[2][2] = {{0.f, 0.f}, {0.f, 0.f}};

    const float scale = 0.044194173824159216f;  // 1/sqrt(512)

    // ldmatrix lane geometry
    const int rowA = mq + (lane & 7) + ((lane >> 3) & 1) * 8;   // + tm*16 (Q and P)
    const int cA   = lane >> 4;
    const int rowB = kw * 32 + (lane & 7) + (lane >> 4) * 8;    // + tb*16 (K)
    const int cB   = (lane >> 3) & 1;
    const int rowV = (lane & 7) + ((lane >> 3) & 1) * 8;        // + ks*16 (V, trans)
    const int cV   = lane >> 4;

    for (int tile = 0; tile < 8; ++tile) {
        const int t0 = tile * 64;
        __syncthreads();
        // K/V tile load (hi/lo), swizzled
#pragma unroll
        for (int i = 0; i < 2; i++) {
            int idx = tid + i * 256;      // 0..511
            int row = idx >> 3, c = idx & 7;
            uint32_t so = row * 128 + ((c ^ (row & 7)) * 16);
            size_t g = ((size_t)b * 512 + t0 + row) * 512 + h * 64 + c * 8;
            *(uint4*)(sm + A_KH + so) = *(const uint4*)&g_Kh[g];
            *(uint4*)(sm + A_KL + so) = *(const uint4*)&g_Kl[g];
            *(uint4*)(sm + A_VH + so) = *(const uint4*)&g_Vh[g];
            *(uint4*)(sm + A_VL + so) = *(const uint4*)&g_Vl[g];
        }
        __syncthreads();

        // ---- S = Q K^T (128q x 64k tile, warp 32x32)
        float accS[2][4][4];
#pragma unroll
        for (int i = 0; i < 2; i++)
#pragma unroll
            for (int j = 0; j < 4; j++)
#pragma unroll
                for (int u = 0; u < 4; u++) accS[i][j][u] = 0.f;

#pragma unroll
        for (int ks = 0; ks < 4; ++ks) {
            uint32_t qh[2][4], ql[2][4];
#pragma unroll
            for (int tm = 0; tm < 2; ++tm) {
                int row = rowA + tm * 16;
                int c = ks * 2 + cA;
                uint32_t so = row * 128 + ((c ^ (row & 7)) * 16);
                ldsm4(qh[tm], sb + A_QH + so);
                ldsm4(ql[tm], sb + A_QL + so);
            }
#pragma unroll
            for (int tb = 0; tb < 2; ++tb) {
                uint32_t kh[4], kl[4];
                int row = rowB + tb * 16;
                int c = ks * 2 + cB;
                uint32_t so = row * 128 + ((c ^ (row & 7)) * 16);
                ldsm4(kh, sb + A_KH + so);
                ldsm4(kl, sb + A_KL + so);
#pragma unroll
                for (int tm = 0; tm < 2; ++tm) {
                    mma16816(accS[tm][tb * 2],     qh[tm], kh[0], kh[1]);
                    mma16816(accS[tm][tb * 2],     qh[tm], kl[0], kl[1]);
                    mma16816(accS[tm][tb * 2],     ql[tm], kh[0], kh[1]);
                    mma16816(accS[tm][tb * 2 + 1], qh[tm], kh[2], kh[3]);
                    mma16816(accS[tm][tb * 2 + 1], qh[tm], kl[2], kl[3]);
                    mma16816(accS[tm][tb * 2 + 1], ql[tm], kh[2], kh[3]);
                }
            }
        }

        // ---- exp + rowsum + pack P to smem
#pragma unroll
        for (int tn = 0; tn < 4; ++tn) {
            int tloc = kw * 32 + tn * 8 + (lane & 3) * 2;
            float b0 = ((float*)(sm + A_BI))[t0 + tloc];
            float b1 = ((float*)(sm + A_BI))[t0 + tloc + 1];
#pragma unroll
            for (int tm = 0; tm < 2; ++tm) {
                float p0 = __expf(fmaf(accS[tm][tn][0], scale, b0));
                float p1 = __expf(fmaf(accS[tm][tn][1], scale, b1));
                float p2 = __expf(fmaf(accS[tm][tn][2], scale, b0));
                float p3 = __expf(fmaf(accS[tm][tn][3], scale, b1));
                rsum[tm][0] += p0 + p1;
                rsum[tm][1] += p2 + p3;
                int c = kw * 4 + tn;
                int rlo = mq + tm * 16 + (lane >> 2);
                int rhi = rlo + 8;
                uint32_t slo = rlo * 128 + ((c ^ (rlo & 7)) * 16) + (lane & 3) * 4;
                uint32_t shi = rhi * 128 + ((c ^ (rhi & 7)) * 16) + (lane & 3) * 4;
                *(uint32_t*)(sm + A_PH + slo) = pack_pair_hi(p0, p1);
                *(uint32_t*)(sm + A_PL + slo) = pack_pair_lo(p0, p1);
                *(uint32_t*)(sm + A_PH + shi) = pack_pair_hi(p2, p3);
                *(uint32_t*)(sm + A_PL + shi) = pack_pair_lo(p2, p3);
            }
        }
        __syncthreads();

        // ---- O += P V  (A = P 128x64, B = V^T via ldmatrix.trans)
#pragma unroll
        for (int ks = 0; ks < 4; ++ks) {
            uint32_t ph[2][4], pl[2][4];
#pragma unroll
            for (int tm = 0; tm < 2; ++tm) {
                int row = rowA + tm * 16;
                int c = ks * 2 + cA;
                uint32_t so = row * 128 + ((c ^ (row & 7)) * 16);
                ldsm4(ph[tm], sb + A_PH + so);
                ldsm4(pl[tm], sb + A_PL + so);
            }
#pragma unroll
            for (int d16 = 0; d16 < 2; ++d16) {
                uint32_t vh[4], vl[4];
                int row = ks * 16 + rowV;
                int c = kw * 4 + d16 * 2 + cV;
                uint32_t so = row * 128 + ((c ^ (row & 7)) * 16);
                ldsm4t(vh, sb + A_VH + so);
                ldsm4t(vl, sb + A_VL + so);
#pragma unroll
                for (int tm = 0; tm < 2; ++tm) {
                    mma16816(accO[tm][d16 * 2],     ph[tm], vh[0], vh[1]);
                    mma16816(accO[tm][d16 * 2],     ph[tm], vl[0], vl[1]);
                    mma16816(accO[tm][d16 * 2],     pl[tm], vh[0], vh[1]);
                    mma16816(accO[tm][d16 * 2 + 1], ph[tm], vh[2], vh[3]);
                    mma16816(accO[tm][d16 * 2 + 1], ph[tm], vl[2], vl[3]);
                    mma16816(accO[tm][d16 * 2 + 1], pl[tm], vh[2], vh[3]);
                }
            }
        }
    }

    // ---- rowsum reduce across quad lanes and the 2 k-warps
    float* RSp = (float*)(sm + A_RS);
#pragma unroll
    for (int tm = 0; tm < 2; ++tm)
#pragma unroll
        for (int u = 0; u < 2; ++u) {
            float v = rsum[tm][u];
            v += __shfl_xor_sync(0xffffffffu, v, 1);
            v += __shfl_xor_sync(0xffffffffu, v, 2);
            rsum[tm][u] = v;
        }
    if ((lane & 3) == 0) {
#pragma unroll
        for (int tm = 0; tm < 2; ++tm) {
            int rlo = mq + tm * 16 + (lane >> 2);
            RSp[kw * 128 + rlo]     = rsum[tm][0];
            RSp[kw * 128 + rlo + 8] = rsum[tm][1];
        }
    }
    __syncthreads();

    // ---- normalize + store O as bf16 hi/lo
#pragma unroll
    for (int tm = 0; tm < 2; ++tm) {
        int rlo = mq + tm * 16 + (lane >> 2);
        int rhi = rlo + 8;
        float invlo = 1.f / (RSp[rlo] + RSp[128 + rlo]);
        float invhi = 1.f / (RSp[rhi] + RSp[128 + rhi]);
        size_t glo = (qrow0 + rlo) * 512 + h * 64;
        size_t ghi = (qrow0 + rhi) * 512 + h * 64;
#pragma unroll
        for (int tn = 0; tn < 4; ++tn) {
            int d = kw * 32 + tn * 8 + (lane & 3) * 2;
            float o0 = accO[tm][tn][0] * invlo, o1 = accO[tm][tn][1] * invlo;
            float o2 = accO[tm][tn][2] * invhi, o3 = accO[tm][tn][3] * invhi;
            *(uint32_t*)&g_ATh[glo + d] = pack_pair_hi(o0, o1);
            *(uint32_t*)&g_ATl[glo + d] = pack_pair_lo(o0, o1);
            *(uint32_t*)&g_ATh[ghi + d] = pack_pair_hi(o2, o3);
            *(uint32_t*)&g_ATl[ghi + d] = pack_pair_lo(o2, o3);
        }
    }
}

// ---------------------------------------------------------------- launch
extern "C" void kernel_launch(void* const* d_in, const int* in_sizes, int n_in,
                              void* d_out, int out_size)
{
    const float* x    = (const float*)d_in[0];
    const float* mask = (const float*)d_in[1];
    const float* WQ   = (const float*)d_in[2];
    const float* WK   = (const float*)d_in[3];
    const float* WV   = (const float*)d_in[4];
    const float* BE   = (const float*)d_in[5];
    const float* WO   = (const float*)d_in[6];
    float* out        = (float*)d_out;

    cudaFuncSetAttribute(attn_mma_kernel,
                         cudaFuncAttributeMaxDynamicSharedMemorySize, ATTN_SMEM);

    prep_a_kernel<<<(Mm * Ee / 4) / 256, 256>>>(x, BE);
    prep_w_kernel<<<(2048 * 512) / 256, 256>>>(WQ, WK, WV, WO);

    dim3 gq(Mm / 128, 512 / 128, 3);
    gemm_bf16x3_kernel<0><<<gq, 256>>>(nullptr);

    dim3 ga(Ss / 128, Hh, Bb);
    attn_mma_kernel<<<ga, 256, ATTN_SMEM>>>(mask);

    dim3 go(Mm / 128, 512 / 128, 1);
    gemm_bf16x3_kernel<1><<<go, 256>>>(out);
}

// round 5
// speedup vs baseline: 3.3017x; 1.1234x over previous
#include <cuda_runtime.h>
#include <cuda_bf16.h>
#include <stdint.h>
#include <math.h>

// ---------------------------------------------------------------- dims
static constexpr int Bb = 64;
static constexpr int Ss = 512;
static constexpr int Ee = 512;
static constexpr int Hh = 8;
static constexpr int Dd = 64;
static constexpr int Mm = Bb * Ss;     // 32768
static constexpr int HD = Hh * Dd;     // 512

// ---------------------------------------------------------------- scratch
__device__ __nv_bfloat16 g_Ah[Mm * Ee];
__device__ __nv_bfloat16 g_Al[Mm * Ee];
__device__ __nv_bfloat16 g_ATh[Mm * HD];
__device__ __nv_bfloat16 g_ATl[Mm * HD];
__device__ __nv_bfloat16 g_Bh[2048 * 512];
__device__ __nv_bfloat16 g_Bl[2048 * 512];
__device__ __nv_bfloat16 g_Qh[Mm * HD];
__device__ __nv_bfloat16 g_Ql[Mm * HD];
__device__ __nv_bfloat16 g_Kh[Mm * HD];
__device__ __nv_bfloat16 g_Kl[Mm * HD];
__device__ __nv_bfloat16 g_Vh[Mm * HD];
__device__ __nv_bfloat16 g_Vl[Mm * HD];

// ---------------------------------------------------------------- helpers
__device__ __forceinline__ void split_bf16(float v, __nv_bfloat16& h, __nv_bfloat16& l) {
    h = __float2bfloat16(v);
    l = __float2bfloat16(v - __bfloat162float(h));
}
__device__ __forceinline__ uint32_t pack_pair_hi(float a, float b) {
    __nv_bfloat162 p;
    p.x = __float2bfloat16(a);
    p.y = __float2bfloat16(b);
    return *(uint32_t*)&p;
}
__device__ __forceinline__ uint32_t pack_pair_lo(float a, float b) {
    __nv_bfloat162 p;
    p.x = __float2bfloat16(a - __bfloat162float(__float2bfloat16(a)));
    p.y = __float2bfloat16(b - __bfloat162float(__float2bfloat16(b)));
    return *(uint32_t*)&p;
}
__device__ __forceinline__ uint32_t smem_u32(const void* p) {
    uint32_t a;
    asm("{ .reg .u64 t; cvta.to.shared.u64 t, %1; cvt.u32.u64 %0, t; }" : "=r"(a) : "l"(p));
    return a;
}
__device__ __forceinline__ void ldsm4(uint32_t r[4], uint32_t addr) {
    asm volatile("ldmatrix.sync.aligned.m8n8.x4.shared.b16 {%0,%1,%2,%3}, [%4];"
                 : "=r"(r[0]), "=r"(r[1]), "=r"(r[2]), "=r"(r[3]) : "r"(addr));
}
__device__ __forceinline__ void ldsm4t(uint32_t r[4], uint32_t addr) {
    asm volatile("ldmatrix.sync.aligned.m8n8.x4.trans.shared.b16 {%0,%1,%2,%3}, [%4];"
                 : "=r"(r[0]), "=r"(r[1]), "=r"(r[2]), "=r"(r[3]) : "r"(addr));
}
__device__ __forceinline__ void mma16816(float d[4], const uint32_t a[4],
                                         uint32_t b0, uint32_t b1) {
    asm volatile("mma.sync.aligned.m16n8k16.row.col.f32.bf16.bf16.f32 "
                 "{%0,%1,%2,%3}, {%4,%5,%6,%7}, {%8,%9}, {%0,%1,%2,%3};"
                 : "+f"(d[0]), "+f"(d[1]), "+f"(d[2]), "+f"(d[3])
                 : "r"(a[0]), "r"(a[1]), "r"(a[2]), "r"(a[3]), "r"(b0), "r"(b1));
}
__device__ __forceinline__ void cpasync16(uint32_t saddr, const void* g) {
    asm volatile("cp.async.cg.shared.global [%0], [%1], 16;" :: "r"(saddr), "l"(g));
}
__device__ __forceinline__ void cpcommit() {
    asm volatile("cp.async.commit_group;" ::: "memory");
}
template <int N>
__device__ __forceinline__ void cpwait() {
    asm volatile("cp.async.wait_group %0;" :: "n"(N) : "memory");
}

// ---------------------------------------------------------------- prep kernels
__global__ __launch_bounds__(256) void prep_a_kernel(const float* __restrict__ x,
                                                     const float* __restrict__ be) {
    uint32_t i4 = blockIdx.x * 256 + threadIdx.x;
    int m = i4 >> 7;
    int k = (i4 & 127) << 2;
    const float4 xv = *(const float4*)&x[(size_t)m * Ee + k];
    const float4 bv = *(const float4*)&be[(size_t)(m & (Ss - 1)) * Ee + k];
    float v[4] = {xv.x + bv.x, xv.y + bv.y, xv.z + bv.z, xv.w + bv.w};
    size_t o = (size_t)m * Ee + k;
    *(uint32_t*)&g_Ah[o]     = pack_pair_hi(v[0], v[1]);
    *(uint32_t*)&g_Ah[o + 2] = pack_pair_hi(v[2], v[3]);
    *(uint32_t*)&g_Al[o]     = pack_pair_lo(v[0], v[1]);
    *(uint32_t*)&g_Al[o + 2] = pack_pair_lo(v[2], v[3]);
}

__global__ __launch_bounds__(256) void prep_w_kernel(const float* __restrict__ WQ,
                                                     const float* __restrict__ WK,
                                                     const float* __restrict__ WV,
                                                     const float* __restrict__ WO) {
    uint32_t idx = blockIdx.x * 256 + threadIdx.x;
    int r = idx >> 9;
    int k = idx & 511;
    float v;
    if (r < 1536) {
        int z = r >> 9;
        int n = r & 511;
        const float* W = (z == 0) ? WQ : (z == 1) ? WK : WV;
        v = W[(size_t)(n >> 6) * (Ee * Dd) + (size_t)k * Dd + (n & 63)];
    } else {
        int n = r - 1536;
        v = WO[(size_t)k * Ee + n];
    }
    __nv_bfloat16 h, l;
    split_bf16(v, h, l);
    g_Bh[idx] = h;
    g_Bl[idx] = l;
}

// ---------------------------------------------------------------- HMMA GEMM (cp.async 2-stage)
static constexpr int SA_H = 0;
static constexpr int SA_L = 8192;
static constexpr int SB_H = 16384;
static constexpr int SB_L = 24576;
static constexpr int GSTAGE = 32768;
static constexpr int GEMM_SMEM = 2 * GSTAGE;   // 64 KB

template <int WHICH>
__global__ __launch_bounds__(256, 2) void gemm_bf16x3_kernel(float* __restrict__ Cout)
{
    extern __shared__ __align__(16) char sm[];
    const uint32_t sb = smem_u32(sm);
    const int tid  = threadIdx.x;
    const int wid  = tid >> 5;
    const int lane = tid & 31;

    const int m0 = blockIdx.x * 128;
    const int n0 = blockIdx.y * 128;
    const int z  = (WHICH == 0) ? blockIdx.z : 0;

    const __nv_bfloat16* Ah = (WHICH == 0) ? g_Ah : g_ATh;
    const __nv_bfloat16* Al = (WHICH == 0) ? g_Al : g_ATl;
    const size_t boff = (WHICH == 0) ? (size_t)z * 512 * 512 : (size_t)1536 * 512;
    const __nv_bfloat16* Bh = g_Bh + boff;
    const __nv_bfloat16* Bl = g_Bl + boff;

    const int m_warp = (wid & 3) * 32;
    const int n_warp = (wid >> 2) * 64;

    const int rA   = m_warp + (lane & 7) + ((lane >> 3) & 1) * 8;
    const int kbA  = lane >> 4;
    const int sxA  = (rA >> 1) & 3;
    const int rB   = n_warp + (lane & 7) + (lane >> 4) * 8;
    const int kbB  = (lane >> 3) & 1;
    const int sxB  = (rB >> 1) & 3;

    float acc[2][8][4];
#pragma unroll
    for (int i = 0; i < 2; i++)
#pragma unroll
        for (int j = 0; j < 8; j++)
#pragma unroll
            for (int u = 0; u < 4; u++) acc[i][j][u] = 0.f;

    // global / smem load geometry
    const int grow0 = (tid + 0)   >> 2, gc80 = (tid + 0)   & 3;
    const int grow1 = (tid + 256) >> 2, gc81 = (tid + 256) & 3;
    const uint32_t so0 = grow0 * 64 + ((gc80 ^ ((grow0 >> 1) & 3)) * 16);
    const uint32_t so1 = grow1 * 64 + ((gc81 ^ ((grow1 >> 1) & 3)) * 16);
    const __nv_bfloat16* pAh0 = Ah + (size_t)(m0 + grow0) * 512 + gc80 * 8;
    const __nv_bfloat16* pAh1 = Ah + (size_t)(m0 + grow1) * 512 + gc81 * 8;
    const __nv_bfloat16* pAl0 = Al + (size_t)(m0 + grow0) * 512 + gc80 * 8;
    const __nv_bfloat16* pAl1 = Al + (size_t)(m0 + grow1) * 512 + gc81 * 8;
    const __nv_bfloat16* pBh0 = Bh + (size_t)(n0 + grow0) * 512 + gc80 * 8;
    const __nv_bfloat16* pBh1 = Bh + (size_t)(n0 + grow1) * 512 + gc81 * 8;
    const __nv_bfloat16* pBl0 = Bl + (size_t)(n0 + grow0) * 512 + gc80 * 8;
    const __nv_bfloat16* pBl1 = Bl + (size_t)(n0 + grow1) * 512 + gc81 * 8;

#define LOAD_CHUNK(k0, stage) do {                                        \
        uint32_t s_ = sb + (stage) * GSTAGE;                              \
        cpasync16(s_ + SA_H + so0, pAh0 + (k0));                          \
        cpasync16(s_ + SA_H + so1, pAh1 + (k0));                          \
        cpasync16(s_ + SA_L + so0, pAl0 + (k0));                          \
        cpasync16(s_ + SA_L + so1, pAl1 + (k0));                          \
        cpasync16(s_ + SB_H + so0, pBh0 + (k0));                          \
        cpasync16(s_ + SB_H + so1, pBh1 + (k0));                          \
        cpasync16(s_ + SB_L + so0, pBl0 + (k0));                          \
        cpasync16(s_ + SB_L + so1, pBl1 + (k0));                          \
        cpcommit();                                                       \
    } while (0)

    LOAD_CHUNK(0, 0);
    LOAD_CHUNK(32, 1);

    for (int c = 0; c < 16; ++c) {
        if (c < 15) cpwait<1>(); else cpwait<0>();
        __syncthreads();

        const uint32_t sbs = sb + (c & 1) * GSTAGE;
#pragma unroll
        for (int kk = 0; kk < 2; ++kk) {
            uint32_t ah[2][4], al[2][4];
#pragma unroll
            for (int tm = 0; tm < 2; ++tm) {
                uint32_t ro = (uint32_t)(rA + tm * 16) * 64 +
                              (uint32_t)(((kk * 2 + kbA) ^ sxA) * 16);
                ldsm4(ah[tm], sbs + SA_H + ro);
                ldsm4(al[tm], sbs + SA_L + ro);
            }
#pragma unroll
            for (int tp = 0; tp < 4; ++tp) {
                uint32_t bh[4], bl[4];
                uint32_t ro = (uint32_t)(rB + tp * 16) * 64 +
                              (uint32_t)(((kk * 2 + kbB) ^ sxB) * 16);
                ldsm4(bh, sbs + SB_H + ro);
                ldsm4(bl, sbs + SB_L + ro);
#pragma unroll
                for (int tm = 0; tm < 2; ++tm) {
                    mma16816(acc[tm][2 * tp],     ah[tm], bh[0], bh[1]);
                    mma16816(acc[tm][2 * tp],     ah[tm], bl[0], bl[1]);
                    mma16816(acc[tm][2 * tp],     al[tm], bh[0], bh[1]);
                    mma16816(acc[tm][2 * tp + 1], ah[tm], bh[2], bh[3]);
                    mma16816(acc[tm][2 * tp + 1], ah[tm], bl[2], bl[3]);
                    mma16816(acc[tm][2 * tp + 1], al[tm], bh[2], bh[3]);
                }
            }
        }
        __syncthreads();
        if (c + 2 < 16) LOAD_CHUNK((c + 2) * 32, c & 1);
    }
#undef LOAD_CHUNK

    // epilogue
    if (WHICH == 0) {
        __nv_bfloat16* Ch = (z == 0) ? g_Qh : (z == 1) ? g_Kh : g_Vh;
        __nv_bfloat16* Cl = (z == 0) ? g_Ql : (z == 1) ? g_Kl : g_Vl;
#pragma unroll
        for (int tm = 0; tm < 2; ++tm) {
            const int m = m0 + m_warp + tm * 16 + (lane >> 2);
#pragma unroll
            for (int tn = 0; tn < 8; ++tn) {
                const int n = n0 + n_warp + tn * 8 + (lane & 3) * 2;
                size_t o0 = (size_t)m * 512 + n;
                size_t o1 = (size_t)(m + 8) * 512 + n;
                *(uint32_t*)&Ch[o0] = pack_pair_hi(acc[tm][tn][0], acc[tm][tn][1]);
                *(uint32_t*)&Cl[o0] = pack_pair_lo(acc[tm][tn][0], acc[tm][tn][1]);
                *(uint32_t*)&Ch[o1] = pack_pair_hi(acc[tm][tn][2], acc[tm][tn][3]);
                *(uint32_t*)&Cl[o1] = pack_pair_lo(acc[tm][tn][2], acc[tm][tn][3]);
            }
        }
    } else {
#pragma unroll
        for (int tm = 0; tm < 2; ++tm) {
            const int m = m0 + m_warp + tm * 16 + (lane >> 2);
#pragma unroll
            for (int tn = 0; tn < 8; ++tn) {
                const int n = n0 + n_warp + tn * 8 + (lane & 3) * 2;
                *(float2*)&Cout[(size_t)m * 512 + n] =
                    make_float2(acc[tm][tn][0], acc[tm][tn][1]);
                *(float2*)&Cout[(size_t)(m + 8) * 512 + n] =
                    make_float2(acc[tm][tn][2], acc[tm][tn][3]);
            }
        }
    }
}

// ---------------------------------------------------------------- tensor-core attention
static constexpr int A_QH = 0;
static constexpr int A_QL = 16384;
static constexpr int A_KH = 32768;
static constexpr int A_KL = 40960;
static constexpr int A_VH = 49152;
static constexpr int A_VL = 57344;
static constexpr int A_PH = 65536;
static constexpr int A_PL = 81920;
static constexpr int A_BI = 98304;   // 512 floats
static constexpr int A_RS = 100352;  // 2 x 128 floats
static constexpr int ATTN_SMEM = 101376;

__global__ __launch_bounds__(256, 2) void attn_mma_kernel(const float* __restrict__ mask)
{
    extern __shared__ char sm[];
    const uint32_t sb = smem_u32(sm);
    const int tid  = threadIdx.x;
    const int wid  = tid >> 5;
    const int lane = tid & 31;

    const int qt = blockIdx.x;
    const int h  = blockIdx.y;
    const int b  = blockIdx.z;
    const int mq = (wid & 3) * 32;
    const int kw = wid >> 2;
    const size_t qrow0 = (size_t)b * 512 + qt * 128;

    // Q hi/lo -> swizzled smem (async)
#pragma unroll
    for (int i = 0; i < 4; i++) {
        int idx = tid + i * 256;
        int row = idx >> 3, c = idx & 7;
        uint32_t so = row * 128 + ((c ^ (row & 7)) * 16);
        size_t g = (qrow0 + row) * 512 + h * 64 + c * 8;
        cpasync16(sb + A_QH + so, &g_Qh[g]);
        cpasync16(sb + A_QL + so, &g_Ql[g]);
    }
#pragma unroll
    for (int i = 0; i < 2; i++) {
        int t = tid + i * 256;
        ((float*)(sm + A_BI))[t] = -1e10f * mask[b * 512 + t];
    }
    cpcommit();

    float accO[2][4][4];
#pragma unroll
    for (int i = 0; i < 2; i++)
#pragma unroll
        for (int j = 0; j < 4; j++)
#pragma unroll
            for (int u = 0; u < 4; u++) accO[i][j][u] = 0.f;
    float rsum[2][2] = {{0.f, 0.f}, {0.f, 0.f}};

    const float scale = 0.044194173824159216f;

    const int rowA = mq + (lane & 7) + ((lane >> 3) & 1) * 8;
    const int cA   = lane >> 4;
    const int rowB = kw * 32 + (lane & 7) + (lane >> 4) * 8;
    const int cB   = (lane >> 3) & 1;
    const int rowV = (lane & 7) + ((lane >> 3) & 1) * 8;
    const int cV   = lane >> 4;

    for (int tile = 0; tile < 8; ++tile) {
        const int t0 = tile * 64;
        __syncthreads();
#pragma unroll
        for (int i = 0; i < 2; i++) {
            int idx = tid + i * 256;
            int row = idx >> 3, c = idx & 7;
            uint32_t so = row * 128 + ((c ^ (row & 7)) * 16);
            size_t g = ((size_t)b * 512 + t0 + row) * 512 + h * 64 + c * 8;
            cpasync16(sb + A_KH + so, &g_Kh[g]);
            cpasync16(sb + A_KL + so, &g_Kl[g]);
            cpasync16(sb + A_VH + so, &g_Vh[g]);
            cpasync16(sb + A_VL + so, &g_Vl[g]);
        }
        cpcommit();
        cpwait<0>();
        __syncthreads();

        // ---- S = Q K^T
        float accS[2][4][4];
#pragma unroll
        for (int i = 0; i < 2; i++)
#pragma unroll
            for (int j = 0; j < 4; j++)
#pragma unroll
                for (int u = 0; u < 4; u++) accS[i][j][u] = 0.f;

#pragma unroll
        for (int ks = 0; ks < 4; ++ks) {
            uint32_t qh[2][4], ql[2][4];
#pragma unroll
            for (int tm = 0; tm < 2; ++tm) {
                int row = rowA + tm * 16;
                int c = ks * 2 + cA;
                uint32_t so = row * 128 + ((c ^ (row & 7)) * 16);
                ldsm4(qh[tm], sb + A_QH + so);
                ldsm4(ql[tm], sb + A_QL + so);
            }
#pragma unroll
            for (int tb = 0; tb < 2; ++tb) {
                uint32_t kh[4], kl[4];
                int row = rowB + tb * 16;
                int c = ks * 2 + cB;
                uint32_t so = row * 128 + ((c ^ (row & 7)) * 16);
                ldsm4(kh, sb + A_KH + so);
                ldsm4(kl, sb + A_KL + so);
#pragma unroll
                for (int tm = 0; tm < 2; ++tm) {
                    mma16816(accS[tm][tb * 2],     qh[tm], kh[0], kh[1]);
                    mma16816(accS[tm][tb * 2],     qh[tm], kl[0], kl[1]);
                    mma16816(accS[tm][tb * 2],     ql[tm], kh[0], kh[1]);
                    mma16816(accS[tm][tb * 2 + 1], qh[tm], kh[2], kh[3]);
                    mma16816(accS[tm][tb * 2 + 1], qh[tm], kl[2], kl[3]);
                    mma16816(accS[tm][tb * 2 + 1], ql[tm], kh[2], kh[3]);
                }
            }
        }

        // ---- exp + rowsum + pack P
#pragma unroll
        for (int tn = 0; tn < 4; ++tn) {
            int tloc = kw * 32 + tn * 8 + (lane & 3) * 2;
            float b0 = ((float*)(sm + A_BI))[t0 + tloc];
            float b1 = ((float*)(sm + A_BI))[t0 + tloc + 1];
#pragma unroll
            for (int tm = 0; tm < 2; ++tm) {
                float p0 = __expf(fmaf(accS[tm][tn][0], scale, b0));
                float p1 = __expf(fmaf(accS[tm][tn][1], scale, b1));
                float p2 = __expf(fmaf(accS[tm][tn][2], scale, b0));
                float p3 = __expf(fmaf(accS[tm][tn][3], scale, b1));
                rsum[tm][0] += p0 + p1;
                rsum[tm][1] += p2 + p3;
                int c = kw * 4 + tn;
                int rlo = mq + tm * 16 + (lane >> 2);
                int rhi = rlo + 8;
                uint32_t slo = rlo * 128 + ((c ^ (rlo & 7)) * 16) + (lane & 3) * 4;
                uint32_t shi = rhi * 128 + ((c ^ (rhi & 7)) * 16) + (lane & 3) * 4;
                *(uint32_t*)(sm + A_PH + slo) = pack_pair_hi(p0, p1);
                *(uint32_t*)(sm + A_PL + slo) = pack_pair_lo(p0, p1);
                *(uint32_t*)(sm + A_PH + shi) = pack_pair_hi(p2, p3);
                *(uint32_t*)(sm + A_PL + shi) = pack_pair_lo(p2, p3);
            }
        }
        __syncthreads();

        // ---- O += P V
#pragma unroll
        for (int ks = 0; ks < 4; ++ks) {
            uint32_t ph[2][4], pl[2][4];
#pragma unroll
            for (int tm = 0; tm < 2; ++tm) {
                int row = rowA + tm * 16;
                int c = ks * 2 + cA;
                uint32_t so = row * 128 + ((c ^ (row & 7)) * 16);
                ldsm4(ph[tm], sb + A_PH + so);
                ldsm4(pl[tm], sb + A_PL + so);
            }
#pragma unroll
            for (int d16 = 0; d16 < 2; ++d16) {
                uint32_t vh[4], vl[4];
                int row = ks * 16 + rowV;
                int c = kw * 4 + d16 * 2 + cV;
                uint32_t so = row * 128 + ((c ^ (row & 7)) * 16);
                ldsm4t(vh, sb + A_VH + so);
                ldsm4t(vl, sb + A_VL + so);
#pragma unroll
                for (int tm = 0; tm < 2; ++tm) {
                    mma16816(accO[tm][d16 * 2],     ph[tm], vh[0], vh[1]);
                    mma16816(accO[tm][d16 * 2],     ph[tm], vl[0], vl[1]);
                    mma16816(accO[tm][d16 * 2],     pl[tm], vh[0], vh[1]);
                    mma16816(accO[tm][d16 * 2 + 1], ph[tm], vh[2], vh[3]);
                    mma16816(accO[tm][d16 * 2 + 1], ph[tm], vl[2], vl[3]);
                    mma16816(accO[tm][d16 * 2 + 1], pl[tm], vh[2], vh[3]);
                }
            }
        }
    }

    // ---- rowsum reduce
    float* RSp = (float*)(sm + A_RS);
#pragma unroll
    for (int tm = 0; tm < 2; ++tm)
#pragma unroll
        for (int u = 0; u < 2; ++u) {
            float v = rsum[tm][u];
            v += __shfl_xor_sync(0xffffffffu, v, 1);
            v += __shfl_xor_sync(0xffffffffu, v, 2);
            rsum[tm][u] = v;
        }
    if ((lane & 3) == 0) {
#pragma unroll
        for (int tm = 0; tm < 2; ++tm) {
            int rlo = mq + tm * 16 + (lane >> 2);
            RSp[kw * 128 + rlo]     = rsum[tm][0];
            RSp[kw * 128 + rlo + 8] = rsum[tm][1];
        }
    }
    __syncthreads();

    // ---- normalize + store
#pragma unroll
    for (int tm = 0; tm < 2; ++tm) {
        int rlo = mq + tm * 16 + (lane >> 2);
        int rhi = rlo + 8;
        float invlo = 1.f / (RSp[rlo] + RSp[128 + rlo]);
        float invhi = 1.f / (RSp[rhi] + RSp[128 + rhi]);
        size_t glo = (qrow0 + rlo) * 512 + h * 64;
        size_t ghi = (qrow0 + rhi) * 512 + h * 64;
#pragma unroll
        for (int tn = 0; tn < 4; ++tn) {
            int d = kw * 32 + tn * 8 + (lane & 3) * 2;
            float o0 = accO[tm][tn][0] * invlo, o1 = accO[tm][tn][1] * invlo;
            float o2 = accO[tm][tn][2] * invhi, o3 = accO[tm][tn][3] * invhi;
            *(uint32_t*)&g_ATh[glo + d] = pack_pair_hi(o0, o1);
            *(uint32_t*)&g_ATl[glo + d] = pack_pair_lo(o0, o1);
            *(uint32_t*)&g_ATh[ghi + d] = pack_pair_hi(o2, o3);
            *(uint32_t*)&g_ATl[ghi + d] = pack_pair_lo(o2, o3);
        }
    }
}

// ---------------------------------------------------------------- launch
extern "C" void kernel_launch(void* const* d_in, const int* in_sizes, int n_in,
                              void* d_out, int out_size)
{
    const float* x    = (const float*)d_in[0];
    const float* mask = (const float*)d_in[1];
    const float* WQ   = (const float*)d_in[2];
    const float* WK   = (const float*)d_in[3];
    const float* WV   = (const float*)d_in[4];
    const float* BE   = (const float*)d_in[5];
    const float* WO   = (const float*)d_in[6];
    float* out        = (float*)d_out;

    cudaFuncSetAttribute(attn_mma_kernel,
                         cudaFuncAttributeMaxDynamicSharedMemorySize, ATTN_SMEM);
    cudaFuncSetAttribute(gemm_bf16x3_kernel<0>,
                         cudaFuncAttributeMaxDynamicSharedMemorySize, GEMM_SMEM);
    cudaFuncSetAttribute(gemm_bf16x3_kernel<1>,
                         cudaFuncAttributeMaxDynamicSharedMemorySize, GEMM_SMEM);

    prep_a_kernel<<<(Mm * Ee / 4) / 256, 256>>>(x, BE);
    prep_w_kernel<<<(2048 * 512) / 256, 256>>>(WQ, WK, WV, WO);

    dim3 gq(Mm / 128, 512 / 128, 3);
    gemm_bf16x3_kernel<0><<<gq, 256, GEMM_SMEM>>>(nullptr);

    dim3 ga(Ss / 128, Hh, Bb);
    attn_mma_kernel<<<ga, 256, ATTN_SMEM>>>(mask);

    dim3 go(Mm / 128, 512 / 128, 1);
    gemm_bf16x3_kernel<1><<<go, 256, GEMM_SMEM>>>(out);
}

// round 6
// speedup vs baseline: 3.4050x; 1.0313x over previous
#include <cuda_runtime.h>
#include <cuda_bf16.h>
#include <stdint.h>
#include <math.h>

// ---------------------------------------------------------------- dims
static constexpr int Bb = 64;
static constexpr int Ss = 512;
static constexpr int Ee = 512;
static constexpr int Hh = 8;
static constexpr int Dd = 64;
static constexpr int Mm = Bb * Ss;     // 32768
static constexpr int HD = Hh * Dd;     // 512

// ---------------------------------------------------------------- scratch
__device__ __nv_bfloat16 g_Ah[Mm * Ee];
__device__ __nv_bfloat16 g_Al[Mm * Ee];
__device__ __nv_bfloat16 g_ATh[Mm * HD];
__device__ __nv_bfloat16 g_ATl[Mm * HD];
__device__ __nv_bfloat16 g_Bh[2048 * 512];
__device__ __nv_bfloat16 g_Bl[2048 * 512];
__device__ __nv_bfloat16 g_Qh[Mm * HD];
__device__ __nv_bfloat16 g_Ql[Mm * HD];
__device__ __nv_bfloat16 g_Kh[Mm * HD];
__device__ __nv_bfloat16 g_Kl[Mm * HD];
__device__ __nv_bfloat16 g_Vh[Mm * HD];
__device__ __nv_bfloat16 g_Vl[Mm * HD];

// ---------------------------------------------------------------- helpers
__device__ __forceinline__ void split_bf16(float v, __nv_bfloat16& h, __nv_bfloat16& l) {
    h = __float2bfloat16(v);
    l = __float2bfloat16(v - __bfloat162float(h));
}
__device__ __forceinline__ uint32_t pack_pair_hi(float a, float b) {
    __nv_bfloat162 p;
    p.x = __float2bfloat16(a);
    p.y = __float2bfloat16(b);
    return *(uint32_t*)&p;
}
__device__ __forceinline__ uint32_t pack_pair_lo(float a, float b) {
    __nv_bfloat162 p;
    p.x = __float2bfloat16(a - __bfloat162float(__float2bfloat16(a)));
    p.y = __float2bfloat16(b - __bfloat162float(__float2bfloat16(b)));
    return *(uint32_t*)&p;
}
__device__ __forceinline__ uint32_t smem_u32(const void* p) {
    uint32_t a;
    asm("{ .reg .u64 t; cvta.to.shared.u64 t, %1; cvt.u32.u64 %0, t; }" : "=r"(a) : "l"(p));
    return a;
}
__device__ __forceinline__ void ldsm4(uint32_t r[4], uint32_t addr) {
    asm volatile("ldmatrix.sync.aligned.m8n8.x4.shared.b16 {%0,%1,%2,%3}, [%4];"
                 : "=r"(r[0]), "=r"(r[1]), "=r"(r[2]), "=r"(r[3]) : "r"(addr));
}
__device__ __forceinline__ void ldsm4t(uint32_t r[4], uint32_t addr) {
    asm volatile("ldmatrix.sync.aligned.m8n8.x4.trans.shared.b16 {%0,%1,%2,%3}, [%4];"
                 : "=r"(r[0]), "=r"(r[1]), "=r"(r[2]), "=r"(r[3]) : "r"(addr));
}
__device__ __forceinline__ void mma16816(float d[4], const uint32_t a[4],
                                         uint32_t b0, uint32_t b1) {
    asm volatile("mma.sync.aligned.m16n8k16.row.col.f32.bf16.bf16.f32 "
                 "{%0,%1,%2,%3}, {%4,%5,%6,%7}, {%8,%9}, {%0,%1,%2,%3};"
                 : "+f"(d[0]), "+f"(d[1]), "+f"(d[2]), "+f"(d[3])
                 : "r"(a[0]), "r"(a[1]), "r"(a[2]), "r"(a[3]), "r"(b0), "r"(b1));
}
__device__ __forceinline__ void cpasync16(uint32_t saddr, const void* g) {
    asm volatile("cp.async.cg.shared.global [%0], [%1], 16;" :: "r"(saddr), "l"(g));
}
__device__ __forceinline__ void cpcommit() {
    asm volatile("cp.async.commit_group;" ::: "memory");
}
template <int N>
__device__ __forceinline__ void cpwait() {
    asm volatile("cp.async.wait_group %0;" :: "n"(N) : "memory");
}

// ---------------------------------------------------------------- prep kernels
__global__ __launch_bounds__(256) void prep_a_kernel(const float* __restrict__ x,
                                                     const float* __restrict__ be) {
    uint32_t i4 = blockIdx.x * 256 + threadIdx.x;
    int m = i4 >> 7;
    int k = (i4 & 127) << 2;
    const float4 xv = *(const float4*)&x[(size_t)m * Ee + k];
    const float4 bv = *(const float4*)&be[(size_t)(m & (Ss - 1)) * Ee + k];
    float v[4] = {xv.x + bv.x, xv.y + bv.y, xv.z + bv.z, xv.w + bv.w};
    size_t o = (size_t)m * Ee + k;
    *(uint32_t*)&g_Ah[o]     = pack_pair_hi(v[0], v[1]);
    *(uint32_t*)&g_Ah[o + 2] = pack_pair_hi(v[2], v[3]);
    *(uint32_t*)&g_Al[o]     = pack_pair_lo(v[0], v[1]);
    *(uint32_t*)&g_Al[o + 2] = pack_pair_lo(v[2], v[3]);
}

__global__ __launch_bounds__(256) void prep_w_kernel(const float* __restrict__ WQ,
                                                     const float* __restrict__ WK,
                                                     const float* __restrict__ WV,
                                                     const float* __restrict__ WO) {
    uint32_t idx = blockIdx.x * 256 + threadIdx.x;
    int r = idx >> 9;
    int k = idx & 511;
    float v;
    if (r < 1536) {
        int z = r >> 9;
        int n = r & 511;
        const float* W = (z == 0) ? WQ : (z == 1) ? WK : WV;
        v = W[(size_t)(n >> 6) * (Ee * Dd) + (size_t)k * Dd + (n & 63)];
    } else {
        int n = r - 1536;
        v = WO[(size_t)k * Ee + n];
    }
    __nv_bfloat16 h, l;
    split_bf16(v, h, l);
    g_Bh[idx] = h;
    g_Bl[idx] = l;
}

// ---------------------------------------------------------------- HMMA GEMM (cp.async 3-stage)
static constexpr int SA_H = 0;
static constexpr int SA_L = 8192;
static constexpr int SB_H = 16384;
static constexpr int SB_L = 24576;
static constexpr int GSTAGE = 32768;
static constexpr int GEMM_SMEM = 3 * GSTAGE;   // 96 KB

template <int WHICH>
__global__ __launch_bounds__(256, 2) void gemm_bf16x3_kernel(float* __restrict__ Cout)
{
    extern __shared__ __align__(16) char sm[];
    const uint32_t sb = smem_u32(sm);
    const int tid  = threadIdx.x;
    const int wid  = tid >> 5;
    const int lane = tid & 31;

    const int m0 = blockIdx.x * 128;
    const int n0 = blockIdx.y * 128;
    const int z  = (WHICH == 0) ? blockIdx.z : 0;

    const __nv_bfloat16* Ah = (WHICH == 0) ? g_Ah : g_ATh;
    const __nv_bfloat16* Al = (WHICH == 0) ? g_Al : g_ATl;
    const size_t boff = (WHICH == 0) ? (size_t)z * 512 * 512 : (size_t)1536 * 512;
    const __nv_bfloat16* Bh = g_Bh + boff;
    const __nv_bfloat16* Bl = g_Bl + boff;

    const int m_warp = (wid & 3) * 32;
    const int n_warp = (wid >> 2) * 64;

    const int rA   = m_warp + (lane & 7) + ((lane >> 3) & 1) * 8;
    const int kbA  = lane >> 4;
    const int sxA  = (rA >> 1) & 3;
    const int rB   = n_warp + (lane & 7) + (lane >> 4) * 8;
    const int kbB  = (lane >> 3) & 1;
    const int sxB  = (rB >> 1) & 3;

    float acc[2][8][4];
#pragma unroll
    for (int i = 0; i < 2; i++)
#pragma unroll
        for (int j = 0; j < 8; j++)
#pragma unroll
            for (int u = 0; u < 4; u++) acc[i][j][u] = 0.f;

    const int grow0 = (tid + 0)   >> 2, gc80 = (tid + 0)   & 3;
    const int grow1 = (tid + 256) >> 2, gc81 = (tid + 256) & 3;
    const uint32_t so0 = grow0 * 64 + ((gc80 ^ ((grow0 >> 1) & 3)) * 16);
    const uint32_t so1 = grow1 * 64 + ((gc81 ^ ((grow1 >> 1) & 3)) * 16);
    const __nv_bfloat16* pAh0 = Ah + (size_t)(m0 + grow0) * 512 + gc80 * 8;
    const __nv_bfloat16* pAh1 = Ah + (size_t)(m0 + grow1) * 512 + gc81 * 8;
    const __nv_bfloat16* pAl0 = Al + (size_t)(m0 + grow0) * 512 + gc80 * 8;
    const __nv_bfloat16* pAl1 = Al + (size_t)(m0 + grow1) * 512 + gc81 * 8;
    const __nv_bfloat16* pBh0 = Bh + (size_t)(n0 + grow0) * 512 + gc80 * 8;
    const __nv_bfloat16* pBh1 = Bh + (size_t)(n0 + grow1) * 512 + gc81 * 8;
    const __nv_bfloat16* pBl0 = Bl + (size_t)(n0 + grow0) * 512 + gc80 * 8;
    const __nv_bfloat16* pBl1 = Bl + (size_t)(n0 + grow1) * 512 + gc81 * 8;

#define LOAD_CHUNK(k0, stage) do {                                        \
        uint32_t s_ = sb + (stage) * GSTAGE;                              \
        cpasync16(s_ + SA_H + so0, pAh0 + (k0));                          \
        cpasync16(s_ + SA_H + so1, pAh1 + (k0));                          \
        cpasync16(s_ + SA_L + so0, pAl0 + (k0));                          \
        cpasync16(s_ + SA_L + so1, pAl1 + (k0));                          \
        cpasync16(s_ + SB_H + so0, pBh0 + (k0));                          \
        cpasync16(s_ + SB_H + so1, pBh1 + (k0));                          \
        cpasync16(s_ + SB_L + so0, pBl0 + (k0));                          \
        cpasync16(s_ + SB_L + so1, pBl1 + (k0));                          \
        cpcommit();                                                       \
    } while (0)

    LOAD_CHUNK(0, 0);
    LOAD_CHUNK(32, 1);

    for (int c = 0; c < 16; ++c) {
        if (c < 15) cpwait<1>(); else cpwait<0>();
        __syncthreads();
        if (c + 2 < 16) LOAD_CHUNK((c + 2) * 32, (c + 2) % 3);

        const uint32_t sbs = sb + (c % 3) * GSTAGE;
#pragma unroll
        for (int kk = 0; kk < 2; ++kk) {
            uint32_t ah[2][4], al[2][4];
#pragma unroll
            for (int tm = 0; tm < 2; ++tm) {
                uint32_t ro = (uint32_t)(rA + tm * 16) * 64 +
                              (uint32_t)(((kk * 2 + kbA) ^ sxA) * 16);
                ldsm4(ah[tm], sbs + SA_H + ro);
                ldsm4(al[tm], sbs + SA_L + ro);
            }
#pragma unroll
            for (int tp = 0; tp < 4; ++tp) {
                uint32_t bh[4], bl[4];
                uint32_t ro = (uint32_t)(rB + tp * 16) * 64 +
                              (uint32_t)(((kk * 2 + kbB) ^ sxB) * 16);
                ldsm4(bh, sbs + SB_H + ro);
                ldsm4(bl, sbs + SB_L + ro);
#pragma unroll
                for (int tm = 0; tm < 2; ++tm) {
                    mma16816(acc[tm][2 * tp],     ah[tm], bh[0], bh[1]);
                    mma16816(acc[tm][2 * tp],     ah[tm], bl[0], bl[1]);
                    mma16816(acc[tm][2 * tp],     al[tm], bh[0], bh[1]);
                    mma16816(acc[tm][2 * tp + 1], ah[tm], bh[2], bh[3]);
                    mma16816(acc[tm][2 * tp + 1], ah[tm], bl[2], bl[3]);
                    mma16816(acc[tm][2 * tp + 1], al[tm], bh[2], bh[3]);
                }
            }
        }
    }
#undef LOAD_CHUNK

    // epilogue
    if (WHICH == 0) {
        __nv_bfloat16* Ch = (z == 0) ? g_Qh : (z == 1) ? g_Kh : g_Vh;
        __nv_bfloat16* Cl = (z == 0) ? g_Ql : (z == 1) ? g_Kl : g_Vl;
#pragma unroll
        for (int tm = 0; tm < 2; ++tm) {
            const int m = m0 + m_warp + tm * 16 + (lane >> 2);
#pragma unroll
            for (int tn = 0; tn < 8; ++tn) {
                const int n = n0 + n_warp + tn * 8 + (lane & 3) * 2;
                size_t o0 = (size_t)m * 512 + n;
                size_t o1 = (size_t)(m + 8) * 512 + n;
                *(uint32_t*)&Ch[o0] = pack_pair_hi(acc[tm][tn][0], acc[tm][tn][1]);
                *(uint32_t*)&Cl[o0] = pack_pair_lo(acc[tm][tn][0], acc[tm][tn][1]);
                *(uint32_t*)&Ch[o1] = pack_pair_hi(acc[tm][tn][2], acc[tm][tn][3]);
                *(uint32_t*)&Cl[o1] = pack_pair_lo(acc[tm][tn][2], acc[tm][tn][3]);
            }
        }
    } else {
#pragma unroll
        for (int tm = 0; tm < 2; ++tm) {
            const int m = m0 + m_warp + tm * 16 + (lane >> 2);
#pragma unroll
            for (int tn = 0; tn < 8; ++tn) {
                const int n = n0 + n_warp + tn * 8 + (lane & 3) * 2;
                *(float2*)&Cout[(size_t)m * 512 + n] =
                    make_float2(acc[tm][tn][0], acc[tm][tn][1]);
                *(float2*)&Cout[(size_t)(m + 8) * 512 + n] =
                    make_float2(acc[tm][tn][2], acc[tm][tn][3]);
            }
        }
    }
}

// ---------------------------------------------------------------- tensor-core attention
// K single-buffered, V double-buffered; K(t+1)/V(t+1) prefetched at mid-tile sync.
static constexpr int A_QH = 0;
static constexpr int A_QL = 16384;
static constexpr int A_KH = 32768;
static constexpr int A_KL = 40960;
static constexpr int A_V0 = 49152;     // stage stride 16384; VH at base, VL at base+8192
static constexpr int A_PH = 81920;
static constexpr int A_PL = 98304;
static constexpr int A_RS = 81920;     // aliases PH (used only after a sync at the end)
static constexpr int ATTN_SMEM = 114688;

__global__ __launch_bounds__(256, 2) void attn_mma_kernel(const float* __restrict__ mask)
{
    extern __shared__ char sm[];
    const uint32_t sb = smem_u32(sm);
    const int tid  = threadIdx.x;
    const int wid  = tid >> 5;
    const int lane = tid & 31;

    const int qt = blockIdx.x;
    const int h  = blockIdx.y;
    const int b  = blockIdx.z;
    const int mq = (wid & 3) * 32;
    const int kw = wid >> 2;
    const size_t qrow0 = (size_t)b * 512 + qt * 128;

    // prologue: Q + K(0) + V(0) async loads, one group
#pragma unroll
    for (int i = 0; i < 4; i++) {
        int idx = tid + i * 256;
        int row = idx >> 3, c = idx & 7;
        uint32_t so = row * 128 + ((c ^ (row & 7)) * 16);
        size_t g = (qrow0 + row) * 512 + h * 64 + c * 8;
        cpasync16(sb + A_QH + so, &g_Qh[g]);
        cpasync16(sb + A_QL + so, &g_Ql[g]);
    }
#pragma unroll
    for (int i = 0; i < 2; i++) {
        int idx = tid + i * 256;
        int row = idx >> 3, c = idx & 7;
        uint32_t so = row * 128 + ((c ^ (row & 7)) * 16);
        size_t g = ((size_t)b * 512 + row) * 512 + h * 64 + c * 8;
        cpasync16(sb + A_KH + so, &g_Kh[g]);
        cpasync16(sb + A_KL + so, &g_Kl[g]);
        cpasync16(sb + A_V0 + so, &g_Vh[g]);
        cpasync16(sb + A_V0 + 8192 + so, &g_Vl[g]);
    }
    cpcommit();

    float accO[2][4][4];
#pragma unroll
    for (int i = 0; i < 2; i++)
#pragma unroll
        for (int j = 0; j < 4; j++)
#pragma unroll
            for (int u = 0; u < 4; u++) accO[i][j][u] = 0.f;
    float rsum[2][2] = {{0.f, 0.f}, {0.f, 0.f}};

    const float scale = 0.044194173824159216f;

    const int rowA = mq + (lane & 7) + ((lane >> 3) & 1) * 8;
    const int cA   = lane >> 4;
    const int rowB = kw * 32 + (lane & 7) + (lane >> 4) * 8;
    const int cB   = (lane >> 3) & 1;
    const int rowV = (lane & 7) + ((lane >> 3) & 1) * 8;
    const int cV   = lane >> 4;

    for (int tile = 0; tile < 8; ++tile) {
        const int t0 = tile * 64;
        cpwait<0>();
        __syncthreads();

        // ---- S = Q K^T
        float accS[2][4][4];
#pragma unroll
        for (int i = 0; i < 2; i++)
#pragma unroll
            for (int j = 0; j < 4; j++)
#pragma unroll
                for (int u = 0; u < 4; u++) accS[i][j][u] = 0.f;

#pragma unroll
        for (int ks = 0; ks < 4; ++ks) {
            uint32_t qh[2][4], ql[2][4];
#pragma unroll
            for (int tm = 0; tm < 2; ++tm) {
                int row = rowA + tm * 16;
                int c = ks * 2 + cA;
                uint32_t so = row * 128 + ((c ^ (row & 7)) * 16);
                ldsm4(qh[tm], sb + A_QH + so);
                ldsm4(ql[tm], sb + A_QL + so);
            }
#pragma unroll
            for (int tb = 0; tb < 2; ++tb) {
                uint32_t kh[4], kl[4];
                int row = rowB + tb * 16;
                int c = ks * 2 + cB;
                uint32_t so = row * 128 + ((c ^ (row & 7)) * 16);
                ldsm4(kh, sb + A_KH + so);
                ldsm4(kl, sb + A_KL + so);
#pragma unroll
                for (int tm = 0; tm < 2; ++tm) {
                    mma16816(accS[tm][tb * 2],     qh[tm], kh[0], kh[1]);
                    mma16816(accS[tm][tb * 2],     qh[tm], kl[0], kl[1]);
                    mma16816(accS[tm][tb * 2],     ql[tm], kh[0], kh[1]);
                    mma16816(accS[tm][tb * 2 + 1], qh[tm], kh[2], kh[3]);
                    mma16816(accS[tm][tb * 2 + 1], qh[tm], kl[2], kl[3]);
                    mma16816(accS[tm][tb * 2 + 1], ql[tm], kh[2], kh[3]);
                }
            }
        }

        // ---- exp + rowsum + pack P (bias from mask inline; L1-resident)
#pragma unroll
        for (int tn = 0; tn < 4; ++tn) {
            int tloc = kw * 32 + tn * 8 + (lane & 3) * 2;
            const float2 mv = *(const float2*)&mask[(size_t)b * 512 + t0 + tloc];
            float b0 = -1e10f * mv.x;
            float b1 = -1e10f * mv.y;
#pragma unroll
            for (int tm = 0; tm < 2; ++tm) {
                float p0 = __expf(fmaf(accS[tm][tn][0], scale, b0));
                float p1 = __expf(fmaf(accS[tm][tn][1], scale, b1));
                float p2 = __expf(fmaf(accS[tm][tn][2], scale, b0));
                float p3 = __expf(fmaf(accS[tm][tn][3], scale, b1));
                rsum[tm][0] += p0 + p1;
                rsum[tm][1] += p2 + p3;
                int c = kw * 4 + tn;
                int rlo = mq + tm * 16 + (lane >> 2);
                int rhi = rlo + 8;
                uint32_t slo = rlo * 128 + ((c ^ (rlo & 7)) * 16) + (lane & 3) * 4;
                uint32_t shi = rhi * 128 + ((c ^ (rhi & 7)) * 16) + (lane & 3) * 4;
                *(uint32_t*)(sm + A_PH + slo) = pack_pair_hi(p0, p1);
                *(uint32_t*)(sm + A_PL + slo) = pack_pair_lo(p0, p1);
                *(uint32_t*)(sm + A_PH + shi) = pack_pair_hi(p2, p3);
                *(uint32_t*)(sm + A_PL + shi) = pack_pair_lo(p2, p3);
            }
        }
        __syncthreads();   // P visible; K reads complete -> safe to overwrite K

        // ---- prefetch K(t+1)/V(t+1), overlapping the PV phase
        if (tile < 7) {
            const int t1 = (tile + 1) * 64;
            const uint32_t vb = sb + A_V0 + ((tile + 1) & 1) * 16384;
#pragma unroll
            for (int i = 0; i < 2; i++) {
                int idx = tid + i * 256;
                int row = idx >> 3, c = idx & 7;
                uint32_t so = row * 128 + ((c ^ (row & 7)) * 16);
                size_t g = ((size_t)b * 512 + t1 + row) * 512 + h * 64 + c * 8;
                cpasync16(sb + A_KH + so, &g_Kh[g]);
                cpasync16(sb + A_KL + so, &g_Kl[g]);
                cpasync16(vb + so, &g_Vh[g]);
                cpasync16(vb + 8192 + so, &g_Vl[g]);
            }
            cpcommit();
        }

        // ---- O += P V (V from current stage)
        const uint32_t vcur = sb + A_V0 + (tile & 1) * 16384;
#pragma unroll
        for (int ks = 0; ks < 4; ++ks) {
            uint32_t ph[2][4], pl[2][4];
#pragma unroll
            for (int tm = 0; tm < 2; ++tm) {
                int row = rowA + tm * 16;
                int c = ks * 2 + cA;
                uint32_t so = row * 128 + ((c ^ (row & 7)) * 16);
                ldsm4(ph[tm], sb + A_PH + so);
                ldsm4(pl[tm], sb + A_PL + so);
            }
#pragma unroll
            for (int d16 = 0; d16 < 2; ++d16) {
                uint32_t vh[4], vl[4];
                int row = ks * 16 + rowV;
                int c = kw * 4 + d16 * 2 + cV;
                uint32_t so = row * 128 + ((c ^ (row & 7)) * 16);
                ldsm4t(vh, vcur + so);
                ldsm4t(vl, vcur + 8192 + so);
#pragma unroll
                for (int tm = 0; tm < 2; ++tm) {
                    mma16816(accO[tm][d16 * 2],     ph[tm], vh[0], vh[1]);
                    mma16816(accO[tm][d16 * 2],     ph[tm], vl[0], vl[1]);
                    mma16816(accO[tm][d16 * 2],     pl[tm], vh[0], vh[1]);
                    mma16816(accO[tm][d16 * 2 + 1], ph[tm], vh[2], vh[3]);
                    mma16816(accO[tm][d16 * 2 + 1], ph[tm], vl[2], vl[3]);
                    mma16816(accO[tm][d16 * 2 + 1], pl[tm], vh[2], vh[3]);
                }
            }
        }
    }

    // ---- rowsum reduce (RS aliases P: sync before reuse)
    __syncthreads();
    float* RSp = (float*)(sm + A_RS);
#pragma unroll
    for (int tm = 0; tm < 2; ++tm)
#pragma unroll
        for (int u = 0; u < 2; ++u) {
            float v = rsum[tm][u];
            v += __shfl_xor_sync(0xffffffffu, v, 1);
            v += __shfl_xor_sync(0xffffffffu, v, 2);
            rsum[tm][u] = v;
        }
    if ((lane & 3) == 0) {
#pragma unroll
        for (int tm = 0; tm < 2; ++tm) {
            int rlo = mq + tm * 16 + (lane >> 2);
            RSp[kw * 128 + rlo]     = rsum[tm][0];
            RSp[kw * 128 + rlo + 8] = rsum[tm][1];
        }
    }
    __syncthreads();

    // ---- normalize + store
#pragma unroll
    for (int tm = 0; tm < 2; ++tm) {
        int rlo = mq + tm * 16 + (lane >> 2);
        int rhi = rlo + 8;
        float invlo = 1.f / (RSp[rlo] + RSp[128 + rlo]);
        float invhi = 1.f / (RSp[rhi] + RSp[128 + rhi]);
        size_t glo = (qrow0 + rlo) * 512 + h * 64;
        size_t ghi = (qrow0 + rhi) * 512 + h * 64;
#pragma unroll
        for (int tn = 0; tn < 4; ++tn) {
            int d = kw * 32 + tn * 8 + (lane & 3) * 2;
            float o0 = accO[tm][tn][0] * invlo, o1 = accO[tm][tn][1] * invlo;
            float o2 = accO[tm][tn][2] * invhi, o3 = accO[tm][tn][3] * invhi;
            *(uint32_t*)&g_ATh[glo + d] = pack_pair_hi(o0, o1);
            *(uint32_t*)&g_ATl[glo + d] = pack_pair_lo(o0, o1);
            *(uint32_t*)&g_ATh[ghi + d] = pack_pair_hi(o2, o3);
            *(uint32_t*)&g_ATl[ghi + d] = pack_pair_lo(o2, o3);
        }
    }
}

// ---------------------------------------------------------------- launch
extern "C" void kernel_launch(void* const* d_in, const int* in_sizes, int n_in,
                              void* d_out, int out_size)
{
    const float* x    = (const float*)d_in[0];
    const float* mask = (const float*)d_in[1];
    const float* WQ   = (const float*)d_in[2];
    const float* WK   = (const float*)d_in[3];
    const float* WV   = (const float*)d_in[4];
    const float* BE   = (const float*)d_in[5];
    const float* WO   = (const float*)d_in[6];
    float* out        = (float*)d_out;

    cudaFuncSetAttribute(attn_mma_kernel,
                         cudaFuncAttributeMaxDynamicSharedMemorySize, ATTN_SMEM);
    cudaFuncSetAttribute(gemm_bf16x3_kernel<0>,
                         cudaFuncAttributeMaxDynamicSharedMemorySize, GEMM_SMEM);
    cudaFuncSetAttribute(gemm_bf16x3_kernel<1>,
                         cudaFuncAttributeMaxDynamicSharedMemorySize, GEMM_SMEM);

    prep_a_kernel<<<(Mm * Ee / 4) / 256, 256>>>(x, BE);
    prep_w_kernel<<<(2048 * 512) / 256, 256>>>(WQ, WK, WV, WO);

    dim3 gq(Mm / 128, 512 / 128, 3);
    gemm_bf16x3_kernel<0><<<gq, 256, GEMM_SMEM>>>(nullptr);

    dim3 ga(Ss / 128, Hh, Bb);
    attn_mma_kernel<<<ga, 256, ATTN_SMEM>>>(mask);

    dim3 go(Mm / 128, 512 / 128, 1);
    gemm_bf16x3_kernel<1><<<go, 256, GEMM_SMEM>>>(out);
}

// round 7
// speedup vs baseline: 3.4391x; 1.0100x over previous
#include <cuda_runtime.h>
#include <cuda_bf16.h>
#include <stdint.h>
#include <math.h>

// ---------------------------------------------------------------- dims
static constexpr int Bb = 64;
static constexpr int Ss = 512;
static constexpr int Ee = 512;
static constexpr int Hh = 8;
static constexpr int Dd = 64;
static constexpr int Mm = Bb * Ss;     // 32768
static constexpr int HD = Hh * Dd;     // 512

// ---------------------------------------------------------------- scratch
__device__ __nv_bfloat16 g_Ah[Mm * Ee];
__device__ __nv_bfloat16 g_Al[Mm * Ee];
__device__ __nv_bfloat16 g_ATh[Mm * HD];
__device__ __nv_bfloat16 g_ATl[Mm * HD];
__device__ __nv_bfloat16 g_Bh[2048 * 512];
__device__ __nv_bfloat16 g_Bl[2048 * 512];
__device__ __nv_bfloat16 g_Qh[Mm * HD];
__device__ __nv_bfloat16 g_Ql[Mm * HD];
__device__ __nv_bfloat16 g_Kh[Mm * HD];
__device__ __nv_bfloat16 g_Kl[Mm * HD];
__device__ __nv_bfloat16 g_Vh[Mm * HD];
__device__ __nv_bfloat16 g_Vl[Mm * HD];

// ---------------------------------------------------------------- helpers
__device__ __forceinline__ void split_bf16(float v, __nv_bfloat16& h, __nv_bfloat16& l) {
    h = __float2bfloat16(v);
    l = __float2bfloat16(v - __bfloat162float(h));
}
__device__ __forceinline__ uint32_t pack_pair_hi(float a, float b) {
    __nv_bfloat162 p;
    p.x = __float2bfloat16(a);
    p.y = __float2bfloat16(b);
    return *(uint32_t*)&p;
}
__device__ __forceinline__ uint32_t pack_pair_lo(float a, float b) {
    __nv_bfloat162 p;
    p.x = __float2bfloat16(a - __bfloat162float(__float2bfloat16(a)));
    p.y = __float2bfloat16(b - __bfloat162float(__float2bfloat16(b)));
    return *(uint32_t*)&p;
}
__device__ __forceinline__ uint32_t smem_u32(const void* p) {
    uint32_t a;
    asm("{ .reg .u64 t; cvta.to.shared.u64 t, %1; cvt.u32.u64 %0, t; }" : "=r"(a) : "l"(p));
    return a;
}
__device__ __forceinline__ void ldsm4(uint32_t r[4], uint32_t addr) {
    asm volatile("ldmatrix.sync.aligned.m8n8.x4.shared.b16 {%0,%1,%2,%3}, [%4];"
                 : "=r"(r[0]), "=r"(r[1]), "=r"(r[2]), "=r"(r[3]) : "r"(addr));
}
__device__ __forceinline__ void ldsm4t(uint32_t r[4], uint32_t addr) {
    asm volatile("ldmatrix.sync.aligned.m8n8.x4.trans.shared.b16 {%0,%1,%2,%3}, [%4];"
                 : "=r"(r[0]), "=r"(r[1]), "=r"(r[2]), "=r"(r[3]) : "r"(addr));
}
__device__ __forceinline__ void mma16816(float d[4], const uint32_t a[4],
                                         uint32_t b0, uint32_t b1) {
    asm volatile("mma.sync.aligned.m16n8k16.row.col.f32.bf16.bf16.f32 "
                 "{%0,%1,%2,%3}, {%4,%5,%6,%7}, {%8,%9}, {%0,%1,%2,%3};"
                 : "+f"(d[0]), "+f"(d[1]), "+f"(d[2]), "+f"(d[3])
                 : "r"(a[0]), "r"(a[1]), "r"(a[2]), "r"(a[3]), "r"(b0), "r"(b1));
}
__device__ __forceinline__ void cpasync16(uint32_t saddr, const void* g) {
    asm volatile("cp.async.cg.shared.global [%0], [%1], 16;" :: "r"(saddr), "l"(g));
}
__device__ __forceinline__ void cpcommit() {
    asm volatile("cp.async.commit_group;" ::: "memory");
}
template <int N>
__device__ __forceinline__ void cpwait() {
    asm volatile("cp.async.wait_group %0;" :: "n"(N) : "memory");
}

// ---------------------------------------------------------------- prep kernels
__global__ __launch_bounds__(256) void prep_a_kernel(const float* __restrict__ x,
                                                     const float* __restrict__ be) {
    uint32_t i4 = blockIdx.x * 256 + threadIdx.x;
    int m = i4 >> 7;
    int k = (i4 & 127) << 2;
    const float4 xv = *(const float4*)&x[(size_t)m * Ee + k];
    const float4 bv = *(const float4*)&be[(size_t)(m & (Ss - 1)) * Ee + k];
    float v[4] = {xv.x + bv.x, xv.y + bv.y, xv.z + bv.z, xv.w + bv.w};
    size_t o = (size_t)m * Ee + k;
    *(uint32_t*)&g_Ah[o]     = pack_pair_hi(v[0], v[1]);
    *(uint32_t*)&g_Ah[o + 2] = pack_pair_hi(v[2], v[3]);
    *(uint32_t*)&g_Al[o]     = pack_pair_lo(v[0], v[1]);
    *(uint32_t*)&g_Al[o + 2] = pack_pair_lo(v[2], v[3]);
}

__global__ __launch_bounds__(256) void prep_w_kernel(const float* __restrict__ WQ,
                                                     const float* __restrict__ WK,
                                                     const float* __restrict__ WV,
                                                     const float* __restrict__ WO) {
    uint32_t idx = blockIdx.x * 256 + threadIdx.x;
    int r = idx >> 9;
    int k = idx & 511;
    float v;
    if (r < 1536) {
        int z = r >> 9;
        int n = r & 511;
        const float* W = (z == 0) ? WQ : (z == 1) ? WK : WV;
        v = W[(size_t)(n >> 6) * (Ee * Dd) + (size_t)k * Dd + (n & 63)];
    } else {
        int n = r - 1536;
        v = WO[(size_t)k * Ee + n];
    }
    __nv_bfloat16 h, l;
    split_bf16(v, h, l);
    g_Bh[idx] = h;
    g_Bl[idx] = l;
}

// ---------------------------------------------------------------- HMMA GEMM (cp.async 3-stage)
static constexpr int SA_H = 0;
static constexpr int SA_L = 8192;
static constexpr int SB_H = 16384;
static constexpr int SB_L = 24576;
static constexpr int GSTAGE = 32768;
static constexpr int GEMM_SMEM = 3 * GSTAGE;   // 96 KB

template <int WHICH>
__global__ __launch_bounds__(256, 2) void gemm_bf16x3_kernel(float* __restrict__ Cout)
{
    extern __shared__ __align__(16) char sm[];
    const uint32_t sb = smem_u32(sm);
    const int tid  = threadIdx.x;
    const int wid  = tid >> 5;
    const int lane = tid & 31;

    const int m0 = blockIdx.x * 128;
    const int n0 = blockIdx.y * 128;
    const int z  = (WHICH == 0) ? blockIdx.z : 0;

    const __nv_bfloat16* Ah = (WHICH == 0) ? g_Ah : g_ATh;
    const __nv_bfloat16* Al = (WHICH == 0) ? g_Al : g_ATl;
    const size_t boff = (WHICH == 0) ? (size_t)z * 512 * 512 : (size_t)1536 * 512;
    const __nv_bfloat16* Bh = g_Bh + boff;
    const __nv_bfloat16* Bl = g_Bl + boff;

    const int m_warp = (wid & 3) * 32;
    const int n_warp = (wid >> 2) * 64;

    const int rA   = m_warp + (lane & 7) + ((lane >> 3) & 1) * 8;
    const int kbA  = lane >> 4;
    const int sxA  = (rA >> 1) & 3;
    const int rB   = n_warp + (lane & 7) + (lane >> 4) * 8;
    const int kbB  = (lane >> 3) & 1;
    const int sxB  = (rB >> 1) & 3;

    float acc[2][8][4];
#pragma unroll
    for (int i = 0; i < 2; i++)
#pragma unroll
        for (int j = 0; j < 8; j++)
#pragma unroll
            for (int u = 0; u < 4; u++) acc[i][j][u] = 0.f;

    const int grow0 = (tid + 0)   >> 2, gc80 = (tid + 0)   & 3;
    const int grow1 = (tid + 256) >> 2, gc81 = (tid + 256) & 3;
    const uint32_t so0 = grow0 * 64 + ((gc80 ^ ((grow0 >> 1) & 3)) * 16);
    const uint32_t so1 = grow1 * 64 + ((gc81 ^ ((grow1 >> 1) & 3)) * 16);
    const __nv_bfloat16* pAh0 = Ah + (size_t)(m0 + grow0) * 512 + gc80 * 8;
    const __nv_bfloat16* pAh1 = Ah + (size_t)(m0 + grow1) * 512 + gc81 * 8;
    const __nv_bfloat16* pAl0 = Al + (size_t)(m0 + grow0) * 512 + gc80 * 8;
    const __nv_bfloat16* pAl1 = Al + (size_t)(m0 + grow1) * 512 + gc81 * 8;
    const __nv_bfloat16* pBh0 = Bh + (size_t)(n0 + grow0) * 512 + gc80 * 8;
    const __nv_bfloat16* pBh1 = Bh + (size_t)(n0 + grow1) * 512 + gc81 * 8;
    const __nv_bfloat16* pBl0 = Bl + (size_t)(n0 + grow0) * 512 + gc80 * 8;
    const __nv_bfloat16* pBl1 = Bl + (size_t)(n0 + grow1) * 512 + gc81 * 8;

#define LOAD_CHUNK(k0, stage) do {                                        \
        uint32_t s_ = sb + (stage) * GSTAGE;                              \
        cpasync16(s_ + SA_H + so0, pAh0 + (k0));                          \
        cpasync16(s_ + SA_H + so1, pAh1 + (k0));                          \
        cpasync16(s_ + SA_L + so0, pAl0 + (k0));                          \
        cpasync16(s_ + SA_L + so1, pAl1 + (k0));                          \
        cpasync16(s_ + SB_H + so0, pBh0 + (k0));                          \
        cpasync16(s_ + SB_H + so1, pBh1 + (k0));                          \
        cpasync16(s_ + SB_L + so0, pBl0 + (k0));                          \
        cpasync16(s_ + SB_L + so1, pBl1 + (k0));                          \
        cpcommit();                                                       \
    } while (0)

    LOAD_CHUNK(0, 0);
    LOAD_CHUNK(32, 1);

    for (int c = 0; c < 16; ++c) {
        if (c < 15) cpwait<1>(); else cpwait<0>();
        __syncthreads();
        if (c + 2 < 16) LOAD_CHUNK((c + 2) * 32, (c + 2) % 3);

        const uint32_t sbs = sb + (c % 3) * GSTAGE;
#pragma unroll
        for (int kk = 0; kk < 2; ++kk) {
            uint32_t ah[2][4], al[2][4];
#pragma unroll
            for (int tm = 0; tm < 2; ++tm) {
                uint32_t ro = (uint32_t)(rA + tm * 16) * 64 +
                              (uint32_t)(((kk * 2 + kbA) ^ sxA) * 16);
                ldsm4(ah[tm], sbs + SA_H + ro);
                ldsm4(al[tm], sbs + SA_L + ro);
            }
#pragma unroll
            for (int tp = 0; tp < 4; ++tp) {
                uint32_t bh[4], bl[4];
                uint32_t ro = (uint32_t)(rB + tp * 16) * 64 +
                              (uint32_t)(((kk * 2 + kbB) ^ sxB) * 16);
                ldsm4(bh, sbs + SB_H + ro);
                ldsm4(bl, sbs + SB_L + ro);
#pragma unroll
                for (int tm = 0; tm < 2; ++tm) {
                    mma16816(acc[tm][2 * tp],     ah[tm], bh[0], bh[1]);
                    mma16816(acc[tm][2 * tp],     ah[tm], bl[0], bl[1]);
                    mma16816(acc[tm][2 * tp],     al[tm], bh[0], bh[1]);
                    mma16816(acc[tm][2 * tp + 1], ah[tm], bh[2], bh[3]);
                    mma16816(acc[tm][2 * tp + 1], ah[tm], bl[2], bl[3]);
                    mma16816(acc[tm][2 * tp + 1], al[tm], bh[2], bh[3]);
                }
            }
        }
    }
#undef LOAD_CHUNK

    // epilogue
    if (WHICH == 0) {
        __nv_bfloat16* Ch = (z == 0) ? g_Qh : (z == 1) ? g_Kh : g_Vh;
        __nv_bfloat16* Cl = (z == 0) ? g_Ql : (z == 1) ? g_Kl : g_Vl;
#pragma unroll
        for (int tm = 0; tm < 2; ++tm) {
            const int m = m0 + m_warp + tm * 16 + (lane >> 2);
#pragma unroll
            for (int tn = 0; tn < 8; ++tn) {
                const int n = n0 + n_warp + tn * 8 + (lane & 3) * 2;
                size_t o0 = (size_t)m * 512 + n;
                size_t o1 = (size_t)(m + 8) * 512 + n;
                *(uint32_t*)&Ch[o0] = pack_pair_hi(acc[tm][tn][0], acc[tm][tn][1]);
                *(uint32_t*)&Cl[o0] = pack_pair_lo(acc[tm][tn][0], acc[tm][tn][1]);
                *(uint32_t*)&Ch[o1] = pack_pair_hi(acc[tm][tn][2], acc[tm][tn][3]);
                *(uint32_t*)&Cl[o1] = pack_pair_lo(acc[tm][tn][2], acc[tm][tn][3]);
            }
        }
    } else {
#pragma unroll
        for (int tm = 0; tm < 2; ++tm) {
            const int m = m0 + m_warp + tm * 16 + (lane >> 2);
#pragma unroll
            for (int tn = 0; tn < 8; ++tn) {
                const int n = n0 + n_warp + tn * 8 + (lane & 3) * 2;
                *(float2*)&Cout[(size_t)m * 512 + n] =
                    make_float2(acc[tm][tn][0], acc[tm][tn][1]);
                *(float2*)&Cout[(size_t)(m + 8) * 512 + n] =
                    make_float2(acc[tm][tn][2], acc[tm][tn][3]);
            }
        }
    }
}

// ---------------------------------------------------------------- tensor-core attention
// FA2-style: warp = 16 q rows x all 64 keys; P stays in registers (S C-frag == PV A-frag).
// K,V double-buffered; ONE sync per key tile.
static constexpr int A_QH = 0;         // 16 KB
static constexpr int A_QL = 16384;     // 16 KB
static constexpr int A_K0 = 32768;     // 2 stages x 16 KB (KH at +0, KL at +8192)
static constexpr int A_V0 = 65536;     // 2 stages x 16 KB
static constexpr int A_BI = 98304;     // 512 floats
static constexpr int ATTN_SMEM = 100352;

__global__ __launch_bounds__(256, 2) void attn_mma_kernel(const float* __restrict__ mask)
{
    extern __shared__ char sm[];
    const uint32_t sb = smem_u32(sm);
    const int tid  = threadIdx.x;
    const int wid  = tid >> 5;
    const int lane = tid & 31;

    const int qt = blockIdx.x;
    const int h  = blockIdx.y;
    const int b  = blockIdx.z;
    const int mq = wid * 16;                    // warp q-offset (16 rows per warp)
    const size_t qrow0 = (size_t)b * 512 + qt * 128;

    // prologue: Q + K(0) + V(0)
#pragma unroll
    for (int i = 0; i < 4; i++) {
        int idx = tid + i * 256;
        int row = idx >> 3, c = idx & 7;
        uint32_t so = row * 128 + ((c ^ (row & 7)) * 16);
        size_t g = (qrow0 + row) * 512 + h * 64 + c * 8;
        cpasync16(sb + A_QH + so, &g_Qh[g]);
        cpasync16(sb + A_QL + so, &g_Ql[g]);
    }
#pragma unroll
    for (int i = 0; i < 2; i++) {
        int idx = tid + i * 256;
        int row = idx >> 3, c = idx & 7;
        uint32_t so = row * 128 + ((c ^ (row & 7)) * 16);
        size_t g = ((size_t)b * 512 + row) * 512 + h * 64 + c * 8;
        cpasync16(sb + A_K0 + so, &g_Kh[g]);
        cpasync16(sb + A_K0 + 8192 + so, &g_Kl[g]);
        cpasync16(sb + A_V0 + so, &g_Vh[g]);
        cpasync16(sb + A_V0 + 8192 + so, &g_Vl[g]);
    }
    cpcommit();
#pragma unroll
    for (int i = 0; i < 2; i++) {
        int t = tid + i * 256;
        ((float*)(sm + A_BI))[t] = -1e10f * mask[(size_t)b * 512 + t];
    }

    float accO[4][2][4];                        // [d16-group][n8][4]
#pragma unroll
    for (int i = 0; i < 4; i++)
#pragma unroll
        for (int j = 0; j < 2; j++)
#pragma unroll
            for (int u = 0; u < 4; u++) accO[i][j][u] = 0.f;
    float rs0 = 0.f, rs1 = 0.f;

    const float scale = 0.044194173824159216f;  // 1/sqrt(512)

    // frag lane geometry
    const int rowQ = mq + (lane & 7) + ((lane >> 3) & 1) * 8;
    const int cQ   = lane >> 4;
    const int rowK = (lane & 7) + (lane >> 4) * 8;        // + kg*16
    const int cK   = (lane >> 3) & 1;
    const int rowV = (lane & 7) + ((lane >> 3) & 1) * 8;  // + kc*16
    const int cV   = lane >> 4;

    for (int tile = 0; tile < 8; ++tile) {
        cpwait<0>();
        __syncthreads();

        // prefetch K/V(t+1) into alternate stage; overlaps this tile's compute
        if (tile < 7) {
            const int t1 = (tile + 1) * 64;
            const uint32_t kb1 = sb + A_K0 + ((tile + 1) & 1) * 16384;
            const uint32_t vb1 = sb + A_V0 + ((tile + 1) & 1) * 16384;
#pragma unroll
            for (int i = 0; i < 2; i++) {
                int idx = tid + i * 256;
                int row = idx >> 3, c = idx & 7;
                uint32_t so = row * 128 + ((c ^ (row & 7)) * 16);
                size_t g = ((size_t)b * 512 + t1 + row) * 512 + h * 64 + c * 8;
                cpasync16(kb1 + so, &g_Kh[g]);
                cpasync16(kb1 + 8192 + so, &g_Kl[g]);
                cpasync16(vb1 + so, &g_Vh[g]);
                cpasync16(vb1 + 8192 + so, &g_Vl[g]);
            }
            cpcommit();
        }

        const uint32_t kb = sb + A_K0 + (tile & 1) * 16384;
        const uint32_t vb = sb + A_V0 + (tile & 1) * 16384;

        // ---- S = Q K^T : 16q x 64k per warp
        float accS[4][2][4];
#pragma unroll
        for (int i = 0; i < 4; i++)
#pragma unroll
            for (int j = 0; j < 2; j++)
#pragma unroll
                for (int u = 0; u < 4; u++) accS[i][j][u] = 0.f;

#pragma unroll
        for (int ks = 0; ks < 4; ++ks) {
            uint32_t qh[4], ql[4];
            {
                uint32_t so = rowQ * 128 + (((ks * 2 + cQ) ^ (rowQ & 7)) * 16);
                ldsm4(qh, sb + A_QH + so);
                ldsm4(ql, sb + A_QL + so);
            }
#pragma unroll
            for (int kg = 0; kg < 4; ++kg) {
                uint32_t kh[4], kl[4];
                int row = kg * 16 + rowK;
                uint32_t so = row * 128 + (((ks * 2 + cK) ^ (row & 7)) * 16);
                ldsm4(kh, kb + so);
                ldsm4(kl, kb + 8192 + so);
                mma16816(accS[kg][0], qh, kh[0], kh[1]);
                mma16816(accS[kg][0], qh, kl[0], kl[1]);
                mma16816(accS[kg][0], ql, kh[0], kh[1]);
                mma16816(accS[kg][1], qh, kh[2], kh[3]);
                mma16816(accS[kg][1], qh, kl[2], kl[3]);
                mma16816(accS[kg][1], ql, kh[2], kh[3]);
            }
        }

        // ---- exp in registers (accS -> unnormalized P)
        const int t0 = tile * 64;
#pragma unroll
        for (int kg = 0; kg < 4; ++kg) {
#pragma unroll
            for (int t8 = 0; t8 < 2; ++t8) {
                int key = t0 + kg * 16 + t8 * 8 + (lane & 3) * 2;
                float b0 = ((const float*)(sm + A_BI))[key];
                float b1 = ((const float*)(sm + A_BI))[key + 1];
                float p0 = __expf(fmaf(accS[kg][t8][0], scale, b0));
                float p1 = __expf(fmaf(accS[kg][t8][1], scale, b1));
                float p2 = __expf(fmaf(accS[kg][t8][2], scale, b0));
                float p3 = __expf(fmaf(accS[kg][t8][3], scale, b1));
                accS[kg][t8][0] = p0;
                accS[kg][t8][1] = p1;
                accS[kg][t8][2] = p2;
                accS[kg][t8][3] = p3;
                rs0 += p0 + p1;
                rs1 += p2 + p3;
            }
        }

        // ---- O += P V : P register C-frag reinterpreted as A-frag (FA2 trick)
#pragma unroll
        for (int kc = 0; kc < 4; ++kc) {
            uint32_t ph[4], pl[4];
            ph[0] = pack_pair_hi(accS[kc][0][0], accS[kc][0][1]);
            ph[1] = pack_pair_hi(accS[kc][0][2], accS[kc][0][3]);
            ph[2] = pack_pair_hi(accS[kc][1][0], accS[kc][1][1]);
            ph[3] = pack_pair_hi(accS[kc][1][2], accS[kc][1][3]);
            pl[0] = pack_pair_lo(accS[kc][0][0], accS[kc][0][1]);
            pl[1] = pack_pair_lo(accS[kc][0][2], accS[kc][0][3]);
            pl[2] = pack_pair_lo(accS[kc][1][0], accS[kc][1][1]);
            pl[3] = pack_pair_lo(accS[kc][1][2], accS[kc][1][3]);
#pragma unroll
            for (int dg = 0; dg < 4; ++dg) {
                uint32_t vh[4], vl[4];
                int row = kc * 16 + rowV;
                uint32_t so = row * 128 + (((dg * 2 + cV) ^ (row & 7)) * 16);
                ldsm4t(vh, vb + so);
                ldsm4t(vl, vb + 8192 + so);
                mma16816(accO[dg][0], ph, vh[0], vh[1]);
                mma16816(accO[dg][0], ph, vl[0], vl[1]);
                mma16816(accO[dg][0], pl, vh[0], vh[1]);
                mma16816(accO[dg][1], ph, vh[2], vh[3]);
                mma16816(accO[dg][1], ph, vl[2], vl[3]);
                mma16816(accO[dg][1], pl, vh[2], vh[3]);
            }
        }
    }

    // ---- rowsum reduce within quad (each warp owns its rows fully)
    rs0 += __shfl_xor_sync(0xffffffffu, rs0, 1);
    rs0 += __shfl_xor_sync(0xffffffffu, rs0, 2);
    rs1 += __shfl_xor_sync(0xffffffffu, rs1, 1);
    rs1 += __shfl_xor_sync(0xffffffffu, rs1, 2);
    const float inv0 = 1.f / rs0;
    const float inv1 = 1.f / rs1;

    // ---- normalize + store O as bf16 hi/lo
    const int r0 = mq + (lane >> 2);
    const int r1 = r0 + 8;
    const size_t g0 = (qrow0 + r0) * 512 + h * 64;
    const size_t g1 = (qrow0 + r1) * 512 + h * 64;
#pragma unroll
    for (int dg = 0; dg < 4; ++dg) {
#pragma unroll
        for (int t8 = 0; t8 < 2; ++t8) {
            int d = dg * 16 + t8 * 8 + (lane & 3) * 2;
            float o0 = accO[dg][t8][0] * inv0, o1 = accO[dg][t8][1] * inv0;
            float o2 = accO[dg][t8][2] * inv1, o3 = accO[dg][t8][3] * inv1;
            *(uint32_t*)&g_ATh[g0 + d] = pack_pair_hi(o0, o1);
            *(uint32_t*)&g_ATl[g0 + d] = pack_pair_lo(o0, o1);
            *(uint32_t*)&g_ATh[g1 + d] = pack_pair_hi(o2, o3);
            *(uint32_t*)&g_ATl[g1 + d] = pack_pair_lo(o2, o3);
        }
    }
}

// ---------------------------------------------------------------- launch
extern "C" void kernel_launch(void* const* d_in, const int* in_sizes, int n_in,
                              void* d_out, int out_size)
{
    const float* x    = (const float*)d_in[0];
    const float* mask = (const float*)d_in[1];
    const float* WQ   = (const float*)d_in[2];
    const float* WK   = (const float*)d_in[3];
    const float* WV   = (const float*)d_in[4];
    const float* BE   = (const float*)d_in[5];
    const float* WO   = (const float*)d_in[6];
    float* out        = (float*)d_out;

    cudaFuncSetAttribute(attn_mma_kernel,
                         cudaFuncAttributeMaxDynamicSharedMemorySize, ATTN_SMEM);
    cudaFuncSetAttribute(gemm_bf16x3_kernel<0>,
                         cudaFuncAttributeMaxDynamicSharedMemorySize, GEMM_SMEM);
    cudaFuncSetAttribute(gemm_bf16x3_kernel<1>,
                         cudaFuncAttributeMaxDynamicSharedMemorySize, GEMM_SMEM);

    prep_a_kernel<<<(Mm * Ee / 4) / 256, 256>>>(x, BE);
    prep_w_kernel<<<(2048 * 512) / 256, 256>>>(WQ, WK, WV, WO);

    dim3 gq(Mm / 128, 512 / 128, 3);
    gemm_bf16x3_kernel<0><<<gq, 256, GEMM_SMEM>>>(nullptr);

    dim3 ga(Ss / 128, Hh, Bb);
    attn_mma_kernel<<<ga, 256, ATTN_SMEM>>>(mask);

    dim3 go(Mm / 128, 512 / 128, 1);
    gemm_bf16x3_kernel<1><<<go, 256, GEMM_SMEM>>>(out);
}

// round 8
// speedup vs baseline: 3.5197x; 1.0234x over previous
#include <cuda_runtime.h>
#include <cuda_bf16.h>
#include <stdint.h>
#include <math.h>

// ---------------------------------------------------------------- dims
static constexpr int Bb = 64;
static constexpr int Ss = 512;
static constexpr int Ee = 512;
static constexpr int Hh = 8;
static constexpr int Dd = 64;
static constexpr int Mm = Bb * Ss;     // 32768
static constexpr int HD = Hh * Dd;     // 512

// ---------------------------------------------------------------- scratch
__device__ __nv_bfloat16 g_Ah[Mm * Ee];
__device__ __nv_bfloat16 g_Al[Mm * Ee];
__device__ __nv_bfloat16 g_ATh[Mm * HD];
__device__ __nv_bfloat16 g_ATl[Mm * HD];
__device__ __nv_bfloat16 g_Bh[2048 * 512];
__device__ __nv_bfloat16 g_Bl[2048 * 512];
__device__ __nv_bfloat16 g_Qh[Mm * HD];
__device__ __nv_bfloat16 g_Ql[Mm * HD];
__device__ __nv_bfloat16 g_Kh[Mm * HD];
__device__ __nv_bfloat16 g_Kl[Mm * HD];
__device__ __nv_bfloat16 g_Vh[Mm * HD];
__device__ __nv_bfloat16 g_Vl[Mm * HD];

// ---------------------------------------------------------------- helpers
// Pack (v0,v1) to bf16x2 hi pair + exact-residual lo pair. 6 instructions.
__device__ __forceinline__ void pack_hilo(float v0, float v1, uint32_t& hp, uint32_t& lp) {
    asm("cvt.rn.bf16x2.f32 %0, %1, %2;" : "=r"(hp) : "f"(v1), "f"(v0));
    float h0 = __uint_as_float(hp << 16);
    float h1 = __uint_as_float(hp & 0xFFFF0000u);
    float r0 = v0 - h0;    // exact
    float r1 = v1 - h1;    // exact
    asm("cvt.rn.bf16x2.f32 %0, %1, %2;" : "=r"(lp) : "f"(r1), "f"(r0));
}
__device__ __forceinline__ float ex2(float x) {
    float r;
    asm("ex2.approx.f32 %0, %1;" : "=f"(r) : "f"(x));
    return r;
}
__device__ __forceinline__ uint32_t smem_u32(const void* p) {
    uint32_t a;
    asm("{ .reg .u64 t; cvta.to.shared.u64 t, %1; cvt.u32.u64 %0, t; }" : "=r"(a) : "l"(p));
    return a;
}
__device__ __forceinline__ void ldsm4(uint32_t r[4], uint32_t addr) {
    asm volatile("ldmatrix.sync.aligned.m8n8.x4.shared.b16 {%0,%1,%2,%3}, [%4];"
                 : "=r"(r[0]), "=r"(r[1]), "=r"(r[2]), "=r"(r[3]) : "r"(addr));
}
__device__ __forceinline__ void ldsm4t(uint32_t r[4], uint32_t addr) {
    asm volatile("ldmatrix.sync.aligned.m8n8.x4.trans.shared.b16 {%0,%1,%2,%3}, [%4];"
                 : "=r"(r[0]), "=r"(r[1]), "=r"(r[2]), "=r"(r[3]) : "r"(addr));
}
__device__ __forceinline__ void mma16816(float d[4], const uint32_t a[4],
                                         uint32_t b0, uint32_t b1) {
    asm volatile("mma.sync.aligned.m16n8k16.row.col.f32.bf16.bf16.f32 "
                 "{%0,%1,%2,%3}, {%4,%5,%6,%7}, {%8,%9}, {%0,%1,%2,%3};"
                 : "+f"(d[0]), "+f"(d[1]), "+f"(d[2]), "+f"(d[3])
                 : "r"(a[0]), "r"(a[1]), "r"(a[2]), "r"(a[3]), "r"(b0), "r"(b1));
}
__device__ __forceinline__ void cpasync16(uint32_t saddr, const void* g) {
    asm volatile("cp.async.cg.shared.global [%0], [%1], 16;" :: "r"(saddr), "l"(g));
}
__device__ __forceinline__ void cpcommit() {
    asm volatile("cp.async.commit_group;" ::: "memory");
}
template <int N>
__device__ __forceinline__ void cpwait() {
    asm volatile("cp.async.wait_group %0;" :: "n"(N) : "memory");
}

// ---------------------------------------------------------------- fused prep
// blocks [0, 16384): A = x + BE split to hi/lo      (Mm*Ee/4 float4s)
// blocks [16384, 20480): weights W^T split to hi/lo (2048*512 elems)
__global__ __launch_bounds__(256) void prep_kernel(const float* __restrict__ x,
                                                   const float* __restrict__ be,
                                                   const float* __restrict__ WQ,
                                                   const float* __restrict__ WK,
                                                   const float* __restrict__ WV,
                                                   const float* __restrict__ WO) {
    if (blockIdx.x < 16384) {
        uint32_t i4 = blockIdx.x * 256 + threadIdx.x;
        int m = i4 >> 7;
        int k = (i4 & 127) << 2;
        const float4 xv = *(const float4*)&x[(size_t)m * Ee + k];
        const float4 bv = *(const float4*)&be[(size_t)(m & (Ss - 1)) * Ee + k];
        uint32_t h01, h23, l01, l23;
        pack_hilo(xv.x + bv.x, xv.y + bv.y, h01, l01);
        pack_hilo(xv.z + bv.z, xv.w + bv.w, h23, l23);
        size_t o = (size_t)m * Ee + k;
        *(uint32_t*)&g_Ah[o]     = h01;
        *(uint32_t*)&g_Ah[o + 2] = h23;
        *(uint32_t*)&g_Al[o]     = l01;
        *(uint32_t*)&g_Al[o + 2] = l23;
    } else {
        uint32_t idx = (blockIdx.x - 16384) * 256 + threadIdx.x;
        int r = idx >> 9;
        int k = idx & 511;
        float v;
        if (r < 1536) {
            int z = r >> 9;
            int n = r & 511;
            const float* W = (z == 0) ? WQ : (z == 1) ? WK : WV;
            v = W[(size_t)(n >> 6) * (Ee * Dd) + (size_t)k * Dd + (n & 63)];
        } else {
            int n = r - 1536;
            v = WO[(size_t)k * Ee + n];
        }
        uint32_t hp, lp;
        pack_hilo(v, v, hp, lp);
        g_Bh[idx] = *(__nv_bfloat16*)&hp;   // low half = bf16(v)
        g_Bl[idx] = *(__nv_bfloat16*)&lp;
    }
}

// ---------------------------------------------------------------- HMMA GEMM (cp.async 3-stage)
static constexpr int SA_H = 0;
static constexpr int SA_L = 8192;
static constexpr int SB_H = 16384;
static constexpr int SB_L = 24576;
static constexpr int GSTAGE = 32768;
static constexpr int GEMM_SMEM = 3 * GSTAGE;   // 96 KB

template <int WHICH>
__global__ __launch_bounds__(256, 2) void gemm_bf16x3_kernel(float* __restrict__ Cout)
{
    extern __shared__ __align__(16) char sm[];
    const uint32_t sb = smem_u32(sm);
    const int tid  = threadIdx.x;
    const int wid  = tid >> 5;
    const int lane = tid & 31;

    const int m0 = blockIdx.x * 128;
    const int n0 = blockIdx.y * 128;
    const int z  = (WHICH == 0) ? blockIdx.z : 0;

    const __nv_bfloat16* Ah = (WHICH == 0) ? g_Ah : g_ATh;
    const __nv_bfloat16* Al = (WHICH == 0) ? g_Al : g_ATl;
    const size_t boff = (WHICH == 0) ? (size_t)z * 512 * 512 : (size_t)1536 * 512;
    const __nv_bfloat16* Bh = g_Bh + boff;
    const __nv_bfloat16* Bl = g_Bl + boff;

    const int m_warp = (wid & 3) * 32;
    const int n_warp = (wid >> 2) * 64;

    const int rA   = m_warp + (lane & 7) + ((lane >> 3) & 1) * 8;
    const int kbA  = lane >> 4;
    const int sxA  = (rA >> 1) & 3;
    const int rB   = n_warp + (lane & 7) + (lane >> 4) * 8;
    const int kbB  = (lane >> 3) & 1;
    const int sxB  = (rB >> 1) & 3;

    float acc[2][8][4];
#pragma unroll
    for (int i = 0; i < 2; i++)
#pragma unroll
        for (int j = 0; j < 8; j++)
#pragma unroll
            for (int u = 0; u < 4; u++) acc[i][j][u] = 0.f;

    const int grow0 = (tid + 0)   >> 2, gc80 = (tid + 0)   & 3;
    const int grow1 = (tid + 256) >> 2, gc81 = (tid + 256) & 3;
    const uint32_t so0 = grow0 * 64 + ((gc80 ^ ((grow0 >> 1) & 3)) * 16);
    const uint32_t so1 = grow1 * 64 + ((gc81 ^ ((grow1 >> 1) & 3)) * 16);
    const __nv_bfloat16* pAh0 = Ah + (size_t)(m0 + grow0) * 512 + gc80 * 8;
    const __nv_bfloat16* pAh1 = Ah + (size_t)(m0 + grow1) * 512 + gc81 * 8;
    const __nv_bfloat16* pAl0 = Al + (size_t)(m0 + grow0) * 512 + gc80 * 8;
    const __nv_bfloat16* pAl1 = Al + (size_t)(m0 + grow1) * 512 + gc81 * 8;
    const __nv_bfloat16* pBh0 = Bh + (size_t)(n0 + grow0) * 512 + gc80 * 8;
    const __nv_bfloat16* pBh1 = Bh + (size_t)(n0 + grow1) * 512 + gc81 * 8;
    const __nv_bfloat16* pBl0 = Bl + (size_t)(n0 + grow0) * 512 + gc80 * 8;
    const __nv_bfloat16* pBl1 = Bl + (size_t)(n0 + grow1) * 512 + gc81 * 8;

#define LOAD_CHUNK(k0, stage) do {                                        \
        uint32_t s_ = sb + (stage) * GSTAGE;                              \
        cpasync16(s_ + SA_H + so0, pAh0 + (k0));                          \
        cpasync16(s_ + SA_H + so1, pAh1 + (k0));                          \
        cpasync16(s_ + SA_L + so0, pAl0 + (k0));                          \
        cpasync16(s_ + SA_L + so1, pAl1 + (k0));                          \
        cpasync16(s_ + SB_H + so0, pBh0 + (k0));                          \
        cpasync16(s_ + SB_H + so1, pBh1 + (k0));                          \
        cpasync16(s_ + SB_L + so0, pBl0 + (k0));                          \
        cpasync16(s_ + SB_L + so1, pBl1 + (k0));                          \
        cpcommit();                                                       \
    } while (0)

    LOAD_CHUNK(0, 0);
    LOAD_CHUNK(32, 1);

    for (int c = 0; c < 16; ++c) {
        if (c < 15) cpwait<1>(); else cpwait<0>();
        __syncthreads();
        if (c + 2 < 16) LOAD_CHUNK((c + 2) * 32, (c + 2) % 3);

        const uint32_t sbs = sb + (c % 3) * GSTAGE;
#pragma unroll
        for (int kk = 0; kk < 2; ++kk) {
            uint32_t ah[2][4], al[2][4];
#pragma unroll
            for (int tm = 0; tm < 2; ++tm) {
                uint32_t ro = (uint32_t)(rA + tm * 16) * 64 +
                              (uint32_t)(((kk * 2 + kbA) ^ sxA) * 16);
                ldsm4(ah[tm], sbs + SA_H + ro);
                ldsm4(al[tm], sbs + SA_L + ro);
            }
#pragma unroll
            for (int tp = 0; tp < 4; ++tp) {
                uint32_t bh[4], bl[4];
                uint32_t ro = (uint32_t)(rB + tp * 16) * 64 +
                              (uint32_t)(((kk * 2 + kbB) ^ sxB) * 16);
                ldsm4(bh, sbs + SB_H + ro);
                ldsm4(bl, sbs + SB_L + ro);
#pragma unroll
                for (int tm = 0; tm < 2; ++tm) {
                    mma16816(acc[tm][2 * tp],     ah[tm], bh[0], bh[1]);
                    mma16816(acc[tm][2 * tp],     ah[tm], bl[0], bl[1]);
                    mma16816(acc[tm][2 * tp],     al[tm], bh[0], bh[1]);
                    mma16816(acc[tm][2 * tp + 1], ah[tm], bh[2], bh[3]);
                    mma16816(acc[tm][2 * tp + 1], ah[tm], bl[2], bl[3]);
                    mma16816(acc[tm][2 * tp + 1], al[tm], bh[2], bh[3]);
                }
            }
        }
    }
#undef LOAD_CHUNK

    // epilogue
    if (WHICH == 0) {
        __nv_bfloat16* Ch = (z == 0) ? g_Qh : (z == 1) ? g_Kh : g_Vh;
        __nv_bfloat16* Cl = (z == 0) ? g_Ql : (z == 1) ? g_Kl : g_Vl;
#pragma unroll
        for (int tm = 0; tm < 2; ++tm) {
            const int m = m0 + m_warp + tm * 16 + (lane >> 2);
#pragma unroll
            for (int tn = 0; tn < 8; ++tn) {
                const int n = n0 + n_warp + tn * 8 + (lane & 3) * 2;
                size_t o0 = (size_t)m * 512 + n;
                size_t o1 = (size_t)(m + 8) * 512 + n;
                uint32_t hp0, lp0, hp1, lp1;
                pack_hilo(acc[tm][tn][0], acc[tm][tn][1], hp0, lp0);
                pack_hilo(acc[tm][tn][2], acc[tm][tn][3], hp1, lp1);
                *(uint32_t*)&Ch[o0] = hp0;
                *(uint32_t*)&Cl[o0] = lp0;
                *(uint32_t*)&Ch[o1] = hp1;
                *(uint32_t*)&Cl[o1] = lp1;
            }
        }
    } else {
#pragma unroll
        for (int tm = 0; tm < 2; ++tm) {
            const int m = m0 + m_warp + tm * 16 + (lane >> 2);
#pragma unroll
            for (int tn = 0; tn < 8; ++tn) {
                const int n = n0 + n_warp + tn * 8 + (lane & 3) * 2;
                *(float2*)&Cout[(size_t)m * 512 + n] =
                    make_float2(acc[tm][tn][0], acc[tm][tn][1]);
                *(float2*)&Cout[(size_t)(m + 8) * 512 + n] =
                    make_float2(acc[tm][tn][2], acc[tm][tn][3]);
            }
        }
    }
}

// ---------------------------------------------------------------- tensor-core attention
// FA2-style: warp = 16 q rows x all 64 keys; P in registers.
// K,V double-buffered; ONE sync per key tile. exp via ex2 with folded log2e.
static constexpr int A_QH = 0;         // 16 KB
static constexpr int A_QL = 16384;     // 16 KB
static constexpr int A_K0 = 32768;     // 2 stages x 16 KB (KH +0, KL +8192)
static constexpr int A_V0 = 65536;     // 2 stages x 16 KB
static constexpr int A_BI = 98304;     // 512 floats (pre-scaled by -1e10*log2e)
static constexpr int ATTN_SMEM = 100352;

__global__ __launch_bounds__(256, 2) void attn_mma_kernel(const float* __restrict__ mask)
{
    extern __shared__ char sm[];
    const uint32_t sb = smem_u32(sm);
    const int tid  = threadIdx.x;
    const int wid  = tid >> 5;
    const int lane = tid & 31;

    const int qt = blockIdx.x;
    const int h  = blockIdx.y;
    const int b  = blockIdx.z;
    const int mq = wid * 16;
    const size_t qrow0 = (size_t)b * 512 + qt * 128;

    // prologue: Q + K(0) + V(0)
#pragma unroll
    for (int i = 0; i < 4; i++) {
        int idx = tid + i * 256;
        int row = idx >> 3, c = idx & 7;
        uint32_t so = row * 128 + ((c ^ (row & 7)) * 16);
        size_t g = (qrow0 + row) * 512 + h * 64 + c * 8;
        cpasync16(sb + A_QH + so, &g_Qh[g]);
        cpasync16(sb + A_QL + so, &g_Ql[g]);
    }
#pragma unroll
    for (int i = 0; i < 2; i++) {
        int idx = tid + i * 256;
        int row = idx >> 3, c = idx & 7;
        uint32_t so = row * 128 + ((c ^ (row & 7)) * 16);
        size_t g = ((size_t)b * 512 + row) * 512 + h * 64 + c * 8;
        cpasync16(sb + A_K0 + so, &g_Kh[g]);
        cpasync16(sb + A_K0 + 8192 + so, &g_Kl[g]);
        cpasync16(sb + A_V0 + so, &g_Vh[g]);
        cpasync16(sb + A_V0 + 8192 + so, &g_Vl[g]);
    }
    cpcommit();
#pragma unroll
    for (int i = 0; i < 2; i++) {
        int t = tid + i * 256;
        ((float*)(sm + A_BI))[t] = -1.4426950408889634e10f * mask[(size_t)b * 512 + t];
    }

    float accO[4][2][4];
#pragma unroll
    for (int i = 0; i < 4; i++)
#pragma unroll
        for (int j = 0; j < 2; j++)
#pragma unroll
            for (int u = 0; u < 4; u++) accO[i][j][u] = 0.f;
    float rs0 = 0.f, rs1 = 0.f;

    const float scale2 = 0.044194173824159216f * 1.4426950408889634f;  // /sqrt(E) * log2(e)

    const int rowQ = mq + (lane & 7) + ((lane >> 3) & 1) * 8;
    const int cQ   = lane >> 4;
    const int rowK = (lane & 7) + (lane >> 4) * 8;
    const int cK   = (lane >> 3) & 1;
    const int rowV = (lane & 7) + ((lane >> 3) & 1) * 8;
    const int cV   = lane >> 4;

    for (int tile = 0; tile < 8; ++tile) {
        cpwait<0>();
        __syncthreads();

        if (tile < 7) {
            const int t1 = (tile + 1) * 64;
            const uint32_t kb1 = sb + A_K0 + ((tile + 1) & 1) * 16384;
            const uint32_t vb1 = sb + A_V0 + ((tile + 1) & 1) * 16384;
#pragma unroll
            for (int i = 0; i < 2; i++) {
                int idx = tid + i * 256;
                int row = idx >> 3, c = idx & 7;
                uint32_t so = row * 128 + ((c ^ (row & 7)) * 16);
                size_t g = ((size_t)b * 512 + t1 + row) * 512 + h * 64 + c * 8;
                cpasync16(kb1 + so, &g_Kh[g]);
                cpasync16(kb1 + 8192 + so, &g_Kl[g]);
                cpasync16(vb1 + so, &g_Vh[g]);
                cpasync16(vb1 + 8192 + so, &g_Vl[g]);
            }
            cpcommit();
        }

        const uint32_t kb = sb + A_K0 + (tile & 1) * 16384;
        const uint32_t vb = sb + A_V0 + (tile & 1) * 16384;

        // ---- S = Q K^T : 16q x 64k per warp
        float accS[4][2][4];
#pragma unroll
        for (int i = 0; i < 4; i++)
#pragma unroll
            for (int j = 0; j < 2; j++)
#pragma unroll
                for (int u = 0; u < 4; u++) accS[i][j][u] = 0.f;

#pragma unroll
        for (int ks = 0; ks < 4; ++ks) {
            uint32_t qh[4], ql[4];
            {
                uint32_t so = rowQ * 128 + (((ks * 2 + cQ) ^ (rowQ & 7)) * 16);
                ldsm4(qh, sb + A_QH + so);
                ldsm4(ql, sb + A_QL + so);
            }
#pragma unroll
            for (int kg = 0; kg < 4; ++kg) {
                uint32_t kh[4], kl[4];
                int row = kg * 16 + rowK;
                uint32_t so = row * 128 + (((ks * 2 + cK) ^ (row & 7)) * 16);
                ldsm4(kh, kb + so);
                ldsm4(kl, kb + 8192 + so);
                mma16816(accS[kg][0], qh, kh[0], kh[1]);
                mma16816(accS[kg][0], qh, kl[0], kl[1]);
                mma16816(accS[kg][0], ql, kh[0], kh[1]);
                mma16816(accS[kg][1], qh, kh[2], kh[3]);
                mma16816(accS[kg][1], qh, kl[2], kl[3]);
                mma16816(accS[kg][1], ql, kh[2], kh[3]);
            }
        }

        // ---- per-16-key chunk: exp (ex2) + pack + PV MMAs, interleaved
        const int t0 = tile * 64;
#pragma unroll
        for (int kc = 0; kc < 4; ++kc) {
            float p[2][4];
#pragma unroll
            for (int t8 = 0; t8 < 2; ++t8) {
                int key = t0 + kc * 16 + t8 * 8 + (lane & 3) * 2;
                const float2 bb = *(const float2*)&((const float*)(sm + A_BI))[key];
                p[t8][0] = ex2(fmaf(accS[kc][t8][0], scale2, bb.x));
                p[t8][1] = ex2(fmaf(accS[kc][t8][1], scale2, bb.y));
                p[t8][2] = ex2(fmaf(accS[kc][t8][2], scale2, bb.x));
                p[t8][3] = ex2(fmaf(accS[kc][t8][3], scale2, bb.y));
                rs0 += p[t8][0] + p[t8][1];
                rs1 += p[t8][2] + p[t8][3];
            }
            uint32_t ph[4], pl[4];
            pack_hilo(p[0][0], p[0][1], ph[0], pl[0]);
            pack_hilo(p[0][2], p[0][3], ph[1], pl[1]);
            pack_hilo(p[1][0], p[1][1], ph[2], pl[2]);
            pack_hilo(p[1][2], p[1][3], ph[3], pl[3]);
#pragma unroll
            for (int dg = 0; dg < 4; ++dg) {
                uint32_t vh[4], vl[4];
                int row = kc * 16 + rowV;
                uint32_t so = row * 128 + (((dg * 2 + cV) ^ (row & 7)) * 16);
                ldsm4t(vh, vb + so);
                ldsm4t(vl, vb + 8192 + so);
                mma16816(accO[dg][0], ph, vh[0], vh[1]);
                mma16816(accO[dg][0], ph, vl[0], vl[1]);
                mma16816(accO[dg][0], pl, vh[0], vh[1]);
                mma16816(accO[dg][1], ph, vh[2], vh[3]);
                mma16816(accO[dg][1], ph, vl[2], vl[3]);
                mma16816(accO[dg][1], pl, vh[2], vh[3]);
            }
        }
    }

    // ---- rowsum reduce within quad
    rs0 += __shfl_xor_sync(0xffffffffu, rs0, 1);
    rs0 += __shfl_xor_sync(0xffffffffu, rs0, 2);
    rs1 += __shfl_xor_sync(0xffffffffu, rs1, 1);
    rs1 += __shfl_xor_sync(0xffffffffu, rs1, 2);
    const float inv0 = 1.f / rs0;
    const float inv1 = 1.f / rs1;

    // ---- normalize + store O as bf16 hi/lo
    const int r0 = mq + (lane >> 2);
    const int r1 = r0 + 8;
    const size_t g0 = (qrow0 + r0) * 512 + h * 64;
    const size_t g1 = (qrow0 + r1) * 512 + h * 64;
#pragma unroll
    for (int dg = 0; dg < 4; ++dg) {
#pragma unroll
        for (int t8 = 0; t8 < 2; ++t8) {
            int d = dg * 16 + t8 * 8 + (lane & 3) * 2;
            uint32_t hp0, lp0, hp1, lp1;
            pack_hilo(accO[dg][t8][0] * inv0, accO[dg][t8][1] * inv0, hp0, lp0);
            pack_hilo(accO[dg][t8][2] * inv1, accO[dg][t8][3] * inv1, hp1, lp1);
            *(uint32_t*)&g_ATh[g0 + d] = hp0;
            *(uint32_t*)&g_ATl[g0 + d] = lp0;
            *(uint32_t*)&g_ATh[g1 + d] = hp1;
            *(uint32_t*)&g_ATl[g1 + d] = lp1;
        }
    }
}

// ---------------------------------------------------------------- launch
extern "C" void kernel_launch(void* const* d_in, const int* in_sizes, int n_in,
                              void* d_out, int out_size)
{
    const float* x    = (const float*)d_in[0];
    const float* mask = (const float*)d_in[1];
    const float* WQ   = (const float*)d_in[2];
    const float* WK   = (const float*)d_in[3];
    const float* WV   = (const float*)d_in[4];
    const float* BE   = (const float*)d_in[5];
    const float* WO   = (const float*)d_in[6];
    float* out        = (float*)d_out;

    cudaFuncSetAttribute(attn_mma_kernel,
                         cudaFuncAttributeMaxDynamicSharedMemorySize, ATTN_SMEM);
    cudaFuncSetAttribute(gemm_bf16x3_kernel<0>,
                         cudaFuncAttributeMaxDynamicSharedMemorySize, GEMM_SMEM);
    cudaFuncSetAttribute(gemm_bf16x3_kernel<1>,
                         cudaFuncAttributeMaxDynamicSharedMemorySize, GEMM_SMEM);

    prep_kernel<<<16384 + 4096, 256>>>(x, BE, WQ, WK, WV, WO);

    dim3 gq(Mm / 128, 512 / 128, 3);
    gemm_bf16x3_kernel<0><<<gq, 256, GEMM_SMEM>>>(nullptr);

    dim3 ga(Ss / 128, Hh, Bb);
    attn_mma_kernel<<<ga, 256, ATTN_SMEM>>>(mask);

    dim3 go(Mm / 128, 512 / 128, 1);
    gemm_bf16x3_kernel<1><<<go, 256, GEMM_SMEM>>>(out);
}

// round 9
// speedup vs baseline: 3.9904x; 1.1337x over previous
#include <cuda_runtime.h>
#include <cuda_bf16.h>
#include <stdint.h>
#include <math.h>

// ---------------------------------------------------------------- dims
static constexpr int Bb = 64;
static constexpr int Ss = 512;
static constexpr int Ee = 512;
static constexpr int Hh = 8;
static constexpr int Dd = 64;
static constexpr int Mm = Bb * Ss;     // 32768
static constexpr int HD = Hh * Dd;     // 512

// ---------------------------------------------------------------- scratch
__device__ __nv_bfloat16 g_Ah[Mm * Ee];
__device__ __nv_bfloat16 g_Al[Mm * Ee];
__device__ __nv_bfloat16 g_ATh[Mm * HD];
__device__ __nv_bfloat16 g_ATl[Mm * HD];
__device__ __nv_bfloat16 g_Bh[2048 * 512];
__device__ __nv_bfloat16 g_Bl[2048 * 512];
__device__ __nv_bfloat16 g_Qh[Mm * HD];
__device__ __nv_bfloat16 g_Ql[Mm * HD];
__device__ __nv_bfloat16 g_Kh[Mm * HD];
__device__ __nv_bfloat16 g_Kl[Mm * HD];
__device__ __nv_bfloat16 g_Vh[Mm * HD];
__device__ __nv_bfloat16 g_Vl[Mm * HD];
// mask compaction
__device__ int g_idx[Bb * Ss];
__device__ int g_nt[Bb];
__device__ int g_nk[Bb];

// ---------------------------------------------------------------- helpers
__device__ __forceinline__ void pack_hilo(float v0, float v1, uint32_t& hp, uint32_t& lp) {
    asm("cvt.rn.bf16x2.f32 %0, %1, %2;" : "=r"(hp) : "f"(v1), "f"(v0));
    float h0 = __uint_as_float(hp << 16);
    float h1 = __uint_as_float(hp & 0xFFFF0000u);
    float r0 = v0 - h0;
    float r1 = v1 - h1;
    asm("cvt.rn.bf16x2.f32 %0, %1, %2;" : "=r"(lp) : "f"(r1), "f"(r0));
}
__device__ __forceinline__ float ex2(float x) {
    float r;
    asm("ex2.approx.f32 %0, %1;" : "=f"(r) : "f"(x));
    return r;
}
__device__ __forceinline__ uint32_t smem_u32(const void* p) {
    uint32_t a;
    asm("{ .reg .u64 t; cvta.to.shared.u64 t, %1; cvt.u32.u64 %0, t; }" : "=r"(a) : "l"(p));
    return a;
}
__device__ __forceinline__ void ldsm4(uint32_t r[4], uint32_t addr) {
    asm volatile("ldmatrix.sync.aligned.m8n8.x4.shared.b16 {%0,%1,%2,%3}, [%4];"
                 : "=r"(r[0]), "=r"(r[1]), "=r"(r[2]), "=r"(r[3]) : "r"(addr));
}
__device__ __forceinline__ void ldsm4t(uint32_t r[4], uint32_t addr) {
    asm volatile("ldmatrix.sync.aligned.m8n8.x4.trans.shared.b16 {%0,%1,%2,%3}, [%4];"
                 : "=r"(r[0]), "=r"(r[1]), "=r"(r[2]), "=r"(r[3]) : "r"(addr));
}
__device__ __forceinline__ void mma16816(float d[4], const uint32_t a[4],
                                         uint32_t b0, uint32_t b1) {
    asm volatile("mma.sync.aligned.m16n8k16.row.col.f32.bf16.bf16.f32 "
                 "{%0,%1,%2,%3}, {%4,%5,%6,%7}, {%8,%9}, {%0,%1,%2,%3};"
                 : "+f"(d[0]), "+f"(d[1]), "+f"(d[2]), "+f"(d[3])
                 : "r"(a[0]), "r"(a[1]), "r"(a[2]), "r"(a[3]), "r"(b0), "r"(b1));
}
__device__ __forceinline__ void cpasync16(uint32_t saddr, const void* g) {
    asm volatile("cp.async.cg.shared.global [%0], [%1], 16;" :: "r"(saddr), "l"(g));
}
__device__ __forceinline__ void cpcommit() {
    asm volatile("cp.async.commit_group;" ::: "memory");
}
template <int N>
__device__ __forceinline__ void cpwait() {
    asm volatile("cp.async.wait_group %0;" :: "n"(N) : "memory");
}

// ---------------------------------------------------------------- mask compaction
__global__ __launch_bounds__(512) void mask_compact_kernel(const float* __restrict__ mask) {
    const int b = blockIdx.x, t = threadIdx.x;
    const int wid = t >> 5, lane = t & 31;
    const bool keep = (mask[(size_t)b * 512 + t] == 0.0f);
    const unsigned bal = __ballot_sync(0xffffffffu, keep);
    __shared__ int wcnt[16], woff[16], snk;
    if (lane == 0) wcnt[wid] = __popc(bal);
    __syncthreads();
    if (t == 0) {
        int s = 0;
        for (int i = 0; i < 16; i++) { woff[i] = s; s += wcnt[i]; }
        snk = s;
        g_nk[b] = s;
        g_nt[b] = (s + 63) >> 6;
    }
    __syncthreads();
    const int nk = snk;
    const int pos = woff[wid] + __popc(bal & ((1u << lane) - 1));
    if (keep) g_idx[b * 512 + pos] = t;
    const int ntk = ((nk + 63) >> 6) << 6;
    if (t >= nk && t < ntk) g_idx[b * 512 + t] = 0;   // padded keys (killed by predicate)
}

// ---------------------------------------------------------------- fused prep
__global__ __launch_bounds__(256) void prep_kernel(const float* __restrict__ x,
                                                   const float* __restrict__ be,
                                                   const float* __restrict__ WQ,
                                                   const float* __restrict__ WK,
                                                   const float* __restrict__ WV,
                                                   const float* __restrict__ WO) {
    if (blockIdx.x < 16384) {
        uint32_t i4 = blockIdx.x * 256 + threadIdx.x;
        int m = i4 >> 7;
        int k = (i4 & 127) << 2;
        const float4 xv = *(const float4*)&x[(size_t)m * Ee + k];
        const float4 bv = *(const float4*)&be[(size_t)(m & (Ss - 1)) * Ee + k];
        uint32_t h01, h23, l01, l23;
        pack_hilo(xv.x + bv.x, xv.y + bv.y, h01, l01);
        pack_hilo(xv.z + bv.z, xv.w + bv.w, h23, l23);
        size_t o = (size_t)m * Ee + k;
        *(uint32_t*)&g_Ah[o]     = h01;
        *(uint32_t*)&g_Ah[o + 2] = h23;
        *(uint32_t*)&g_Al[o]     = l01;
        *(uint32_t*)&g_Al[o + 2] = l23;
    } else {
        uint32_t idx = (blockIdx.x - 16384) * 256 + threadIdx.x;
        int r = idx >> 9;
        int k = idx & 511;
        float v;
        if (r < 1536) {
            int z = r >> 9;
            int n = r & 511;
            const float* W = (z == 0) ? WQ : (z == 1) ? WK : WV;
            v = W[(size_t)(n >> 6) * (Ee * Dd) + (size_t)k * Dd + (n & 63)];
        } else {
            int n = r - 1536;
            v = WO[(size_t)k * Ee + n];
        }
        uint32_t hp, lp;
        pack_hilo(v, v, hp, lp);
        g_Bh[idx] = *(__nv_bfloat16*)&hp;
        g_Bl[idx] = *(__nv_bfloat16*)&lp;
    }
}

// ---------------------------------------------------------------- HMMA GEMM (cp.async 3-stage)
static constexpr int SA_H = 0;
static constexpr int SA_L = 8192;
static constexpr int SB_H = 16384;
static constexpr int SB_L = 24576;
static constexpr int GSTAGE = 32768;
static constexpr int GEMM_SMEM = 3 * GSTAGE;   // 96 KB

template <int WHICH>
__global__ __launch_bounds__(256, 2) void gemm_bf16x3_kernel(float* __restrict__ Cout)
{
    extern __shared__ __align__(16) char sm[];
    const uint32_t sb = smem_u32(sm);
    const int tid  = threadIdx.x;
    const int wid  = tid >> 5;
    const int lane = tid & 31;

    const int m0 = blockIdx.x * 128;
    const int n0 = blockIdx.y * 128;
    const int z  = (WHICH == 0) ? blockIdx.z : 0;

    const __nv_bfloat16* Ah = (WHICH == 0) ? g_Ah : g_ATh;
    const __nv_bfloat16* Al = (WHICH == 0) ? g_Al : g_ATl;
    const size_t boff = (WHICH == 0) ? (size_t)z * 512 * 512 : (size_t)1536 * 512;
    const __nv_bfloat16* Bh = g_Bh + boff;
    const __nv_bfloat16* Bl = g_Bl + boff;

    const int m_warp = (wid & 3) * 32;
    const int n_warp = (wid >> 2) * 64;

    const int rA   = m_warp + (lane & 7) + ((lane >> 3) & 1) * 8;
    const int kbA  = lane >> 4;
    const int sxA  = (rA >> 1) & 3;
    const int rB   = n_warp + (lane & 7) + (lane >> 4) * 8;
    const int kbB  = (lane >> 3) & 1;
    const int sxB  = (rB >> 1) & 3;

    float acc[2][8][4];
#pragma unroll
    for (int i = 0; i < 2; i++)
#pragma unroll
        for (int j = 0; j < 8; j++)
#pragma unroll
            for (int u = 0; u < 4; u++) acc[i][j][u] = 0.f;

    const int grow0 = (tid + 0)   >> 2, gc80 = (tid + 0)   & 3;
    const int grow1 = (tid + 256) >> 2, gc81 = (tid + 256) & 3;
    const uint32_t so0 = grow0 * 64 + ((gc80 ^ ((grow0 >> 1) & 3)) * 16);
    const uint32_t so1 = grow1 * 64 + ((gc81 ^ ((grow1 >> 1) & 3)) * 16);
    const __nv_bfloat16* pAh0 = Ah + (size_t)(m0 + grow0) * 512 + gc80 * 8;
    const __nv_bfloat16* pAh1 = Ah + (size_t)(m0 + grow1) * 512 + gc81 * 8;
    const __nv_bfloat16* pAl0 = Al + (size_t)(m0 + grow0) * 512 + gc80 * 8;
    const __nv_bfloat16* pAl1 = Al + (size_t)(m0 + grow1) * 512 + gc81 * 8;
    const __nv_bfloat16* pBh0 = Bh + (size_t)(n0 + grow0) * 512 + gc80 * 8;
    const __nv_bfloat16* pBh1 = Bh + (size_t)(n0 + grow1) * 512 + gc81 * 8;
    const __nv_bfloat16* pBl0 = Bl + (size_t)(n0 + grow0) * 512 + gc80 * 8;
    const __nv_bfloat16* pBl1 = Bl + (size_t)(n0 + grow1) * 512 + gc81 * 8;

#define LOAD_CHUNK(k0, stage) do {                                        \
        uint32_t s_ = sb + (stage) * GSTAGE;                              \
        cpasync16(s_ + SA_H + so0, pAh0 + (k0));                          \
        cpasync16(s_ + SA_H + so1, pAh1 + (k0));                          \
        cpasync16(s_ + SA_L + so0, pAl0 + (k0));                          \
        cpasync16(s_ + SA_L + so1, pAl1 + (k0));                          \
        cpasync16(s_ + SB_H + so0, pBh0 + (k0));                          \
        cpasync16(s_ + SB_H + so1, pBh1 + (k0));                          \
        cpasync16(s_ + SB_L + so0, pBl0 + (k0));                          \
        cpasync16(s_ + SB_L + so1, pBl1 + (k0));                          \
        cpcommit();                                                       \
    } while (0)

    LOAD_CHUNK(0, 0);
    LOAD_CHUNK(32, 1);

    for (int c = 0; c < 16; ++c) {
        if (c < 15) cpwait<1>(); else cpwait<0>();
        __syncthreads();
        if (c + 2 < 16) LOAD_CHUNK((c + 2) * 32, (c + 2) % 3);

        const uint32_t sbs = sb + (c % 3) * GSTAGE;
#pragma unroll
        for (int kk = 0; kk < 2; ++kk) {
            uint32_t ah[2][4], al[2][4];
#pragma unroll
            for (int tm = 0; tm < 2; ++tm) {
                uint32_t ro = (uint32_t)(rA + tm * 16) * 64 +
                              (uint32_t)(((kk * 2 + kbA) ^ sxA) * 16);
                ldsm4(ah[tm], sbs + SA_H + ro);
                ldsm4(al[tm], sbs + SA_L + ro);
            }
#pragma unroll
            for (int tp = 0; tp < 4; ++tp) {
                uint32_t bh[4], bl[4];
                uint32_t ro = (uint32_t)(rB + tp * 16) * 64 +
                              (uint32_t)(((kk * 2 + kbB) ^ sxB) * 16);
                ldsm4(bh, sbs + SB_H + ro);
                ldsm4(bl, sbs + SB_L + ro);
#pragma unroll
                for (int tm = 0; tm < 2; ++tm) {
                    mma16816(acc[tm][2 * tp],     ah[tm], bh[0], bh[1]);
                    mma16816(acc[tm][2 * tp],     ah[tm], bl[0], bl[1]);
                    mma16816(acc[tm][2 * tp],     al[tm], bh[0], bh[1]);
                    mma16816(acc[tm][2 * tp + 1], ah[tm], bh[2], bh[3]);
                    mma16816(acc[tm][2 * tp + 1], ah[tm], bl[2], bl[3]);
                    mma16816(acc[tm][2 * tp + 1], al[tm], bh[2], bh[3]);
                }
            }
        }
    }
#undef LOAD_CHUNK

    // epilogue
    if (WHICH == 0) {
        __nv_bfloat16* Ch = (z == 0) ? g_Qh : (z == 1) ? g_Kh : g_Vh;
        __nv_bfloat16* Cl = (z == 0) ? g_Ql : (z == 1) ? g_Kl : g_Vl;
#pragma unroll
        for (int tm = 0; tm < 2; ++tm) {
            const int m = m0 + m_warp + tm * 16 + (lane >> 2);
#pragma unroll
            for (int tn = 0; tn < 8; ++tn) {
                const int n = n0 + n_warp + tn * 8 + (lane & 3) * 2;
                size_t o0 = (size_t)m * 512 + n;
                size_t o1 = (size_t)(m + 8) * 512 + n;
                uint32_t hp0, lp0, hp1, lp1;
                pack_hilo(acc[tm][tn][0], acc[tm][tn][1], hp0, lp0);
                pack_hilo(acc[tm][tn][2], acc[tm][tn][3], hp1, lp1);
                *(uint32_t*)&Ch[o0] = hp0;
                *(uint32_t*)&Cl[o0] = lp0;
                *(uint32_t*)&Ch[o1] = hp1;
                *(uint32_t*)&Cl[o1] = lp1;
            }
        }
    } else {
#pragma unroll
        for (int tm = 0; tm < 2; ++tm) {
            const int m = m0 + m_warp + tm * 16 + (lane >> 2);
#pragma unroll
            for (int tn = 0; tn < 8; ++tn) {
                const int n = n0 + n_warp + tn * 8 + (lane & 3) * 2;
                *(float2*)&Cout[(size_t)m * 512 + n] =
                    make_float2(acc[tm][tn][0], acc[tm][tn][1]);
                *(float2*)&Cout[(size_t)(m + 8) * 512 + n] =
                    make_float2(acc[tm][tn][2], acc[tm][tn][3]);
            }
        }
    }
}

// ---------------------------------------------------------------- tensor-core attention
// FA2-style + compacted keys: only unmasked keys are processed (masked keys
// contribute exactly 0 in numerator and denominator, identical to reference).
static constexpr int A_QH = 0;         // 16 KB
static constexpr int A_QL = 16384;     // 16 KB
static constexpr int A_K0 = 32768;     // 2 stages x 16 KB (KH +0, KL +8192)
static constexpr int A_V0 = 65536;     // 2 stages x 16 KB
static constexpr int ATTN_SMEM = 98304;

__global__ __launch_bounds__(256, 2) void attn_mma_kernel()
{
    extern __shared__ char sm[];
    const uint32_t sb = smem_u32(sm);
    const int tid  = threadIdx.x;
    const int wid  = tid >> 5;
    const int lane = tid & 31;

    const int qt = blockIdx.x;
    const int h  = blockIdx.y;
    const int b  = blockIdx.z;
    const int mq = wid * 16;
    const size_t qrow0 = (size_t)b * 512 + qt * 128;

    const int nt = g_nt[b];
    const int nk = g_nk[b];
    const int* idxp = &g_idx[b * 512];

    // prologue: Q + K(0)/V(0) via compacted indices
#pragma unroll
    for (int i = 0; i < 4; i++) {
        int idx = tid + i * 256;
        int row = idx >> 3, c = idx & 7;
        uint32_t so = row * 128 + ((c ^ (row & 7)) * 16);
        size_t g = (qrow0 + row) * 512 + h * 64 + c * 8;
        cpasync16(sb + A_QH + so, &g_Qh[g]);
        cpasync16(sb + A_QL + so, &g_Ql[g]);
    }
#pragma unroll
    for (int i = 0; i < 2; i++) {
        int idx = tid + i * 256;
        int row = idx >> 3, c = idx & 7;
        uint32_t so = row * 128 + ((c ^ (row & 7)) * 16);
        int key = __ldg(&idxp[row]);
        size_t g = ((size_t)b * 512 + key) * 512 + h * 64 + c * 8;
        cpasync16(sb + A_K0 + so, &g_Kh[g]);
        cpasync16(sb + A_K0 + 8192 + so, &g_Kl[g]);
        cpasync16(sb + A_V0 + so, &g_Vh[g]);
        cpasync16(sb + A_V0 + 8192 + so, &g_Vl[g]);
    }
    cpcommit();

    float accO[4][2][4];
#pragma unroll
    for (int i = 0; i < 4; i++)
#pragma unroll
        for (int j = 0; j < 2; j++)
#pragma unroll
            for (int u = 0; u < 4; u++) accO[i][j][u] = 0.f;
    float rs0 = 0.f, rs1 = 0.f;

    const float scale2 = 0.044194173824159216f * 1.4426950408889634f;  // /sqrt(E)*log2(e)

    const int rowQ = mq + (lane & 7) + ((lane >> 3) & 1) * 8;
    const int cQ   = lane >> 4;
    const int rowK = (lane & 7) + (lane >> 4) * 8;
    const int cK   = (lane >> 3) & 1;
    const int rowV = (lane & 7) + ((lane >> 3) & 1) * 8;
    const int cV   = lane >> 4;

    for (int tile = 0; tile < nt; ++tile) {
        cpwait<0>();
        __syncthreads();

        if (tile + 1 < nt) {
            const int t1 = (tile + 1) * 64;
            const uint32_t kb1 = sb + A_K0 + ((tile + 1) & 1) * 16384;
            const uint32_t vb1 = sb + A_V0 + ((tile + 1) & 1) * 16384;
#pragma unroll
            for (int i = 0; i < 2; i++) {
                int idx = tid + i * 256;
                int row = idx >> 3, c = idx & 7;
                uint32_t so = row * 128 + ((c ^ (row & 7)) * 16);
                int key = __ldg(&idxp[t1 + row]);
                size_t g = ((size_t)b * 512 + key) * 512 + h * 64 + c * 8;
                cpasync16(kb1 + so, &g_Kh[g]);
                cpasync16(kb1 + 8192 + so, &g_Kl[g]);
                cpasync16(vb1 + so, &g_Vh[g]);
                cpasync16(vb1 + 8192 + so, &g_Vl[g]);
            }
            cpcommit();
        }

        const uint32_t kb = sb + A_K0 + (tile & 1) * 16384;
        const uint32_t vb = sb + A_V0 + (tile & 1) * 16384;

        // ---- S = Q K^T : 16q x 64(compacted)k per warp
        float accS[4][2][4];
#pragma unroll
        for (int i = 0; i < 4; i++)
#pragma unroll
            for (int j = 0; j < 2; j++)
#pragma unroll
                for (int u = 0; u < 4; u++) accS[i][j][u] = 0.f;

#pragma unroll
        for (int ks = 0; ks < 4; ++ks) {
            uint32_t qh[4], ql[4];
            {
                uint32_t so = rowQ * 128 + (((ks * 2 + cQ) ^ (rowQ & 7)) * 16);
                ldsm4(qh, sb + A_QH + so);
                ldsm4(ql, sb + A_QL + so);
            }
#pragma unroll
            for (int kg = 0; kg < 4; ++kg) {
                uint32_t kh[4], kl[4];
                int row = kg * 16 + rowK;
                uint32_t so = row * 128 + (((ks * 2 + cK) ^ (row & 7)) * 16);
                ldsm4(kh, kb + so);
                ldsm4(kl, kb + 8192 + so);
                mma16816(accS[kg][0], qh, kh[0], kh[1]);
                mma16816(accS[kg][0], qh, kl[0], kl[1]);
                mma16816(accS[kg][0], ql, kh[0], kh[1]);
                mma16816(accS[kg][1], qh, kh[2], kh[3]);
                mma16816(accS[kg][1], qh, kl[2], kl[3]);
                mma16816(accS[kg][1], ql, kh[2], kh[3]);
            }
        }

        // ---- per-16-key chunk: predicate-padded exp (ex2) + pack + PV MMAs
        const int t0 = tile * 64;
#pragma unroll
        for (int kc = 0; kc < 4; ++kc) {
            float p[2][4];
#pragma unroll
            for (int t8 = 0; t8 < 2; ++t8) {
                int key = t0 + kc * 16 + t8 * 8 + (lane & 3) * 2;
                bool v0 = key < nk;
                bool v1 = key + 1 < nk;
                p[t8][0] = v0 ? ex2(accS[kc][t8][0] * scale2) : 0.f;
                p[t8][1] = v1 ? ex2(accS[kc][t8][1] * scale2) : 0.f;
                p[t8][2] = v0 ? ex2(accS[kc][t8][2] * scale2) : 0.f;
                p[t8][3] = v1 ? ex2(accS[kc][t8][3] * scale2) : 0.f;
                rs0 += p[t8][0] + p[t8][1];
                rs1 += p[t8][2] + p[t8][3];
            }
            uint32_t ph[4], pl[4];
            pack_hilo(p[0][0], p[0][1], ph[0], pl[0]);
            pack_hilo(p[0][2], p[0][3], ph[1], pl[1]);
            pack_hilo(p[1][0], p[1][1], ph[2], pl[2]);
            pack_hilo(p[1][2], p[1][3], ph[3], pl[3]);
#pragma unroll
            for (int dg = 0; dg < 4; ++dg) {
                uint32_t vh[4], vl[4];
                int row = kc * 16 + rowV;
                uint32_t so = row * 128 + (((dg * 2 + cV) ^ (row & 7)) * 16);
                ldsm4t(vh, vb + so);
                ldsm4t(vl, vb + 8192 + so);
                mma16816(accO[dg][0], ph, vh[0], vh[1]);
                mma16816(accO[dg][0], ph, vl[0], vl[1]);
                mma16816(accO[dg][0], pl, vh[0], vh[1]);
                mma16816(accO[dg][1], ph, vh[2], vh[3]);
                mma16816(accO[dg][1], ph, vl[2], vl[3]);
                mma16816(accO[dg][1], pl, vh[2], vh[3]);
            }
        }
    }

    // ---- rowsum reduce within quad
    rs0 += __shfl_xor_sync(0xffffffffu, rs0, 1);
    rs0 += __shfl_xor_sync(0xffffffffu, rs0, 2);
    rs1 += __shfl_xor_sync(0xffffffffu, rs1, 1);
    rs1 += __shfl_xor_sync(0xffffffffu, rs1, 2);
    const float inv0 = 1.f / rs0;
    const float inv1 = 1.f / rs1;

    // ---- normalize + store O as bf16 hi/lo
    const int r0 = mq + (lane >> 2);
    const int r1 = r0 + 8;
    const size_t g0 = (qrow0 + r0) * 512 + h * 64;
    const size_t g1 = (qrow0 + r1) * 512 + h * 64;
#pragma unroll
    for (int dg = 0; dg < 4; ++dg) {
#pragma unroll
        for (int t8 = 0; t8 < 2; ++t8) {
            int d = dg * 16 + t8 * 8 + (lane & 3) * 2;
            uint32_t hp0, lp0, hp1, lp1;
            pack_hilo(accO[dg][t8][0] * inv0, accO[dg][t8][1] * inv0, hp0, lp0);
            pack_hilo(accO[dg][t8][2] * inv1, accO[dg][t8][3] * inv1, hp1, lp1);
            *(uint32_t*)&g_ATh[g0 + d] = hp0;
            *(uint32_t*)&g_ATl[g0 + d] = lp0;
            *(uint32_t*)&g_ATh[g1 + d] = hp1;
            *(uint32_t*)&g_ATl[g1 + d] = lp1;
        }
    }
}

// ---------------------------------------------------------------- launch
extern "C" void kernel_launch(void* const* d_in, const int* in_sizes, int n_in,
                              void* d_out, int out_size)
{
    const float* x    = (const float*)d_in[0];
    const float* mask = (const float*)d_in[1];
    const float* WQ   = (const float*)d_in[2];
    const float* WK   = (const float*)d_in[3];
    const float* WV   = (const float*)d_in[4];
    const float* BE   = (const float*)d_in[5];
    const float* WO   = (const float*)d_in[6];
    float* out        = (float*)d_out;

    cudaFuncSetAttribute(attn_mma_kernel,
                         cudaFuncAttributeMaxDynamicSharedMemorySize, ATTN_SMEM);
    cudaFuncSetAttribute(gemm_bf16x3_kernel<0>,
                         cudaFuncAttributeMaxDynamicSharedMemorySize, GEMM_SMEM);
    cudaFuncSetAttribute(gemm_bf16x3_kernel<1>,
                         cudaFuncAttributeMaxDynamicSharedMemorySize, GEMM_SMEM);

    mask_compact_kernel<<<Bb, 512>>>(mask);
    prep_kernel<<<16384 + 4096, 256>>>(x, BE, WQ, WK, WV, WO);

    dim3 gq(Mm / 128, 512 / 128, 3);
    gemm_bf16x3_kernel<0><<<gq, 256, GEMM_SMEM>>>(nullptr);

    dim3 ga(Ss / 128, Hh, Bb);
    attn_mma_kernel<<<ga, 256, ATTN_SMEM>>>();

    dim3 go(Mm / 128, 512 / 128, 1);
    gemm_bf16x3_kernel<1><<<go, 256, GEMM_SMEM>>>(out);
}

// round 10
// speedup vs baseline: 3.9947x; 1.0011x over previous
#include <cuda_runtime.h>
#include <cuda_bf16.h>
#include <stdint.h>
#include <math.h>

// ---------------------------------------------------------------- dims
static constexpr int Bb = 64;
static constexpr int Ss = 512;
static constexpr int Ee = 512;
static constexpr int Hh = 8;
static constexpr int Dd = 64;
static constexpr int Mm = Bb * Ss;     // 32768
static constexpr int HD = Hh * Dd;     // 512

// ---------------------------------------------------------------- scratch
__device__ __nv_bfloat16 g_Ah[Mm * Ee];
__device__ __nv_bfloat16 g_Al[Mm * Ee];
__device__ __nv_bfloat16 g_ATh[Mm * HD];
__device__ __nv_bfloat16 g_ATl[Mm * HD];
__device__ __nv_bfloat16 g_Bh[2048 * 512];
__device__ __nv_bfloat16 g_Bl[2048 * 512];
__device__ __nv_bfloat16 g_Qh[Mm * HD];
__device__ __nv_bfloat16 g_Ql[Mm * HD];
__device__ __nv_bfloat16 g_Kh[Mm * HD];
__device__ __nv_bfloat16 g_Kl[Mm * HD];
__device__ __nv_bfloat16 g_Vh[Mm * HD];
__device__ __nv_bfloat16 g_Vl[Mm * HD];
// mask compaction
__device__ int g_idx[Bb * Ss];
__device__ int g_nt[Bb];
__device__ int g_nk[Bb];

// ---------------------------------------------------------------- helpers
__device__ __forceinline__ void pack_hilo(float v0, float v1, uint32_t& hp, uint32_t& lp) {
    asm("cvt.rn.bf16x2.f32 %0, %1, %2;" : "=r"(hp) : "f"(v1), "f"(v0));
    float h0 = __uint_as_float(hp << 16);
    float h1 = __uint_as_float(hp & 0xFFFF0000u);
    float r0 = v0 - h0;
    float r1 = v1 - h1;
    asm("cvt.rn.bf16x2.f32 %0, %1, %2;" : "=r"(lp) : "f"(r1), "f"(r0));
}
__device__ __forceinline__ float ex2(float x) {
    float r;
    asm("ex2.approx.f32 %0, %1;" : "=f"(r) : "f"(x));
    return r;
}
__device__ __forceinline__ uint32_t smem_u32(const void* p) {
    uint32_t a;
    asm("{ .reg .u64 t; cvta.to.shared.u64 t, %1; cvt.u32.u64 %0, t; }" : "=r"(a) : "l"(p));
    return a;
}
__device__ __forceinline__ void ldsm4(uint32_t r[4], uint32_t addr) {
    asm volatile("ldmatrix.sync.aligned.m8n8.x4.shared.b16 {%0,%1,%2,%3}, [%4];"
                 : "=r"(r[0]), "=r"(r[1]), "=r"(r[2]), "=r"(r[3]) : "r"(addr));
}
__device__ __forceinline__ void ldsm4t(uint32_t r[4], uint32_t addr) {
    asm volatile("ldmatrix.sync.aligned.m8n8.x4.trans.shared.b16 {%0,%1,%2,%3}, [%4];"
                 : "=r"(r[0]), "=r"(r[1]), "=r"(r[2]), "=r"(r[3]) : "r"(addr));
}
__device__ __forceinline__ void mma16816(float d[4], const uint32_t a[4],
                                         uint32_t b0, uint32_t b1) {
    asm volatile("mma.sync.aligned.m16n8k16.row.col.f32.bf16.bf16.f32 "
                 "{%0,%1,%2,%3}, {%4,%5,%6,%7}, {%8,%9}, {%0,%1,%2,%3};"
                 : "+f"(d[0]), "+f"(d[1]), "+f"(d[2]), "+f"(d[3])
                 : "r"(a[0]), "r"(a[1]), "r"(a[2]), "r"(a[3]), "r"(b0), "r"(b1));
}
__device__ __forceinline__ void cpasync16(uint32_t saddr, const void* g) {
    asm volatile("cp.async.cg.shared.global [%0], [%1], 16;" :: "r"(saddr), "l"(g));
}
__device__ __forceinline__ void cpcommit() {
    asm volatile("cp.async.commit_group;" ::: "memory");
}
template <int N>
__device__ __forceinline__ void cpwait() {
    asm volatile("cp.async.wait_group %0;" :: "n"(N) : "memory");
}

// ---------------------------------------------------------------- mask compaction
__global__ __launch_bounds__(512) void mask_compact_kernel(const float* __restrict__ mask) {
    const int b = blockIdx.x, t = threadIdx.x;
    const int wid = t >> 5, lane = t & 31;
    const bool keep = (mask[(size_t)b * 512 + t] == 0.0f);
    const unsigned bal = __ballot_sync(0xffffffffu, keep);
    __shared__ int wcnt[16], woff[16], snk;
    if (lane == 0) wcnt[wid] = __popc(bal);
    __syncthreads();
    if (t == 0) {
        int s = 0;
        for (int i = 0; i < 16; i++) { woff[i] = s; s += wcnt[i]; }
        snk = s;
        g_nk[b] = s;
        g_nt[b] = (s + 63) >> 6;
    }
    __syncthreads();
    const int nk = snk;
    const int pos = woff[wid] + __popc(bal & ((1u << lane) - 1));
    if (keep) g_idx[b * 512 + pos] = t;
    const int ntk = ((nk + 63) >> 6) << 6;
    if (t >= nk && t < ntk) g_idx[b * 512 + t] = 0;   // padded keys (killed by predicate)
}

// ---------------------------------------------------------------- fused prep
__global__ __launch_bounds__(256) void prep_kernel(const float* __restrict__ x,
                                                   const float* __restrict__ be,
                                                   const float* __restrict__ WQ,
                                                   const float* __restrict__ WK,
                                                   const float* __restrict__ WV,
                                                   const float* __restrict__ WO) {
    if (blockIdx.x < 16384) {
        uint32_t i4 = blockIdx.x * 256 + threadIdx.x;
        int m = i4 >> 7;
        int k = (i4 & 127) << 2;
        const float4 xv = *(const float4*)&x[(size_t)m * Ee + k];
        const float4 bv = *(const float4*)&be[(size_t)(m & (Ss - 1)) * Ee + k];
        uint32_t h01, h23, l01, l23;
        pack_hilo(xv.x + bv.x, xv.y + bv.y, h01, l01);
        pack_hilo(xv.z + bv.z, xv.w + bv.w, h23, l23);
        size_t o = (size_t)m * Ee + k;
        *(uint32_t*)&g_Ah[o]     = h01;
        *(uint32_t*)&g_Ah[o + 2] = h23;
        *(uint32_t*)&g_Al[o]     = l01;
        *(uint32_t*)&g_Al[o + 2] = l23;
    } else {
        uint32_t idx = (blockIdx.x - 16384) * 256 + threadIdx.x;
        int r = idx >> 9;
        int k = idx & 511;
        float v;
        if (r < 1536) {
            int z = r >> 9;
            int n = r & 511;
            const float* W = (z == 0) ? WQ : (z == 1) ? WK : WV;
            v = W[(size_t)(n >> 6) * (Ee * Dd) + (size_t)k * Dd + (n & 63)];
        } else {
            int n = r - 1536;
            v = WO[(size_t)k * Ee + n];
        }
        uint32_t hp, lp;
        pack_hilo(v, v, hp, lp);
        g_Bh[idx] = *(__nv_bfloat16*)&hp;
        g_Bl[idx] = *(__nv_bfloat16*)&lp;
    }
}

// ---------------------------------------------------------------- HMMA GEMM (cp.async 3-stage)
static constexpr int SA_H = 0;
static constexpr int SA_L = 8192;
static constexpr int SB_H = 16384;
static constexpr int SB_L = 24576;
static constexpr int GSTAGE = 32768;
static constexpr int GEMM_SMEM = 3 * GSTAGE;   // 96 KB

template <int WHICH>
__global__ __launch_bounds__(256, 2) void gemm_bf16x3_kernel(float* __restrict__ Cout)
{
    extern __shared__ __align__(16) char sm[];
    const uint32_t sb = smem_u32(sm);
    const int tid  = threadIdx.x;
    const int wid  = tid >> 5;
    const int lane = tid & 31;

    const int m0 = blockIdx.x * 128;
    const int n0 = blockIdx.y * 128;
    const int z  = (WHICH == 0) ? blockIdx.z : 0;

    const __nv_bfloat16* Ah = (WHICH == 0) ? g_Ah : g_ATh;
    const __nv_bfloat16* Al = (WHICH == 0) ? g_Al : g_ATl;
    const size_t boff = (WHICH == 0) ? (size_t)z * 512 * 512 : (size_t)1536 * 512;
    const __nv_bfloat16* Bh = g_Bh + boff;
    const __nv_bfloat16* Bl = g_Bl + boff;

    const int m_warp = (wid & 3) * 32;
    const int n_warp = (wid >> 2) * 64;

    const int rA   = m_warp + (lane & 7) + ((lane >> 3) & 1) * 8;
    const int kbA  = lane >> 4;
    const int sxA  = (rA >> 1) & 3;
    const int rB   = n_warp + (lane & 7) + (lane >> 4) * 8;
    const int kbB  = (lane >> 3) & 1;
    const int sxB  = (rB >> 1) & 3;

    float acc[2][8][4];
#pragma unroll
    for (int i = 0; i < 2; i++)
#pragma unroll
        for (int j = 0; j < 8; j++)
#pragma unroll
            for (int u = 0; u < 4; u++) acc[i][j][u] = 0.f;

    const int grow0 = (tid + 0)   >> 2, gc80 = (tid + 0)   & 3;
    const int grow1 = (tid + 256) >> 2, gc81 = (tid + 256) & 3;
    const uint32_t so0 = grow0 * 64 + ((gc80 ^ ((grow0 >> 1) & 3)) * 16);
    const uint32_t so1 = grow1 * 64 + ((gc81 ^ ((grow1 >> 1) & 3)) * 16);
    const __nv_bfloat16* pAh0 = Ah + (size_t)(m0 + grow0) * 512 + gc80 * 8;
    const __nv_bfloat16* pAh1 = Ah + (size_t)(m0 + grow1) * 512 + gc81 * 8;
    const __nv_bfloat16* pAl0 = Al + (size_t)(m0 + grow0) * 512 + gc80 * 8;
    const __nv_bfloat16* pAl1 = Al + (size_t)(m0 + grow1) * 512 + gc81 * 8;
    const __nv_bfloat16* pBh0 = Bh + (size_t)(n0 + grow0) * 512 + gc80 * 8;
    const __nv_bfloat16* pBh1 = Bh + (size_t)(n0 + grow1) * 512 + gc81 * 8;
    const __nv_bfloat16* pBl0 = Bl + (size_t)(n0 + grow0) * 512 + gc80 * 8;
    const __nv_bfloat16* pBl1 = Bl + (size_t)(n0 + grow1) * 512 + gc81 * 8;

#define LOAD_CHUNK(k0, stage) do {                                        \
        uint32_t s_ = sb + (stage) * GSTAGE;                              \
        cpasync16(s_ + SA_H + so0, pAh0 + (k0));                          \
        cpasync16(s_ + SA_H + so1, pAh1 + (k0));                          \
        cpasync16(s_ + SA_L + so0, pAl0 + (k0));                          \
        cpasync16(s_ + SA_L + so1, pAl1 + (k0));                          \
        cpasync16(s_ + SB_H + so0, pBh0 + (k0));                          \
        cpasync16(s_ + SB_H + so1, pBh1 + (k0));                          \
        cpasync16(s_ + SB_L + so0, pBl0 + (k0));                          \
        cpasync16(s_ + SB_L + so1, pBl1 + (k0));                          \
        cpcommit();                                                       \
    } while (0)

    LOAD_CHUNK(0, 0);
    LOAD_CHUNK(32, 1);

    for (int c = 0; c < 16; ++c) {
        if (c < 15) cpwait<1>(); else cpwait<0>();
        __syncthreads();
        if (c + 2 < 16) LOAD_CHUNK((c + 2) * 32, (c + 2) % 3);

        const uint32_t sbs = sb + (c % 3) * GSTAGE;
#pragma unroll
        for (int kk = 0; kk < 2; ++kk) {
            uint32_t ah[2][4], al[2][4];
#pragma unroll
            for (int tm = 0; tm < 2; ++tm) {
                uint32_t ro = (uint32_t)(rA + tm * 16) * 64 +
                              (uint32_t)(((kk * 2 + kbA) ^ sxA) * 16);
                ldsm4(ah[tm], sbs + SA_H + ro);
                ldsm4(al[tm], sbs + SA_L + ro);
            }
#pragma unroll
            for (int tp = 0; tp < 4; ++tp) {
                uint32_t bh[4], bl[4];
                uint32_t ro = (uint32_t)(rB + tp * 16) * 64 +
                              (uint32_t)(((kk * 2 + kbB) ^ sxB) * 16);
                ldsm4(bh, sbs + SB_H + ro);
                ldsm4(bl, sbs + SB_L + ro);
                // term-major round-robin over 4 independent acc chains
                // (same per-acc term order as before: hh, hl, lh -> bit-identical)
#pragma unroll
                for (int tm = 0; tm < 2; ++tm) {
                    mma16816(acc[tm][2 * tp],     ah[tm], bh[0], bh[1]);
                    mma16816(acc[tm][2 * tp + 1], ah[tm], bh[2], bh[3]);
                }
#pragma unroll
                for (int tm = 0; tm < 2; ++tm) {
                    mma16816(acc[tm][2 * tp],     ah[tm], bl[0], bl[1]);
                    mma16816(acc[tm][2 * tp + 1], ah[tm], bl[2], bl[3]);
                }
#pragma unroll
                for (int tm = 0; tm < 2; ++tm) {
                    mma16816(acc[tm][2 * tp],     al[tm], bh[0], bh[1]);
                    mma16816(acc[tm][2 * tp + 1], al[tm], bh[2], bh[3]);
                }
            }
        }
    }
#undef LOAD_CHUNK

    // epilogue
    if (WHICH == 0) {
        __nv_bfloat16* Ch = (z == 0) ? g_Qh : (z == 1) ? g_Kh : g_Vh;
        __nv_bfloat16* Cl = (z == 0) ? g_Ql : (z == 1) ? g_Kl : g_Vl;
#pragma unroll
        for (int tm = 0; tm < 2; ++tm) {
            const int m = m0 + m_warp + tm * 16 + (lane >> 2);
#pragma unroll
            for (int tn = 0; tn < 8; ++tn) {
                const int n = n0 + n_warp + tn * 8 + (lane & 3) * 2;
                size_t o0 = (size_t)m * 512 + n;
                size_t o1 = (size_t)(m + 8) * 512 + n;
                uint32_t hp0, lp0, hp1, lp1;
                pack_hilo(acc[tm][tn][0], acc[tm][tn][1], hp0, lp0);
                pack_hilo(acc[tm][tn][2], acc[tm][tn][3], hp1, lp1);
                *(uint32_t*)&Ch[o0] = hp0;
                *(uint32_t*)&Cl[o0] = lp0;
                *(uint32_t*)&Ch[o1] = hp1;
                *(uint32_t*)&Cl[o1] = lp1;
            }
        }
    } else {
#pragma unroll
        for (int tm = 0; tm < 2; ++tm) {
            const int m = m0 + m_warp + tm * 16 + (lane >> 2);
#pragma unroll
            for (int tn = 0; tn < 8; ++tn) {
                const int n = n0 + n_warp + tn * 8 + (lane & 3) * 2;
                *(float2*)&Cout[(size_t)m * 512 + n] =
                    make_float2(acc[tm][tn][0], acc[tm][tn][1]);
                *(float2*)&Cout[(size_t)(m + 8) * 512 + n] =
                    make_float2(acc[tm][tn][2], acc[tm][tn][3]);
            }
        }
    }
}

// ---------------------------------------------------------------- tensor-core attention
// FA2-style + compacted keys. MMA blocks emitted chain-round-robin.
static constexpr int A_QH = 0;         // 16 KB
static constexpr int A_QL = 16384;     // 16 KB
static constexpr int A_K0 = 32768;     // 2 stages x 16 KB (KH +0, KL +8192)
static constexpr int A_V0 = 65536;     // 2 stages x 16 KB
static constexpr int ATTN_SMEM = 98304;

__global__ __launch_bounds__(256, 2) void attn_mma_kernel()
{
    extern __shared__ char sm[];
    const uint32_t sb = smem_u32(sm);
    const int tid  = threadIdx.x;
    const int wid  = tid >> 5;
    const int lane = tid & 31;

    const int qt = blockIdx.x;
    const int h  = blockIdx.y;
    const int b  = blockIdx.z;
    const int mq = wid * 16;
    const size_t qrow0 = (size_t)b * 512 + qt * 128;

    const int nt = g_nt[b];
    const int nk = g_nk[b];
    const int* idxp = &g_idx[b * 512];

    // prologue: Q + K(0)/V(0) via compacted indices
#pragma unroll
    for (int i = 0; i < 4; i++) {
        int idx = tid + i * 256;
        int row = idx >> 3, c = idx & 7;
        uint32_t so = row * 128 + ((c ^ (row & 7)) * 16);
        size_t g = (qrow0 + row) * 512 + h * 64 + c * 8;
        cpasync16(sb + A_QH + so, &g_Qh[g]);
        cpasync16(sb + A_QL + so, &g_Ql[g]);
    }
#pragma unroll
    for (int i = 0; i < 2; i++) {
        int idx = tid + i * 256;
        int row = idx >> 3, c = idx & 7;
        uint32_t so = row * 128 + ((c ^ (row & 7)) * 16);
        int key = __ldg(&idxp[row]);
        size_t g = ((size_t)b * 512 + key) * 512 + h * 64 + c * 8;
        cpasync16(sb + A_K0 + so, &g_Kh[g]);
        cpasync16(sb + A_K0 + 8192 + so, &g_Kl[g]);
        cpasync16(sb + A_V0 + so, &g_Vh[g]);
        cpasync16(sb + A_V0 + 8192 + so, &g_Vl[g]);
    }
    cpcommit();

    float accO[4][2][4];
#pragma unroll
    for (int i = 0; i < 4; i++)
#pragma unroll
        for (int j = 0; j < 2; j++)
#pragma unroll
            for (int u = 0; u < 4; u++) accO[i][j][u] = 0.f;
    float rs0 = 0.f, rs1 = 0.f;

    const float scale2 = 0.044194173824159216f * 1.4426950408889634f;  // /sqrt(E)*log2(e)

    const int rowQ = mq + (lane & 7) + ((lane >> 3) & 1) * 8;
    const int cQ   = lane >> 4;
    const int rowK = (lane & 7) + (lane >> 4) * 8;
    const int cK   = (lane >> 3) & 1;
    const int rowV = (lane & 7) + ((lane >> 3) & 1) * 8;
    const int cV   = lane >> 4;

    for (int tile = 0; tile < nt; ++tile) {
        cpwait<0>();
        __syncthreads();

        if (tile + 1 < nt) {
            const int t1 = (tile + 1) * 64;
            const uint32_t kb1 = sb + A_K0 + ((tile + 1) & 1) * 16384;
            const uint32_t vb1 = sb + A_V0 + ((tile + 1) & 1) * 16384;
#pragma unroll
            for (int i = 0; i < 2; i++) {
                int idx = tid + i * 256;
                int row = idx >> 3, c = idx & 7;
                uint32_t so = row * 128 + ((c ^ (row & 7)) * 16);
                int key = __ldg(&idxp[t1 + row]);
                size_t g = ((size_t)b * 512 + key) * 512 + h * 64 + c * 8;
                cpasync16(kb1 + so, &g_Kh[g]);
                cpasync16(kb1 + 8192 + so, &g_Kl[g]);
                cpasync16(vb1 + so, &g_Vh[g]);
                cpasync16(vb1 + 8192 + so, &g_Vl[g]);
            }
            cpcommit();
        }

        const uint32_t kb = sb + A_K0 + (tile & 1) * 16384;
        const uint32_t vb = sb + A_V0 + (tile & 1) * 16384;

        // ---- S = Q K^T : 16q x 64(compacted)k per warp
        float accS[4][2][4];
#pragma unroll
        for (int i = 0; i < 4; i++)
#pragma unroll
            for (int j = 0; j < 2; j++)
#pragma unroll
                for (int u = 0; u < 4; u++) accS[i][j][u] = 0.f;

#pragma unroll
        for (int ks = 0; ks < 4; ++ks) {
            uint32_t qh[4], ql[4];
            {
                uint32_t so = rowQ * 128 + (((ks * 2 + cQ) ^ (rowQ & 7)) * 16);
                ldsm4(qh, sb + A_QH + so);
                ldsm4(ql, sb + A_QL + so);
            }
#pragma unroll
            for (int kg = 0; kg < 4; ++kg) {
                uint32_t kh[4], kl[4];
                int row = kg * 16 + rowK;
                uint32_t so = row * 128 + (((ks * 2 + cK) ^ (row & 7)) * 16);
                ldsm4(kh, kb + so);
                ldsm4(kl, kb + 8192 + so);
                // chain round-robin: alternate the two accS chains per term
                mma16816(accS[kg][0], qh, kh[0], kh[1]);
                mma16816(accS[kg][1], qh, kh[2], kh[3]);
                mma16816(accS[kg][0], qh, kl[0], kl[1]);
                mma16816(accS[kg][1], qh, kl[2], kl[3]);
                mma16816(accS[kg][0], ql, kh[0], kh[1]);
                mma16816(accS[kg][1], ql, kh[2], kh[3]);
            }
        }

        // ---- per-16-key chunk: predicate-padded exp (ex2) + pack + PV MMAs
        const int t0 = tile * 64;
#pragma unroll
        for (int kc = 0; kc < 4; ++kc) {
            float p[2][4];
#pragma unroll
            for (int t8 = 0; t8 < 2; ++t8) {
                int key = t0 + kc * 16 + t8 * 8 + (lane & 3) * 2;
                bool v0 = key < nk;
                bool v1 = key + 1 < nk;
                p[t8][0] = v0 ? ex2(accS[kc][t8][0] * scale2) : 0.f;
                p[t8][1] = v1 ? ex2(accS[kc][t8][1] * scale2) : 0.f;
                p[t8][2] = v0 ? ex2(accS[kc][t8][2] * scale2) : 0.f;
                p[t8][3] = v1 ? ex2(accS[kc][t8][3] * scale2) : 0.f;
                rs0 += p[t8][0] + p[t8][1];
                rs1 += p[t8][2] + p[t8][3];
            }
            uint32_t ph[4], pl[4];
            pack_hilo(p[0][0], p[0][1], ph[0], pl[0]);
            pack_hilo(p[0][2], p[0][3], ph[1], pl[1]);
            pack_hilo(p[1][0], p[1][1], ph[2], pl[2]);
            pack_hilo(p[1][2], p[1][3], ph[3], pl[3]);
#pragma unroll
            for (int dg = 0; dg < 4; ++dg) {
                uint32_t vh[4], vl[4];
                int row = kc * 16 + rowV;
                uint32_t so = row * 128 + (((dg * 2 + cV) ^ (row & 7)) * 16);
                ldsm4t(vh, vb + so);
                ldsm4t(vl, vb + 8192 + so);
                // chain round-robin: alternate the two accO chains per term
                mma16816(accO[dg][0], ph, vh[0], vh[1]);
                mma16816(accO[dg][1], ph, vh[2], vh[3]);
                mma16816(accO[dg][0], ph, vl[0], vl[1]);
                mma16816(accO[dg][1], ph, vl[2], vl[3]);
                mma16816(accO[dg][0], pl, vh[0], vh[1]);
                mma16816(accO[dg][1], pl, vh[2], vh[3]);
            }
        }
    }

    // ---- rowsum reduce within quad
    rs0 += __shfl_xor_sync(0xffffffffu, rs0, 1);
    rs0 += __shfl_xor_sync(0xffffffffu, rs0, 2);
    rs1 += __shfl_xor_sync(0xffffffffu, rs1, 1);
    rs1 += __shfl_xor_sync(0xffffffffu, rs1, 2);
    const float inv0 = 1.f / rs0;
    const float inv1 = 1.f / rs1;

    // ---- normalize + store O as bf16 hi/lo
    const int r0 = mq + (lane >> 2);
    const int r1 = r0 + 8;
    const size_t g0 = (qrow0 + r0) * 512 + h * 64;
    const size_t g1 = (qrow0 + r1) * 512 + h * 64;
#pragma unroll
    for (int dg = 0; dg < 4; ++dg) {
#pragma unroll
        for (int t8 = 0; t8 < 2; ++t8) {
            int d = dg * 16 + t8 * 8 + (lane & 3) * 2;
            uint32_t hp0, lp0, hp1, lp1;
            pack_hilo(accO[dg][t8][0] * inv0, accO[dg][t8][1] * inv0, hp0, lp0);
            pack_hilo(accO[dg][t8][2] * inv1, accO[dg][t8][3] * inv1, hp1, lp1);
            *(uint32_t*)&g_ATh[g0 + d] = hp0;
            *(uint32_t*)&g_ATl[g0 + d] = lp0;
            *(uint32_t*)&g_ATh[g1 + d] = hp1;
            *(uint32_t*)&g_ATl[g1 + d] = lp1;
        }
    }
}

// ---------------------------------------------------------------- launch
extern "C" void kernel_launch(void* const* d_in, const int* in_sizes, int n_in,
                              void* d_out, int out_size)
{
    const float* x    = (const float*)d_in[0];
    const float* mask = (const float*)d_in[1];
    const float* WQ   = (const float*)d_in[2];
    const float* WK   = (const float*)d_in[3];
    const float* WV   = (const float*)d_in[4];
    const float* BE   = (const float*)d_in[5];
    const float* WO   = (const float*)d_in[6];
    float* out        = (float*)d_out;

    cudaFuncSetAttribute(attn_mma_kernel,
                         cudaFuncAttributeMaxDynamicSharedMemorySize, ATTN_SMEM);
    cudaFuncSetAttribute(gemm_bf16x3_kernel<0>,
                         cudaFuncAttributeMaxDynamicSharedMemorySize, GEMM_SMEM);
    cudaFuncSetAttribute(gemm_bf16x3_kernel<1>,
                         cudaFuncAttributeMaxDynamicSharedMemorySize, GEMM_SMEM);

    mask_compact_kernel<<<Bb, 512>>>(mask);
    prep_kernel<<<16384 + 4096, 256>>>(x, BE, WQ, WK, WV, WO);

    dim3 gq(Mm / 128, 512 / 128, 3);
    gemm_bf16x3_kernel<0><<<gq, 256, GEMM_SMEM>>>(nullptr);

    dim3 ga(Ss / 128, Hh, Bb);
    attn_mma_kernel<<<ga, 256, ATTN_SMEM>>>();

    dim3 go(Mm / 128, 512 / 128, 1);
    gemm_bf16x3_kernel<1><<<go, 256, GEMM_SMEM>>>(out);
}